// round 2
// baseline (speedup 1.0000x reference)
#include <cuda_runtime.h>
#include <math.h>

#define N_NODES 20000
#define HDIM    512
#define FEAT    1029
#define NUM_GAT 5
#define E_CAP   360000

// ---------------- scratch (device globals; no allocation) ----------------
__device__ float g_X  [(size_t)N_NODES * FEAT];   // concat buffer
__device__ float g_h  [(size_t)N_NODES * HDIM];   // node features
__device__ float g_hw [(size_t)N_NODES * HDIM];   // h @ W (and MLP temp)
__device__ float g_acc[(size_t)N_NODES * HDIM];   // GAT accumulation (and MLP temp)
__device__ float g_s  [N_NODES];
__device__ float g_t  [N_NODES];
__device__ float g_dn [N_NODES];
__device__ float g_e  [E_CAP];

// ---------------- GEMM: C = act(A@B + bias) ----------------
// A: M x K row-major, B: K x N row-major, C: M x N row-major
// BM=BN=64, BK=16, 256 threads, 4x4 per-thread micro-tile.
#define BM 64
#define BN 64
#define BK 16

template <int ACT>  // 0 = none, 1 = relu
__global__ void gemm_bias_act(const float* __restrict__ A, const float* __restrict__ B,
                              const float* __restrict__ bias, float* __restrict__ C,
                              int M, int K, int N) {
    __shared__ float As[BK][BM];   // transposed: As[k][m]
    __shared__ float Bs[BK][BN];

    const int tid = threadIdx.x;
    const int tx = tid & 15;        // 0..15
    const int ty = tid >> 4;        // 0..15
    const int row0 = blockIdx.y * BM;
    const int col0 = blockIdx.x * BN;

    float acc[4][4] = {};

    for (int k0 = 0; k0 < K; k0 += BK) {
        // load A tile (BM x BK), store transposed
        #pragma unroll
        for (int i = 0; i < 4; i++) {
            int lin = tid + i * 256;
            int m = lin >> 4;        // /BK
            int kk = lin & 15;       // %BK
            int gm = row0 + m, gk = k0 + kk;
            float v = 0.f;
            if (gm < M && gk < K) v = A[(size_t)gm * K + gk];
            As[kk][m] = v;
        }
        // load B tile (BK x BN)
        #pragma unroll
        for (int i = 0; i < 4; i++) {
            int lin = tid + i * 256;
            int kk = lin >> 6;       // /BN
            int n = lin & 63;        // %BN
            int gk = k0 + kk, gn = col0 + n;
            float v = 0.f;
            if (gk < K && gn < N) v = B[(size_t)gk * N + gn];
            Bs[kk][n] = v;
        }
        __syncthreads();

        #pragma unroll
        for (int kk = 0; kk < BK; kk++) {
            float ra[4], rb[4];
            #pragma unroll
            for (int i = 0; i < 4; i++) ra[i] = As[kk][ty * 4 + i];
            #pragma unroll
            for (int j = 0; j < 4; j++) rb[j] = Bs[kk][tx * 4 + j];
            #pragma unroll
            for (int i = 0; i < 4; i++)
                #pragma unroll
                for (int j = 0; j < 4; j++)
                    acc[i][j] += ra[i] * rb[j];
        }
        __syncthreads();
    }

    #pragma unroll
    for (int i = 0; i < 4; i++) {
        int gm = row0 + ty * 4 + i;
        if (gm >= M) continue;
        #pragma unroll
        for (int j = 0; j < 4; j++) {
            int gn = col0 + tx * 4 + j;
            if (gn >= N) continue;
            float v = acc[i][j];
            if (bias) v += bias[gn];
            if (ACT == 1) v = fmaxf(v, 0.f);
            C[(size_t)gm * N + gn] = v;
        }
    }
}

// ---------------- concat: X[i] = [a[i](512) | goal[i](512) | info[i](5)] ----------------
__global__ void concat_feats(const float* __restrict__ a, const float* __restrict__ goal,
                             const float* __restrict__ info, float* __restrict__ X, int n) {
    size_t i = (size_t)blockIdx.x * blockDim.x + threadIdx.x;
    size_t total = (size_t)n * FEAT;
    if (i >= total) return;
    int node = (int)(i / FEAT);
    int c = (int)(i % FEAT);
    float v;
    if (c < 512)       v = a[(size_t)node * 512 + c];
    else if (c < 1024) v = goal[(size_t)node * 512 + (c - 512)];
    else               v = info[(size_t)node * 5 + (c - 1024)];
    X[i] = v;
}

// ---------------- per-node dots: s = hw @ a1, t = hw @ a2 ----------------
__global__ void row_dots(const float* __restrict__ hw, const float* __restrict__ a,
                         float* __restrict__ s, float* __restrict__ t, int n) {
    int warp = (blockIdx.x * blockDim.x + threadIdx.x) >> 5;
    int lane = threadIdx.x & 31;
    if (warp >= n) return;
    const float* row = hw + (size_t)warp * HDIM;
    float s1 = 0.f, s2 = 0.f;
    #pragma unroll 4
    for (int c = lane; c < HDIM; c += 32) {
        float h = row[c];
        s1 += h * a[c];
        s2 += h * a[HDIM + c];
    }
    #pragma unroll
    for (int o = 16; o; o >>= 1) {
        s1 += __shfl_down_sync(0xffffffffu, s1, o);
        s2 += __shfl_down_sync(0xffffffffu, s2, o);
    }
    if (lane == 0) { s[warp] = s1; t[warp] = s2; }
}

// ---------------- zero fill ----------------
__global__ void zero_f(float* __restrict__ p, int n) {
    int i = blockIdx.x * blockDim.x + threadIdx.x;
    if (i < n) p[i] = 0.f;
}

// ---------------- edge scores: e = exp(-leaky_relu(s[src]+t[dst])), denom += e ------------
__global__ void edge_scores(const int* __restrict__ src, const int* __restrict__ dst,
                            const float* __restrict__ s, const float* __restrict__ t,
                            float* __restrict__ e, float* __restrict__ denom, int E) {
    int i = blockIdx.x * blockDim.x + threadIdx.x;
    if (i >= E) return;
    int si = src[i], di = dst[i];
    float sc = s[si] + t[di];
    float lr = sc > 0.f ? sc : 0.2f * sc;
    float ev = expf(-lr);
    e[i] = ev;
    atomicAdd(&denom[si], ev);
}

// ---------------- scatter: out[src] += e * hw[dst]  (one block per edge, 128 thr) --------
__global__ void scatter_msgs(const int* __restrict__ src, const int* __restrict__ dst,
                             const float* __restrict__ e, const float* __restrict__ hw,
                             float* __restrict__ out, int E) {
    int edge = blockIdx.x;
    if (edge >= E) return;
    int sI = src[edge], dI = dst[edge];
    float ev = e[edge];
    const float4* hr = reinterpret_cast<const float4*>(hw + (size_t)dI * HDIM);
    float* orow = out + (size_t)sI * HDIM;
    int c = threadIdx.x;                 // 0..127, 4 floats each
    float4 v = hr[c];
    atomicAdd(&orow[c * 4 + 0], ev * v.x);
    atomicAdd(&orow[c * 4 + 1], ev * v.y);
    atomicAdd(&orow[c * 4 + 2], ev * v.z);
    atomicAdd(&orow[c * 4 + 3], ev * v.w);
}

// ---------------- finalize: h = relu(acc / (denom + 1e-10)) ----------------
__global__ void gat_finalize(const float* __restrict__ acc, const float* __restrict__ denom,
                             float* __restrict__ h, int total) {
    int i = blockIdx.x * blockDim.x + threadIdx.x;
    if (i >= total) return;
    int node = i >> 9;  // /512
    float d = denom[node] + 1e-10f;
    h[i] = fmaxf(acc[i] / d, 0.f);
}

// ---------------- final GEMV + sigmoid: out = sigmoid(h2 @ V3 + vb3) ----------------
__global__ void gemv_sigmoid(const float* __restrict__ h2, const float* __restrict__ v3,
                             const float* __restrict__ vb3, float* __restrict__ out, int n) {
    int warp = (blockIdx.x * blockDim.x + threadIdx.x) >> 5;
    int lane = threadIdx.x & 31;
    if (warp >= n) return;
    const float* row = h2 + (size_t)warp * HDIM;
    float acc = 0.f;
    #pragma unroll 4
    for (int c = lane; c < HDIM; c += 32) acc += row[c] * v3[c];
    #pragma unroll
    for (int o = 16; o; o >>= 1) acc += __shfl_down_sync(0xffffffffu, acc, o);
    if (lane == 0) {
        float x = acc + vb3[0];
        out[warp] = 1.f / (1.f + expf(-x));
    }
}

// ---------------- host launcher ----------------
extern "C" void kernel_launch(void* const* d_in, const int* in_sizes, int n_in,
                              void* d_out, int out_size) {
    const float* feat = (const float*)d_in[0];
    const float* goal = (const float*)d_in[1];
    const float* info = (const float*)d_in[2];
    const int*   esrc = (const int*)d_in[3];
    const int*   edst = (const int*)d_in[4];
    const float* W1   = (const float*)d_in[5];
    const float* b1   = (const float*)d_in[6];
    const float* W2   = (const float*)d_in[7];
    const float* b2   = (const float*)d_in[8];
    const float* W3   = (const float*)d_in[9];
    const float* b3   = (const float*)d_in[10];
    const float* V1   = (const float*)d_in[11];
    const float* vb1  = (const float*)d_in[12];
    const float* V2   = (const float*)d_in[13];
    const float* vb2  = (const float*)d_in[14];
    const float* V3   = (const float*)d_in[15];
    const float* vb3  = (const float*)d_in[16];
    const float* gatW = (const float*)d_in[17];
    const float* gatA = (const float*)d_in[18];
    float* out = (float*)d_out;

    int E = in_sizes[3];
    if (E > E_CAP) E = E_CAP;
    const int n = N_NODES;

    float *X, *h, *hw, *acc, *s, *t, *dn, *e;
    cudaGetSymbolAddress((void**)&X,  g_X);
    cudaGetSymbolAddress((void**)&h,  g_h);
    cudaGetSymbolAddress((void**)&hw, g_hw);
    cudaGetSymbolAddress((void**)&acc,g_acc);
    cudaGetSymbolAddress((void**)&s,  g_s);
    cudaGetSymbolAddress((void**)&t,  g_t);
    cudaGetSymbolAddress((void**)&dn, g_dn);
    cudaGetSymbolAddress((void**)&e,  g_e);

    const dim3 gemm_grid_h((HDIM + BN - 1) / BN, (n + BM - 1) / BM);   // 8 x 313
    const int concat_blocks = (int)(((size_t)n * FEAT + 255) / 256);
    const int node_warp_blocks = (n * 32 + 255) / 256;                  // warp per node
    const int hdim_total = n * HDIM;
    const int hdim_blocks = (hdim_total + 255) / 256;
    const int edge_blocks = (E + 255) / 256;

    // ---- input MLP ----  (NOTE: _mlp3 layer 3 has NO relu)
    concat_feats<<<concat_blocks, 256>>>(feat, goal, info, X, n);
    gemm_bias_act<1><<<gemm_grid_h, 256>>>(X,  W1, b1, h,  n, FEAT, HDIM);
    gemm_bias_act<1><<<gemm_grid_h, 256>>>(h,  W2, b2, hw, n, HDIM, HDIM);
    gemm_bias_act<0><<<gemm_grid_h, 256>>>(hw, W3, b3, h,  n, HDIM, HDIM);

    // ---- GAT layers ----
    for (int l = 0; l < NUM_GAT; l++) {
        const float* Wl = gatW + (size_t)l * HDIM * HDIM;
        const float* al = gatA + (size_t)l * 2 * HDIM;
        gemm_bias_act<0><<<gemm_grid_h, 256>>>(h, Wl, nullptr, hw, n, HDIM, HDIM);
        row_dots<<<node_warp_blocks, 256>>>(hw, al, s, t, n);
        zero_f<<<hdim_blocks, 256>>>(acc, hdim_total);
        zero_f<<<(n + 255) / 256, 256>>>(dn, n);
        edge_scores<<<edge_blocks, 256>>>(esrc, edst, s, t, e, dn, E);
        scatter_msgs<<<E, 128>>>(esrc, edst, e, hw, acc, E);
        gat_finalize<<<hdim_blocks, 256>>>(acc, dn, h, hdim_total);
    }

    // ---- output MLP ----
    concat_feats<<<concat_blocks, 256>>>(h, goal, info, X, n);
    gemm_bias_act<1><<<gemm_grid_h, 256>>>(X,  V1, vb1, hw,  n, FEAT, HDIM);
    gemm_bias_act<1><<<gemm_grid_h, 256>>>(hw, V2, vb2, acc, n, HDIM, HDIM);
    gemv_sigmoid<<<node_warp_blocks, 256>>>(acc, V3, vb3, out, n);
}

// round 4
// speedup vs baseline: 1.2219x; 1.2219x over previous
#include <cuda_runtime.h>
#include <math.h>

#define N_NODES 20000
#define HDIM    512
#define FEAT    1029
#define FEATP   1032   // padded row stride (multiple of 4 -> 16B-aligned float4 rows)
#define NUM_GAT 5
#define E_CAP   360000

// ---------------- scratch (device globals; no allocation) ----------------
__device__ float g_X  [(size_t)N_NODES * FEATP];
__device__ float g_h  [(size_t)N_NODES * HDIM];
__device__ float g_hw [(size_t)N_NODES * HDIM];
__device__ float g_acc[(size_t)N_NODES * HDIM];
__device__ float g_s  [N_NODES];
__device__ float g_t  [N_NODES];
__device__ float g_dn [N_NODES];
__device__ float g_e  [E_CAP];

// ---------------- GEMM: C = act(A@B + bias) ----------------
// A: M x K row-major (K = padded stride, multiple of 4; padded cols are zero)
// B: KB x N row-major (KB = real inner dim; k >= KB reads as 0)
// BM=BN=128, BK=16, 256 threads, 8x8 per-thread micro-tile, float4 LDS.
#define BM 128
#define BN 128
#define BK 16

template <int ACT>  // 0 = none, 1 = relu
__global__ __launch_bounds__(256, 2)
void gemm_bias_act(const float* __restrict__ A, const float* __restrict__ B,
                   const float* __restrict__ bias, float* __restrict__ C,
                   int M, int K, int KB, int N) {
    __shared__ float As[BK][BM];   // transposed: As[k][m]
    __shared__ float Bs[BK][BN];

    const int tid = threadIdx.x;
    const int tx = tid & 15;        // 0..15 -> col group
    const int ty = tid >> 4;        // 0..15 -> row group
    const int row0 = blockIdx.y * BM;
    const int col0 = blockIdx.x * BN;

    float acc[8][8] = {};

    for (int k0 = 0; k0 < K; k0 += BK) {
        const bool fullM = (row0 + BM <= M);

        // ---- load A tile (BM x BK) -> As transposed ----
        // 512 float4 total, 2 per thread. K is a multiple of 4 and k0 a
        // multiple of 16 <= K-16, so every float4 is in-bounds and aligned.
        #pragma unroll
        for (int it = 0; it < 2; it++) {
            int f = tid + it * 256;        // 0..511
            int r  = f >> 2;               // row within tile (0..127)
            int c4 = f & 3;                // float4 col (0..3)
            int gm = row0 + r;
            int gk = k0 + c4 * 4;
            float4 v = make_float4(0.f, 0.f, 0.f, 0.f);
            if (fullM || gm < M)
                v = *reinterpret_cast<const float4*>(&A[(size_t)gm * K + gk]);
            As[c4 * 4 + 0][r] = v.x;
            As[c4 * 4 + 1][r] = v.y;
            As[c4 * 4 + 2][r] = v.z;
            As[c4 * 4 + 3][r] = v.w;
        }

        // ---- load B tile (BK x BN) ---- 512 float4 total, 2 per thread
        #pragma unroll
        for (int it = 0; it < 2; it++) {
            int f = tid + it * 256;        // 0..511
            int r  = f >> 5;               // k row (0..15)
            int c4 = f & 31;               // float4 col (0..31)
            int gk = k0 + r;
            int gn = col0 + c4 * 4;
            float4 v = make_float4(0.f, 0.f, 0.f, 0.f);
            if (gk < KB && gn + 3 < N)
                v = *reinterpret_cast<const float4*>(&B[(size_t)gk * N + gn]);
            *reinterpret_cast<float4*>(&Bs[r][c4 * 4]) = v;
        }
        __syncthreads();

        #pragma unroll
        for (int kk = 0; kk < BK; kk++) {
            float4 a0 = *reinterpret_cast<const float4*>(&As[kk][ty * 8]);
            float4 a1 = *reinterpret_cast<const float4*>(&As[kk][ty * 8 + 4]);
            float4 b0 = *reinterpret_cast<const float4*>(&Bs[kk][tx * 8]);
            float4 b1 = *reinterpret_cast<const float4*>(&Bs[kk][tx * 8 + 4]);
            float ra[8] = {a0.x, a0.y, a0.z, a0.w, a1.x, a1.y, a1.z, a1.w};
            float rb[8] = {b0.x, b0.y, b0.z, b0.w, b1.x, b1.y, b1.z, b1.w};
            #pragma unroll
            for (int i = 0; i < 8; i++)
                #pragma unroll
                for (int j = 0; j < 8; j++)
                    acc[i][j] += ra[i] * rb[j];
        }
        __syncthreads();
    }

    // ---- epilogue ----
    float bj[8];
    #pragma unroll
    for (int j = 0; j < 8; j++) {
        int gn = col0 + tx * 8 + j;
        bj[j] = (bias && gn < N) ? bias[gn] : 0.f;
    }
    #pragma unroll
    for (int i = 0; i < 8; i++) {
        int gm = row0 + ty * 8 + i;
        if (gm >= M) continue;
        int gn = col0 + tx * 8;
        float v[8];
        #pragma unroll
        for (int j = 0; j < 8; j++) {
            v[j] = acc[i][j] + bj[j];
            if (ACT == 1) v[j] = fmaxf(v[j], 0.f);
        }
        if (gn + 7 < N) {
            *reinterpret_cast<float4*>(&C[(size_t)gm * N + gn])     = make_float4(v[0], v[1], v[2], v[3]);
            *reinterpret_cast<float4*>(&C[(size_t)gm * N + gn + 4]) = make_float4(v[4], v[5], v[6], v[7]);
        } else {
            #pragma unroll
            for (int j = 0; j < 8; j++)
                if (gn + j < N) C[(size_t)gm * N + gn + j] = v[j];
        }
    }
}

// ---------------- concat into padded X: [a(512) | goal(512) | info(5) | 0,0,0] ----------
__global__ void concat_feats(const float* __restrict__ a, const float* __restrict__ goal,
                             const float* __restrict__ info, float* __restrict__ X, int n) {
    size_t i = (size_t)blockIdx.x * blockDim.x + threadIdx.x;
    size_t total = (size_t)n * FEATP;
    if (i >= total) return;
    int node = (int)(i / FEATP);
    int c = (int)(i % FEATP);
    float v;
    if (c < 512)       v = a[(size_t)node * 512 + c];
    else if (c < 1024) v = goal[(size_t)node * 512 + (c - 512)];
    else if (c < 1029) v = info[(size_t)node * 5 + (c - 1024)];
    else               v = 0.f;
    X[i] = v;
}

// ---------------- per-node dots: s = hw @ a1, t = hw @ a2 ----------------
__global__ void row_dots(const float* __restrict__ hw, const float* __restrict__ a,
                         float* __restrict__ s, float* __restrict__ t, int n) {
    int warp = (blockIdx.x * blockDim.x + threadIdx.x) >> 5;
    int lane = threadIdx.x & 31;
    if (warp >= n) return;
    const float* row = hw + (size_t)warp * HDIM;
    float s1 = 0.f, s2 = 0.f;
    #pragma unroll 4
    for (int c = lane; c < HDIM; c += 32) {
        float h = row[c];
        s1 += h * a[c];
        s2 += h * a[HDIM + c];
    }
    #pragma unroll
    for (int o = 16; o; o >>= 1) {
        s1 += __shfl_down_sync(0xffffffffu, s1, o);
        s2 += __shfl_down_sync(0xffffffffu, s2, o);
    }
    if (lane == 0) { s[warp] = s1; t[warp] = s2; }
}

// ---------------- zero fill ----------------
__global__ void zero_f(float* __restrict__ p, int n) {
    int i = blockIdx.x * blockDim.x + threadIdx.x;
    if (i < n) p[i] = 0.f;
}

// ---------------- edge scores ----------------
__global__ void edge_scores(const int* __restrict__ src, const int* __restrict__ dst,
                            const float* __restrict__ s, const float* __restrict__ t,
                            float* __restrict__ e, float* __restrict__ denom, int E) {
    int i = blockIdx.x * blockDim.x + threadIdx.x;
    if (i >= E) return;
    int si = src[i], di = dst[i];
    float sc = s[si] + t[di];
    float lr = sc > 0.f ? sc : 0.2f * sc;
    float ev = expf(-lr);
    e[i] = ev;
    atomicAdd(&denom[si], ev);
}

// ---------------- scatter: out[src] += e * hw[dst] ----------------
__global__ void scatter_msgs(const int* __restrict__ src, const int* __restrict__ dst,
                             const float* __restrict__ e, const float* __restrict__ hw,
                             float* __restrict__ out, int E) {
    int edge = blockIdx.x;
    if (edge >= E) return;
    int sI = src[edge], dI = dst[edge];
    float ev = e[edge];
    const float4* hr = reinterpret_cast<const float4*>(hw + (size_t)dI * HDIM);
    float* orow = out + (size_t)sI * HDIM;
    int c = threadIdx.x;                 // 0..127
    float4 v = hr[c];
    atomicAdd(&orow[c * 4 + 0], ev * v.x);
    atomicAdd(&orow[c * 4 + 1], ev * v.y);
    atomicAdd(&orow[c * 4 + 2], ev * v.z);
    atomicAdd(&orow[c * 4 + 3], ev * v.w);
}

// ---------------- finalize: h = relu(acc / (denom + 1e-10)) ----------------
__global__ void gat_finalize(const float* __restrict__ acc, const float* __restrict__ denom,
                             float* __restrict__ h, int total) {
    int i = blockIdx.x * blockDim.x + threadIdx.x;
    if (i >= total) return;
    int node = i >> 9;
    float d = denom[node] + 1e-10f;
    h[i] = fmaxf(acc[i] / d, 0.f);
}

// ---------------- final GEMV + sigmoid ----------------
__global__ void gemv_sigmoid(const float* __restrict__ h2, const float* __restrict__ v3,
                             const float* __restrict__ vb3, float* __restrict__ out, int n) {
    int warp = (blockIdx.x * blockDim.x + threadIdx.x) >> 5;
    int lane = threadIdx.x & 31;
    if (warp >= n) return;
    const float* row = h2 + (size_t)warp * HDIM;
    float acc = 0.f;
    #pragma unroll 4
    for (int c = lane; c < HDIM; c += 32) acc += row[c] * v3[c];
    #pragma unroll
    for (int o = 16; o; o >>= 1) acc += __shfl_down_sync(0xffffffffu, acc, o);
    if (lane == 0) {
        float x = acc + vb3[0];
        out[warp] = 1.f / (1.f + expf(-x));
    }
}

// ---------------- host launcher ----------------
extern "C" void kernel_launch(void* const* d_in, const int* in_sizes, int n_in,
                              void* d_out, int out_size) {
    const float* feat = (const float*)d_in[0];
    const float* goal = (const float*)d_in[1];
    const float* info = (const float*)d_in[2];
    const int*   esrc = (const int*)d_in[3];
    const int*   edst = (const int*)d_in[4];
    const float* W1   = (const float*)d_in[5];
    const float* b1   = (const float*)d_in[6];
    const float* W2   = (const float*)d_in[7];
    const float* b2   = (const float*)d_in[8];
    const float* W3   = (const float*)d_in[9];
    const float* b3   = (const float*)d_in[10];
    const float* V1   = (const float*)d_in[11];
    const float* vb1  = (const float*)d_in[12];
    const float* V2   = (const float*)d_in[13];
    const float* vb2  = (const float*)d_in[14];
    const float* V3   = (const float*)d_in[15];
    const float* vb3  = (const float*)d_in[16];
    const float* gatW = (const float*)d_in[17];
    const float* gatA = (const float*)d_in[18];
    float* out = (float*)d_out;

    int E = in_sizes[3];
    if (E > E_CAP) E = E_CAP;
    const int n = N_NODES;

    float *X, *h, *hw, *acc, *s, *t, *dn, *e;
    cudaGetSymbolAddress((void**)&X,  g_X);
    cudaGetSymbolAddress((void**)&h,  g_h);
    cudaGetSymbolAddress((void**)&hw, g_hw);
    cudaGetSymbolAddress((void**)&acc,g_acc);
    cudaGetSymbolAddress((void**)&s,  g_s);
    cudaGetSymbolAddress((void**)&t,  g_t);
    cudaGetSymbolAddress((void**)&dn, g_dn);
    cudaGetSymbolAddress((void**)&e,  g_e);

    const dim3 gemm_grid_h((HDIM + BN - 1) / BN, (n + BM - 1) / BM);   // 4 x 157
    const int concat_blocks = (int)(((size_t)n * FEATP + 255) / 256);
    const int node_warp_blocks = (n * 32 + 255) / 256;
    const int hdim_total = n * HDIM;
    const int hdim_blocks = (hdim_total + 255) / 256;
    const int edge_blocks = (E + 255) / 256;

    // ---- input MLP ---- (layer 3 has NO relu)
    concat_feats<<<concat_blocks, 256>>>(feat, goal, info, X, n);
    gemm_bias_act<1><<<gemm_grid_h, 256>>>(X,  W1, b1, h,  n, FEATP, FEAT, HDIM);
    gemm_bias_act<1><<<gemm_grid_h, 256>>>(h,  W2, b2, hw, n, HDIM, HDIM, HDIM);
    gemm_bias_act<0><<<gemm_grid_h, 256>>>(hw, W3, b3, h,  n, HDIM, HDIM, HDIM);

    // ---- GAT layers ----
    for (int l = 0; l < NUM_GAT; l++) {
        const float* Wl = gatW + (size_t)l * HDIM * HDIM;
        const float* al = gatA + (size_t)l * 2 * HDIM;
        gemm_bias_act<0><<<gemm_grid_h, 256>>>(h, Wl, nullptr, hw, n, HDIM, HDIM, HDIM);
        row_dots<<<node_warp_blocks, 256>>>(hw, al, s, t, n);
        zero_f<<<hdim_blocks, 256>>>(acc, hdim_total);
        zero_f<<<(n + 255) / 256, 256>>>(dn, n);
        edge_scores<<<edge_blocks, 256>>>(esrc, edst, s, t, e, dn, E);
        scatter_msgs<<<E, 128>>>(esrc, edst, e, hw, acc, E);
        gat_finalize<<<hdim_blocks, 256>>>(acc, dn, h, hdim_total);
    }

    // ---- output MLP ----
    concat_feats<<<concat_blocks, 256>>>(h, goal, info, X, n);
    gemm_bias_act<1><<<gemm_grid_h, 256>>>(X,  V1, vb1, hw,  n, FEATP, FEAT, HDIM);
    gemm_bias_act<1><<<gemm_grid_h, 256>>>(hw, V2, vb2, acc, n, HDIM, HDIM, HDIM);
    gemv_sigmoid<<<node_warp_blocks, 256>>>(acc, V3, vb3, out, n);
}

// round 5
// speedup vs baseline: 1.9635x; 1.6068x over previous
#include <cuda_runtime.h>
#include <math.h>
#include <stdint.h>

#define N_NODES 20000
#define HDIM    512
#define FEAT    1029
#define FEATP   1032   // padded row stride (multiple of 4)
#define NUM_GAT 5
#define E_CAP   360000

// ---------------- scratch (device globals; no allocation) ----------------
__device__ float g_X   [(size_t)N_NODES * FEATP];
__device__ float g_h   [(size_t)N_NODES * HDIM];
__device__ float g_hw  [(size_t)N_NODES * HDIM];
__device__ float g_acc [(size_t)N_NODES * HDIM];
__device__ float g_s   [N_NODES];
__device__ float g_t   [N_NODES];
__device__ int   g_cnt [N_NODES];
__device__ int   g_off [N_NODES + 1];
__device__ int   g_cur [N_NODES];
__device__ int   g_dsts[E_CAP];     // dst[] reordered so edges are grouped by src

// ================= TF32 split (3xTF32) GEMM =================
// C = act(A@B + bias); A: M x K (K = padded stride), B: KB x N, C: M x N
// Block tile 128x64, K-tile 32. 8 warps: 4 (m) x 2 (n), warp tile 32x32.
// mma.sync.m16n8k8 tf32; Dekker split hi/lo for fp32-level accuracy.
#define TBM 128
#define TBN 64
#define TBK 32
#define AS_STRIDE (TBM + 8)   // 136: conflict-free fragment LDS
#define BS_STRIDE (TBN + 8)   // 72

__device__ __forceinline__ uint32_t f32_to_tf32(float x) {
    uint32_t r; asm("cvt.rna.tf32.f32 %0, %1;" : "=r"(r) : "f"(x)); return r;
}

__device__ __forceinline__ void mma_tf32(float* c, const uint32_t* a, const uint32_t* b) {
    asm("mma.sync.aligned.m16n8k8.row.col.f32.tf32.tf32.f32 "
        "{%0,%1,%2,%3}, {%4,%5,%6,%7}, {%8,%9}, {%0,%1,%2,%3};"
        : "+f"(c[0]), "+f"(c[1]), "+f"(c[2]), "+f"(c[3])
        : "r"(a[0]), "r"(a[1]), "r"(a[2]), "r"(a[3]), "r"(b[0]), "r"(b[1]));
}

template <int ACT>  // 0 = none, 1 = relu
__global__ __launch_bounds__(256, 2)
void gemm_tf32(const float* __restrict__ A, const float* __restrict__ B,
               const float* __restrict__ bias, float* __restrict__ C,
               int M, int K, int KB, int N) {
    __shared__ float As[TBK * AS_STRIDE];  // As[k][m]
    __shared__ float Bs[TBK * BS_STRIDE];  // Bs[k][n]

    const int tid  = threadIdx.x;
    const int wid  = tid >> 5;
    const int lane = tid & 31;
    const int lq   = lane >> 2;   // 0..7
    const int lr   = lane & 3;    // 0..3
    const int wm   = (wid & 3) * 32;   // warp m offset: 0,32,64,96
    const int wn   = (wid >> 2) * 32;  // warp n offset: 0,32
    const int row0 = blockIdx.y * TBM;
    const int col0 = blockIdx.x * TBN;

    float c[2][4][4] = {};   // [m-atom][n-atom][reg]

    for (int k0 = 0; k0 < K; k0 += TBK) {
        // ---- load A tile (128 x 32) -> As[k][m]; 1024 float4, 4/thread ----
        {
            int m = tid & 127;
            int kqb = tid >> 7;          // 0..1
            #pragma unroll
            for (int it = 0; it < 4; it++) {
                int kq = kqb + it * 2;   // 0..7
                int gm = row0 + m, gk = k0 + kq * 4;
                float4 v = make_float4(0.f, 0.f, 0.f, 0.f);
                if (gm < M && gk + 3 < K)
                    v = *reinterpret_cast<const float4*>(A + (size_t)gm * K + gk);
                As[(kq * 4 + 0) * AS_STRIDE + m] = v.x;
                As[(kq * 4 + 1) * AS_STRIDE + m] = v.y;
                As[(kq * 4 + 2) * AS_STRIDE + m] = v.z;
                As[(kq * 4 + 3) * AS_STRIDE + m] = v.w;
            }
        }
        // ---- load B tile (32 x 64) -> Bs[k][n]; 512 float4, 2/thread ----
        #pragma unroll
        for (int it = 0; it < 2; it++) {
            int f  = tid + it * 256;  // 0..511
            int kk = f >> 4;          // 0..31
            int nq = f & 15;          // 0..15
            int gk = k0 + kk, gn = col0 + nq * 4;
            float4 v = make_float4(0.f, 0.f, 0.f, 0.f);
            if (gk < KB) v = *reinterpret_cast<const float4*>(B + (size_t)gk * N + gn);
            *reinterpret_cast<float4*>(Bs + kk * BS_STRIDE + nq * 4) = v;
        }
        __syncthreads();

        #pragma unroll
        for (int ks = 0; ks < TBK; ks += 8) {
            // A fragments (m16k8, row-major): a0:(lq,lr) a1:(lq+8,lr) a2:(lq,lr+4) a3:(lq+8,lr+4)
            uint32_t ah[2][4], al[2][4];
            #pragma unroll
            for (int ma = 0; ma < 2; ma++) {
                int mrow = wm + ma * 16;
                #pragma unroll
                for (int r = 0; r < 4; r++) {
                    int row = mrow + lq + (r & 1) * 8;
                    int kk  = ks + lr + (r >> 1) * 4;
                    float x = As[kk * AS_STRIDE + row];
                    uint32_t hb = f32_to_tf32(x);
                    ah[ma][r] = hb;
                    al[ma][r] = f32_to_tf32(x - __uint_as_float(hb));
                }
            }
            // B fragments (k8n8, col-major): b0:(k=lr, n=lq) b1:(k=lr+4, n=lq)
            uint32_t bh[4][2], bl[4][2];
            #pragma unroll
            for (int na = 0; na < 4; na++) {
                int ncol = wn + na * 8 + lq;
                #pragma unroll
                for (int r = 0; r < 2; r++) {
                    int kk = ks + lr + r * 4;
                    float x = Bs[kk * BS_STRIDE + ncol];
                    uint32_t hb = f32_to_tf32(x);
                    bh[na][r] = hb;
                    bl[na][r] = f32_to_tf32(x - __uint_as_float(hb));
                }
            }
            #pragma unroll
            for (int ma = 0; ma < 2; ma++) {
                #pragma unroll
                for (int na = 0; na < 4; na++) {
                    mma_tf32(c[ma][na], ah[ma], bh[na]);   // hi*hi
                    mma_tf32(c[ma][na], ah[ma], bl[na]);   // hi*lo
                    mma_tf32(c[ma][na], al[ma], bh[na]);   // lo*hi
                }
            }
        }
        __syncthreads();
    }

    // ---- epilogue: c0:(lq, 2lr) c1:(lq, 2lr+1) c2:(lq+8, 2lr) c3:(lq+8, 2lr+1) ----
    #pragma unroll
    for (int na = 0; na < 4; na++) {
        int gn = col0 + wn + na * 8 + 2 * lr;
        float b0 = bias ? bias[gn]     : 0.f;
        float b1 = bias ? bias[gn + 1] : 0.f;
        #pragma unroll
        for (int ma = 0; ma < 2; ma++) {
            int gm = row0 + wm + ma * 16 + lq;
            float v0 = c[ma][na][0] + b0;
            float v1 = c[ma][na][1] + b1;
            float v2 = c[ma][na][2] + b0;
            float v3 = c[ma][na][3] + b1;
            if (ACT == 1) {
                v0 = fmaxf(v0, 0.f); v1 = fmaxf(v1, 0.f);
                v2 = fmaxf(v2, 0.f); v3 = fmaxf(v3, 0.f);
            }
            if (gm < M)
                *reinterpret_cast<float2*>(C + (size_t)gm * N + gn) = make_float2(v0, v1);
            if (gm + 8 < M)
                *reinterpret_cast<float2*>(C + (size_t)(gm + 8) * N + gn) = make_float2(v2, v3);
        }
    }
}

// ---------------- concat into padded X ----------------
__global__ void concat_feats(const float* __restrict__ a, const float* __restrict__ goal,
                             const float* __restrict__ info, float* __restrict__ X, int n) {
    size_t i = (size_t)blockIdx.x * blockDim.x + threadIdx.x;
    size_t total = (size_t)n * FEATP;
    if (i >= total) return;
    int node = (int)(i / FEATP);
    int c = (int)(i % FEATP);
    float v;
    if (c < 512)       v = a[(size_t)node * 512 + c];
    else if (c < 1024) v = goal[(size_t)node * 512 + (c - 512)];
    else if (c < 1029) v = info[(size_t)node * 5 + (c - 1024)];
    else               v = 0.f;
    X[i] = v;
}

// ---------------- per-node dots: s = hw @ a1, t = hw @ a2 ----------------
__global__ void row_dots(const float* __restrict__ hw, const float* __restrict__ a,
                         float* __restrict__ s, float* __restrict__ t, int n) {
    int warp = (blockIdx.x * blockDim.x + threadIdx.x) >> 5;
    int lane = threadIdx.x & 31;
    if (warp >= n) return;
    const float* row = hw + (size_t)warp * HDIM;
    float s1 = 0.f, s2 = 0.f;
    #pragma unroll 4
    for (int c = lane; c < HDIM; c += 32) {
        float h = row[c];
        s1 += h * a[c];
        s2 += h * a[HDIM + c];
    }
    #pragma unroll
    for (int o = 16; o; o >>= 1) {
        s1 += __shfl_down_sync(0xffffffffu, s1, o);
        s2 += __shfl_down_sync(0xffffffffu, s2, o);
    }
    if (lane == 0) { s[warp] = s1; t[warp] = s2; }
}

// ================= CSR build (once per launch) =================
__global__ void zero_i(int* __restrict__ p, int n) {
    int i = blockIdx.x * blockDim.x + threadIdx.x;
    if (i < n) p[i] = 0;
}

__global__ void csr_count(const int* __restrict__ src, int* __restrict__ cnt, int E) {
    int i = blockIdx.x * blockDim.x + threadIdx.x;
    if (i < E) atomicAdd(&cnt[src[i]], 1);
}

__global__ void csr_scan(const int* __restrict__ cnt, int* __restrict__ off, int n) {
    __shared__ int sh[1024];
    __shared__ int carry;
    int tid = threadIdx.x;
    if (tid == 0) carry = 0;
    __syncthreads();
    for (int base = 0; base < n; base += 1024) {
        int i = base + tid;
        int v = (i < n) ? cnt[i] : 0;
        sh[tid] = v;
        __syncthreads();
        for (int o = 1; o < 1024; o <<= 1) {
            int x = (tid >= o) ? sh[tid - o] : 0;
            __syncthreads();
            sh[tid] += x;
            __syncthreads();
        }
        if (i < n) off[i] = carry + sh[tid] - v;  // exclusive prefix
        __syncthreads();
        if (tid == 0) carry += sh[1023];
        __syncthreads();
    }
    if (tid == 0) off[n] = carry;
}

__global__ void csr_place(const int* __restrict__ src, const int* __restrict__ dst,
                          const int* __restrict__ off, int* __restrict__ cur,
                          int* __restrict__ dsts, int E) {
    int i = blockIdx.x * blockDim.x + threadIdx.x;
    if (i >= E) return;
    int u = src[i];
    int p = off[u] + atomicAdd(&cur[u], 1);
    dsts[p] = dst[i];
}

// ---------------- fused GAT aggregation (gather, no atomics) ----------------
// h_out[u] = relu( sum_e ev * hw[dst_e] / (sum_e ev + 1e-10) ),
// ev = exp(-leaky_relu(s[u] + t[dst_e], 0.2))
__global__ void gat_aggregate(const int* __restrict__ off, const int* __restrict__ dsts,
                              const float* __restrict__ s, const float* __restrict__ t,
                              const float* __restrict__ hw, float* __restrict__ hout) {
    int u = blockIdx.x;
    int c = threadIdx.x;          // 0..127, one float4 per thread
    int beg = off[u], end = off[u + 1];
    float su = s[u];
    float4 acc = make_float4(0.f, 0.f, 0.f, 0.f);
    float dsum = 0.f;
    for (int p = beg; p < end; p++) {
        int d = dsts[p];
        float sc = su + t[d];
        float lr = sc > 0.f ? sc : 0.2f * sc;
        float ev = expf(-lr);
        dsum += ev;
        float4 v = *(reinterpret_cast<const float4*>(hw + (size_t)d * HDIM) + c);
        acc.x += ev * v.x; acc.y += ev * v.y;
        acc.z += ev * v.z; acc.w += ev * v.w;
    }
    float inv = 1.f / (dsum + 1e-10f);
    float4 o;
    o.x = fmaxf(acc.x * inv, 0.f);
    o.y = fmaxf(acc.y * inv, 0.f);
    o.z = fmaxf(acc.z * inv, 0.f);
    o.w = fmaxf(acc.w * inv, 0.f);
    *(reinterpret_cast<float4*>(hout + (size_t)u * HDIM) + c) = o;
}

// ---------------- final GEMV + sigmoid ----------------
__global__ void gemv_sigmoid(const float* __restrict__ h2, const float* __restrict__ v3,
                             const float* __restrict__ vb3, float* __restrict__ out, int n) {
    int warp = (blockIdx.x * blockDim.x + threadIdx.x) >> 5;
    int lane = threadIdx.x & 31;
    if (warp >= n) return;
    const float* row = h2 + (size_t)warp * HDIM;
    float acc = 0.f;
    #pragma unroll 4
    for (int c = lane; c < HDIM; c += 32) acc += row[c] * v3[c];
    #pragma unroll
    for (int o = 16; o; o >>= 1) acc += __shfl_down_sync(0xffffffffu, acc, o);
    if (lane == 0) {
        float x = acc + vb3[0];
        out[warp] = 1.f / (1.f + expf(-x));
    }
}

// ---------------- host launcher ----------------
extern "C" void kernel_launch(void* const* d_in, const int* in_sizes, int n_in,
                              void* d_out, int out_size) {
    const float* feat = (const float*)d_in[0];
    const float* goal = (const float*)d_in[1];
    const float* info = (const float*)d_in[2];
    const int*   esrc = (const int*)d_in[3];
    const int*   edst = (const int*)d_in[4];
    const float* W1   = (const float*)d_in[5];
    const float* b1   = (const float*)d_in[6];
    const float* W2   = (const float*)d_in[7];
    const float* b2   = (const float*)d_in[8];
    const float* W3   = (const float*)d_in[9];
    const float* b3   = (const float*)d_in[10];
    const float* V1   = (const float*)d_in[11];
    const float* vb1  = (const float*)d_in[12];
    const float* V2   = (const float*)d_in[13];
    const float* vb2  = (const float*)d_in[14];
    const float* V3   = (const float*)d_in[15];
    const float* vb3  = (const float*)d_in[16];
    const float* gatW = (const float*)d_in[17];
    const float* gatA = (const float*)d_in[18];
    float* out = (float*)d_out;

    int E = in_sizes[3];
    if (E > E_CAP) E = E_CAP;
    const int n = N_NODES;

    float *X, *h, *hw, *acc, *s, *t;
    int *cnt, *off, *cur, *dsts;
    cudaGetSymbolAddress((void**)&X,   g_X);
    cudaGetSymbolAddress((void**)&h,   g_h);
    cudaGetSymbolAddress((void**)&hw,  g_hw);
    cudaGetSymbolAddress((void**)&acc, g_acc);
    cudaGetSymbolAddress((void**)&s,   g_s);
    cudaGetSymbolAddress((void**)&t,   g_t);
    cudaGetSymbolAddress((void**)&cnt, g_cnt);
    cudaGetSymbolAddress((void**)&off, g_off);
    cudaGetSymbolAddress((void**)&cur, g_cur);
    cudaGetSymbolAddress((void**)&dsts,g_dsts);

    const dim3 gemm_grid(HDIM / TBN, (n + TBM - 1) / TBM);   // 8 x 157
    const int concat_blocks = (int)(((size_t)n * FEATP + 255) / 256);
    const int node_warp_blocks = (n * 32 + 255) / 256;
    const int edge_blocks = (E + 255) / 256;

    // ---- CSR build (once; reused by all 5 GAT layers) ----
    zero_i<<<(n + 255) / 256, 256>>>(cnt, n);
    zero_i<<<(n + 255) / 256, 256>>>(cur, n);
    csr_count<<<edge_blocks, 256>>>(esrc, cnt, E);
    csr_scan<<<1, 1024>>>(cnt, off, n);
    csr_place<<<edge_blocks, 256>>>(esrc, edst, off, cur, dsts, E);

    // ---- input MLP ---- (layer 3 has NO relu)
    concat_feats<<<concat_blocks, 256>>>(feat, goal, info, X, n);
    gemm_tf32<1><<<gemm_grid, 256>>>(X,  W1, b1, h,  n, FEATP, FEAT, HDIM);
    gemm_tf32<1><<<gemm_grid, 256>>>(h,  W2, b2, hw, n, HDIM, HDIM, HDIM);
    gemm_tf32<0><<<gemm_grid, 256>>>(hw, W3, b3, h,  n, HDIM, HDIM, HDIM);

    // ---- GAT layers ----
    for (int l = 0; l < NUM_GAT; l++) {
        const float* Wl = gatW + (size_t)l * HDIM * HDIM;
        const float* al = gatA + (size_t)l * 2 * HDIM;
        gemm_tf32<0><<<gemm_grid, 256>>>(h, Wl, nullptr, hw, n, HDIM, HDIM, HDIM);
        row_dots<<<node_warp_blocks, 256>>>(hw, al, s, t, n);
        gat_aggregate<<<n, 128>>>(off, dsts, s, t, hw, h);
    }

    // ---- output MLP ----
    concat_feats<<<concat_blocks, 256>>>(h, goal, info, X, n);
    gemm_tf32<1><<<gemm_grid, 256>>>(X,  V1, vb1, hw,  n, FEATP, FEAT, HDIM);
    gemm_tf32<1><<<gemm_grid, 256>>>(hw, V2, vb2, acc, n, HDIM, HDIM, HDIM);
    gemv_sigmoid<<<node_warp_blocks, 256>>>(acc, V3, vb3, out, n);
}

// round 6
// speedup vs baseline: 2.7451x; 1.3981x over previous
#include <cuda_runtime.h>
#include <cuda_bf16.h>
#include <math.h>
#include <stdint.h>

#define N_NODES 20000
#define HDIM    512
#define FEAT    1029
#define FEATP   1032   // padded A row stride (multiple of 4)
#define NUM_GAT 5
#define E_CAP   360000

// k2-row counts (bf16 pairs) per weight, padded to multiple of 16
#define K2_FEAT 528    // ceil(1029/2)=515 -> 528
#define K2_H    256
// offsets into the packed split-weight buffer (in k2 rows)
#define OFF_W1   0
#define OFF_V1   (K2_FEAT)
#define OFF_W2   (2*K2_FEAT)
#define OFF_W3   (OFF_W2 + K2_H)
#define OFF_V2   (OFF_W3 + K2_H)
#define OFF_GAT0 (OFF_V2 + K2_H)
#define K2_TOTAL (OFF_GAT0 + 5*K2_H)   // 3104

// ---------------- scratch (device globals; no allocation) ----------------
__device__ float    g_X   [(size_t)N_NODES * FEATP];
__device__ float    g_h   [(size_t)N_NODES * HDIM];
__device__ float    g_hw  [(size_t)N_NODES * HDIM];
__device__ float    g_acc [(size_t)N_NODES * HDIM];
__device__ float    g_s   [N_NODES];
__device__ float    g_t   [N_NODES];
__device__ int      g_cnt [N_NODES];
__device__ int      g_off [N_NODES + 1];
__device__ int      g_cur [N_NODES];
__device__ int      g_dsts[E_CAP];
__device__ uint32_t g_Bh  [(size_t)K2_TOTAL * HDIM];   // bf16x2 hi parts, [k2][n]
__device__ uint32_t g_Bl  [(size_t)K2_TOTAL * HDIM];   // bf16x2 lo parts

// ---------------- weight split: B(KB x 512 fp32) -> Bh/Bl bf16x2 [k2][n] ----------------
__global__ void split_w(const float* __restrict__ B, uint32_t* __restrict__ Bh,
                        uint32_t* __restrict__ Bl, int KB, int k2rows) {
    int idx = blockIdx.x * blockDim.x + threadIdx.x;
    if (idx >= k2rows * HDIM) return;
    int k2 = idx >> 9, n = idx & 511;
    int k = 2 * k2;
    float x0 = (k     < KB) ? B[(size_t)k * HDIM + n]       : 0.f;
    float x1 = (k + 1 < KB) ? B[(size_t)(k + 1) * HDIM + n] : 0.f;
    float h0 = __bfloat162float(__float2bfloat16(x0));
    float h1 = __bfloat162float(__float2bfloat16(x1));
    __nv_bfloat162 hp = __floats2bfloat162_rn(x0, x1);
    __nv_bfloat162 lp = __floats2bfloat162_rn(x0 - h0, x1 - h1);
    Bh[idx] = *reinterpret_cast<uint32_t*>(&hp);
    Bl[idx] = *reinterpret_cast<uint32_t*>(&lp);
}

// ================= 3-pass split-bf16 GEMM (m16n8k16) =================
// C = act(A@B + bias). A: M x K fp32 (K = padded stride). B pre-split in
// Bh/Bl. Block tile 128x64, K-tile 32; 8 warps = 4(m) x 2(n), warp tile 32x32.
#define TBM 128
#define TBN 64
#define ASTR 136   // bank = 8*lr + lq : conflict-free
#define BSTR 72

__device__ __forceinline__ void mma_bf16(float* c, const uint32_t* a, const uint32_t* b) {
    asm("mma.sync.aligned.m16n8k16.row.col.f32.bf16.bf16.f32 "
        "{%0,%1,%2,%3}, {%4,%5,%6,%7}, {%8,%9}, {%0,%1,%2,%3};"
        : "+f"(c[0]), "+f"(c[1]), "+f"(c[2]), "+f"(c[3])
        : "r"(a[0]), "r"(a[1]), "r"(a[2]), "r"(a[3]), "r"(b[0]), "r"(b[1]));
}

template <int ACT>  // 0 = none, 1 = relu
__global__ __launch_bounds__(256, 2)
void gemm_split_bf16(const float* __restrict__ A, const uint32_t* __restrict__ Bh,
                     const uint32_t* __restrict__ Bl, const float* __restrict__ bias,
                     float* __restrict__ C, int M, int K, int KP, int N) {
    __shared__ uint32_t As_hi[16 * ASTR];   // [k2][m] bf16x2 (k, k+1)
    __shared__ uint32_t As_lo[16 * ASTR];
    __shared__ uint32_t Bs_hi[16 * BSTR];   // [k2][n]
    __shared__ uint32_t Bs_lo[16 * BSTR];

    const int tid  = threadIdx.x;
    const int wid  = tid >> 5;
    const int lane = tid & 31;
    const int lq   = lane >> 2;   // 0..7
    const int lr   = lane & 3;    // 0..3
    const int wm   = (wid & 3) * 32;   // 0,32,64,96
    const int wn   = (wid >> 2) * 32;  // 0,32
    const int row0 = blockIdx.y * TBM;
    const int col0 = blockIdx.x * TBN;

    float c[2][4][4] = {};

    const int mA  = tid & 127;
    const int c4b = tid >> 7;    // 0..1
    const int rB  = tid >> 4;    // 0..15
    const int qB  = tid & 15;    // 0..15

    for (int k0 = 0; k0 < KP; k0 += 32) {
        // ---- stage A tile (128 x 32 fp32) -> split bf16x2 SMEM ----
        #pragma unroll
        for (int it = 0; it < 4; it++) {
            int c4 = c4b + it * 2;          // 0..7
            int gm = row0 + mA, gk = k0 + c4 * 4;
            float4 v = make_float4(0.f, 0.f, 0.f, 0.f);
            if (gm < M && gk + 3 < K)
                v = *reinterpret_cast<const float4*>(A + (size_t)gm * K + gk);
            float h0 = __bfloat162float(__float2bfloat16(v.x));
            float h1 = __bfloat162float(__float2bfloat16(v.y));
            float h2 = __bfloat162float(__float2bfloat16(v.z));
            float h3 = __bfloat162float(__float2bfloat16(v.w));
            __nv_bfloat162 hp0 = __floats2bfloat162_rn(v.x, v.y);
            __nv_bfloat162 hp1 = __floats2bfloat162_rn(v.z, v.w);
            __nv_bfloat162 lp0 = __floats2bfloat162_rn(v.x - h0, v.y - h1);
            __nv_bfloat162 lp1 = __floats2bfloat162_rn(v.z - h2, v.w - h3);
            int k2 = c4 * 2;
            As_hi[(k2    ) * ASTR + mA] = *reinterpret_cast<uint32_t*>(&hp0);
            As_hi[(k2 + 1) * ASTR + mA] = *reinterpret_cast<uint32_t*>(&hp1);
            As_lo[(k2    ) * ASTR + mA] = *reinterpret_cast<uint32_t*>(&lp0);
            As_lo[(k2 + 1) * ASTR + mA] = *reinterpret_cast<uint32_t*>(&lp1);
        }
        // ---- stage B tile (16 k2-rows x 64 cols), already split ----
        {
            size_t gidx = (size_t)((k0 >> 1) + rB) * N + col0 + qB * 4;
            *reinterpret_cast<uint4*>(&Bs_hi[rB * BSTR + qB * 4]) =
                *reinterpret_cast<const uint4*>(Bh + gidx);
            *reinterpret_cast<uint4*>(&Bs_lo[rB * BSTR + qB * 4]) =
                *reinterpret_cast<const uint4*>(Bl + gidx);
        }
        __syncthreads();

        #pragma unroll
        for (int ks2 = 0; ks2 < 16; ks2 += 8) {
            uint32_t ah[2][4], al[2][4], bh[4][2], bl[4][2];
            #pragma unroll
            for (int ma = 0; ma < 2; ma++) {
                int row = wm + ma * 16 + lq;
                int kA0 = (ks2 + lr) * ASTR, kA1 = (ks2 + lr + 4) * ASTR;
                ah[ma][0] = As_hi[kA0 + row];     ah[ma][1] = As_hi[kA0 + row + 8];
                ah[ma][2] = As_hi[kA1 + row];     ah[ma][3] = As_hi[kA1 + row + 8];
                al[ma][0] = As_lo[kA0 + row];     al[ma][1] = As_lo[kA0 + row + 8];
                al[ma][2] = As_lo[kA1 + row];     al[ma][3] = As_lo[kA1 + row + 8];
            }
            #pragma unroll
            for (int na = 0; na < 4; na++) {
                int ncol = wn + na * 8 + lq;
                int kB0 = (ks2 + lr) * BSTR, kB1 = (ks2 + lr + 4) * BSTR;
                bh[na][0] = Bs_hi[kB0 + ncol];    bh[na][1] = Bs_hi[kB1 + ncol];
                bl[na][0] = Bs_lo[kB0 + ncol];    bl[na][1] = Bs_lo[kB1 + ncol];
            }
            #pragma unroll
            for (int ma = 0; ma < 2; ma++) {
                #pragma unroll
                for (int na = 0; na < 4; na++) {
                    mma_bf16(c[ma][na], ah[ma], bh[na]);   // hi*hi
                    mma_bf16(c[ma][na], ah[ma], bl[na]);   // hi*lo
                    mma_bf16(c[ma][na], al[ma], bh[na]);   // lo*hi
                }
            }
        }
        __syncthreads();
    }

    // ---- epilogue: c0:(lq,2lr) c1:(lq,2lr+1) c2:(lq+8,2lr) c3:(lq+8,2lr+1) ----
    #pragma unroll
    for (int na = 0; na < 4; na++) {
        int gn = col0 + wn + na * 8 + 2 * lr;
        float b0 = bias ? bias[gn]     : 0.f;
        float b1 = bias ? bias[gn + 1] : 0.f;
        #pragma unroll
        for (int ma = 0; ma < 2; ma++) {
            int gm = row0 + wm + ma * 16 + lq;
            float v0 = c[ma][na][0] + b0;
            float v1 = c[ma][na][1] + b1;
            float v2 = c[ma][na][2] + b0;
            float v3 = c[ma][na][3] + b1;
            if (ACT == 1) {
                v0 = fmaxf(v0, 0.f); v1 = fmaxf(v1, 0.f);
                v2 = fmaxf(v2, 0.f); v3 = fmaxf(v3, 0.f);
            }
            if (gm < M)
                *reinterpret_cast<float2*>(C + (size_t)gm * N + gn) = make_float2(v0, v1);
            if (gm + 8 < M)
                *reinterpret_cast<float2*>(C + (size_t)(gm + 8) * N + gn) = make_float2(v2, v3);
        }
    }
}

// ---------------- concat into padded X ----------------
__global__ void concat_feats(const float* __restrict__ a, const float* __restrict__ goal,
                             const float* __restrict__ info, float* __restrict__ X, int n) {
    size_t i = (size_t)blockIdx.x * blockDim.x + threadIdx.x;
    size_t total = (size_t)n * FEATP;
    if (i >= total) return;
    int node = (int)(i / FEATP);
    int c = (int)(i % FEATP);
    float v;
    if (c < 512)       v = a[(size_t)node * 512 + c];
    else if (c < 1024) v = goal[(size_t)node * 512 + (c - 512)];
    else if (c < 1029) v = info[(size_t)node * 5 + (c - 1024)];
    else               v = 0.f;
    X[i] = v;
}

// ---------------- per-node dots: s = hw @ a1, t = hw @ a2 ----------------
__global__ void row_dots(const float* __restrict__ hw, const float* __restrict__ a,
                         float* __restrict__ s, float* __restrict__ t, int n) {
    int warp = (blockIdx.x * blockDim.x + threadIdx.x) >> 5;
    int lane = threadIdx.x & 31;
    if (warp >= n) return;
    const float* row = hw + (size_t)warp * HDIM;
    float s1 = 0.f, s2 = 0.f;
    #pragma unroll 4
    for (int c = lane; c < HDIM; c += 32) {
        float h = row[c];
        s1 += h * a[c];
        s2 += h * a[HDIM + c];
    }
    #pragma unroll
    for (int o = 16; o; o >>= 1) {
        s1 += __shfl_down_sync(0xffffffffu, s1, o);
        s2 += __shfl_down_sync(0xffffffffu, s2, o);
    }
    if (lane == 0) { s[warp] = s1; t[warp] = s2; }
}

// ================= CSR build (once per launch) =================
__global__ void zero_i(int* __restrict__ p, int n) {
    int i = blockIdx.x * blockDim.x + threadIdx.x;
    if (i < n) p[i] = 0;
}

__global__ void csr_count(const int* __restrict__ src, int* __restrict__ cnt, int E) {
    int i = blockIdx.x * blockDim.x + threadIdx.x;
    if (i < E) atomicAdd(&cnt[src[i]], 1);
}

__global__ void csr_scan(const int* __restrict__ cnt, int* __restrict__ off, int n) {
    __shared__ int sh[1024];
    __shared__ int carry;
    int tid = threadIdx.x;
    if (tid == 0) carry = 0;
    __syncthreads();
    for (int base = 0; base < n; base += 1024) {
        int i = base + tid;
        int v = (i < n) ? cnt[i] : 0;
        sh[tid] = v;
        __syncthreads();
        for (int o = 1; o < 1024; o <<= 1) {
            int x = (tid >= o) ? sh[tid - o] : 0;
            __syncthreads();
            sh[tid] += x;
            __syncthreads();
        }
        if (i < n) off[i] = carry + sh[tid] - v;
        __syncthreads();
        if (tid == 0) carry += sh[1023];
        __syncthreads();
    }
    if (tid == 0) off[n] = carry;
}

__global__ void csr_place(const int* __restrict__ src, const int* __restrict__ dst,
                          const int* __restrict__ off, int* __restrict__ cur,
                          int* __restrict__ dsts, int E) {
    int i = blockIdx.x * blockDim.x + threadIdx.x;
    if (i >= E) return;
    int u = src[i];
    int p = off[u] + atomicAdd(&cur[u], 1);
    dsts[p] = dst[i];
}

// ---------------- fused GAT aggregation (gather, no atomics) ----------------
__global__ void gat_aggregate(const int* __restrict__ off, const int* __restrict__ dsts,
                              const float* __restrict__ s, const float* __restrict__ t,
                              const float* __restrict__ hw, float* __restrict__ hout) {
    int u = blockIdx.x;
    int c = threadIdx.x;          // 0..127
    int beg = off[u], end = off[u + 1];
    float su = s[u];
    float4 acc = make_float4(0.f, 0.f, 0.f, 0.f);
    float dsum = 0.f;
    for (int p = beg; p < end; p++) {
        int d = dsts[p];
        float sc = su + t[d];
        float lr = sc > 0.f ? sc : 0.2f * sc;
        float ev = expf(-lr);
        dsum += ev;
        float4 v = *(reinterpret_cast<const float4*>(hw + (size_t)d * HDIM) + c);
        acc.x += ev * v.x; acc.y += ev * v.y;
        acc.z += ev * v.z; acc.w += ev * v.w;
    }
    float inv = 1.f / (dsum + 1e-10f);
    float4 o;
    o.x = fmaxf(acc.x * inv, 0.f);
    o.y = fmaxf(acc.y * inv, 0.f);
    o.z = fmaxf(acc.z * inv, 0.f);
    o.w = fmaxf(acc.w * inv, 0.f);
    *(reinterpret_cast<float4*>(hout + (size_t)u * HDIM) + c) = o;
}

// ---------------- final GEMV + sigmoid ----------------
__global__ void gemv_sigmoid(const float* __restrict__ h2, const float* __restrict__ v3,
                             const float* __restrict__ vb3, float* __restrict__ out, int n) {
    int warp = (blockIdx.x * blockDim.x + threadIdx.x) >> 5;
    int lane = threadIdx.x & 31;
    if (warp >= n) return;
    const float* row = h2 + (size_t)warp * HDIM;
    float acc = 0.f;
    #pragma unroll 4
    for (int c = lane; c < HDIM; c += 32) acc += row[c] * v3[c];
    #pragma unroll
    for (int o = 16; o; o >>= 1) acc += __shfl_down_sync(0xffffffffu, acc, o);
    if (lane == 0) {
        float x = acc + vb3[0];
        out[warp] = 1.f / (1.f + expf(-x));
    }
}

// ---------------- host launcher ----------------
extern "C" void kernel_launch(void* const* d_in, const int* in_sizes, int n_in,
                              void* d_out, int out_size) {
    const float* feat = (const float*)d_in[0];
    const float* goal = (const float*)d_in[1];
    const float* info = (const float*)d_in[2];
    const int*   esrc = (const int*)d_in[3];
    const int*   edst = (const int*)d_in[4];
    const float* W1   = (const float*)d_in[5];
    const float* b1   = (const float*)d_in[6];
    const float* W2   = (const float*)d_in[7];
    const float* b2   = (const float*)d_in[8];
    const float* W3   = (const float*)d_in[9];
    const float* b3   = (const float*)d_in[10];
    const float* V1   = (const float*)d_in[11];
    const float* vb1  = (const float*)d_in[12];
    const float* V2   = (const float*)d_in[13];
    const float* vb2  = (const float*)d_in[14];
    const float* V3   = (const float*)d_in[15];
    const float* vb3  = (const float*)d_in[16];
    const float* gatW = (const float*)d_in[17];
    const float* gatA = (const float*)d_in[18];
    float* out = (float*)d_out;

    int E = in_sizes[3];
    if (E > E_CAP) E = E_CAP;
    const int n = N_NODES;

    float *X, *h, *hw, *acc, *s, *t;
    int *cnt, *off, *cur, *dsts;
    uint32_t *Bh, *Bl;
    cudaGetSymbolAddress((void**)&X,   g_X);
    cudaGetSymbolAddress((void**)&h,   g_h);
    cudaGetSymbolAddress((void**)&hw,  g_hw);
    cudaGetSymbolAddress((void**)&acc, g_acc);
    cudaGetSymbolAddress((void**)&s,   g_s);
    cudaGetSymbolAddress((void**)&t,   g_t);
    cudaGetSymbolAddress((void**)&cnt, g_cnt);
    cudaGetSymbolAddress((void**)&off, g_off);
    cudaGetSymbolAddress((void**)&cur, g_cur);
    cudaGetSymbolAddress((void**)&dsts,g_dsts);
    cudaGetSymbolAddress((void**)&Bh,  g_Bh);
    cudaGetSymbolAddress((void**)&Bl,  g_Bl);

    const dim3 gemm_grid(HDIM / TBN, (n + TBM - 1) / TBM);   // 8 x 157
    const int concat_blocks = (int)(((size_t)n * FEATP + 255) / 256);
    const int node_warp_blocks = (n * 32 + 255) / 256;
    const int edge_blocks = (E + 255) / 256;

    // ---- split all weights once ----
    {
        const int tpb = 256;
        int nf = K2_FEAT * HDIM, nh = K2_H * HDIM;
        split_w<<<(nf + tpb - 1) / tpb, tpb>>>(W1, Bh + (size_t)OFF_W1 * HDIM, Bl + (size_t)OFF_W1 * HDIM, FEAT, K2_FEAT);
        split_w<<<(nf + tpb - 1) / tpb, tpb>>>(V1, Bh + (size_t)OFF_V1 * HDIM, Bl + (size_t)OFF_V1 * HDIM, FEAT, K2_FEAT);
        split_w<<<(nh + tpb - 1) / tpb, tpb>>>(W2, Bh + (size_t)OFF_W2 * HDIM, Bl + (size_t)OFF_W2 * HDIM, HDIM, K2_H);
        split_w<<<(nh + tpb - 1) / tpb, tpb>>>(W3, Bh + (size_t)OFF_W3 * HDIM, Bl + (size_t)OFF_W3 * HDIM, HDIM, K2_H);
        split_w<<<(nh + tpb - 1) / tpb, tpb>>>(V2, Bh + (size_t)OFF_V2 * HDIM, Bl + (size_t)OFF_V2 * HDIM, HDIM, K2_H);
        for (int l = 0; l < NUM_GAT; l++)
            split_w<<<(nh + tpb - 1) / tpb, tpb>>>(gatW + (size_t)l * HDIM * HDIM,
                                                   Bh + (size_t)(OFF_GAT0 + l * K2_H) * HDIM,
                                                   Bl + (size_t)(OFF_GAT0 + l * K2_H) * HDIM, HDIM, K2_H);
    }

    // ---- CSR build (once; reused by all 5 GAT layers) ----
    zero_i<<<(n + 255) / 256, 256>>>(cnt, n);
    zero_i<<<(n + 255) / 256, 256>>>(cur, n);
    csr_count<<<edge_blocks, 256>>>(esrc, cnt, E);
    csr_scan<<<1, 1024>>>(cnt, off, n);
    csr_place<<<edge_blocks, 256>>>(esrc, edst, off, cur, dsts, E);

    const int KP_FEAT = 2 * K2_FEAT;   // 1056
    const int KP_H    = 2 * K2_H;      // 512

    // ---- input MLP ---- (layer 3 has NO relu)
    concat_feats<<<concat_blocks, 256>>>(feat, goal, info, X, n);
    gemm_split_bf16<1><<<gemm_grid, 256>>>(X,  Bh + (size_t)OFF_W1 * HDIM, Bl + (size_t)OFF_W1 * HDIM, b1, h,  n, FEATP, KP_FEAT, HDIM);
    gemm_split_bf16<1><<<gemm_grid, 256>>>(h,  Bh + (size_t)OFF_W2 * HDIM, Bl + (size_t)OFF_W2 * HDIM, b2, hw, n, HDIM,  KP_H,    HDIM);
    gemm_split_bf16<0><<<gemm_grid, 256>>>(hw, Bh + (size_t)OFF_W3 * HDIM, Bl + (size_t)OFF_W3 * HDIM, b3, h,  n, HDIM,  KP_H,    HDIM);

    // ---- GAT layers ----
    for (int l = 0; l < NUM_GAT; l++) {
        const float* al = gatA + (size_t)l * 2 * HDIM;
        gemm_split_bf16<0><<<gemm_grid, 256>>>(h, Bh + (size_t)(OFF_GAT0 + l * K2_H) * HDIM,
                                               Bl + (size_t)(OFF_GAT0 + l * K2_H) * HDIM,
                                               nullptr, hw, n, HDIM, KP_H, HDIM);
        row_dots<<<node_warp_blocks, 256>>>(hw, al, s, t, n);
        gat_aggregate<<<n, 128>>>(off, dsts, s, t, hw, h);
    }

    // ---- output MLP ----
    concat_feats<<<concat_blocks, 256>>>(h, goal, info, X, n);
    gemm_split_bf16<1><<<gemm_grid, 256>>>(X,  Bh + (size_t)OFF_V1 * HDIM, Bl + (size_t)OFF_V1 * HDIM, vb1, hw,  n, FEATP, KP_FEAT, HDIM);
    gemm_split_bf16<1><<<gemm_grid, 256>>>(hw, Bh + (size_t)OFF_V2 * HDIM, Bl + (size_t)OFF_V2 * HDIM, vb2, acc, n, HDIM,  KP_H,    HDIM);
    gemv_sigmoid<<<node_warp_blocks, 256>>>(acc, V3, vb3, out, n);
}

// round 7
// speedup vs baseline: 2.7962x; 1.0186x over previous
#include <cuda_runtime.h>
#include <cuda_bf16.h>
#include <math.h>
#include <stdint.h>

#define N_NODES 20000
#define HDIM    512
#define FEAT    1029
#define NUM_GAT 5
#define E_CAP   360000

// k2-row counts (bf16 pairs) per weight, padded to multiple of 16
#define K2_FEAT 528    // ceil(1029/2)=515 -> 528  (KP=1056)
#define K2_H    256
#define OFF_W1   0
#define OFF_V1   (K2_FEAT)
#define OFF_W2   (2*K2_FEAT)
#define OFF_W3   (OFF_W2 + K2_H)
#define OFF_V2   (OFF_W3 + K2_H)
#define OFF_GAT0 (OFF_V2 + K2_H)
#define K2_TOTAL (OFF_GAT0 + 5*K2_H)

// ---------------- scratch (device globals; no allocation) ----------------
__device__ float    g_h   [(size_t)N_NODES * HDIM];
__device__ float    g_hw  [(size_t)N_NODES * HDIM];
__device__ float    g_acc [(size_t)N_NODES * HDIM];
__device__ float    g_s   [N_NODES];
__device__ float    g_t   [N_NODES];
__device__ int      g_cnt [N_NODES];
__device__ int      g_off [N_NODES + 1];
__device__ int      g_cur [N_NODES];
__device__ int      g_dsts[E_CAP];     // dst reordered, grouped by src
__device__ int      g_srcs[E_CAP];     // src of each reordered edge
__device__ float    g_e   [E_CAP];     // per-edge weight (CSR order)
__device__ uint32_t g_Bh  [(size_t)K2_TOTAL * HDIM];
__device__ uint32_t g_Bl  [(size_t)K2_TOTAL * HDIM];

// ---------------- weight split ----------------
__global__ void split_w(const float* __restrict__ B, uint32_t* __restrict__ Bh,
                        uint32_t* __restrict__ Bl, int KB, int k2rows) {
    int idx = blockIdx.x * blockDim.x + threadIdx.x;
    if (idx >= k2rows * HDIM) return;
    int k2 = idx >> 9, n = idx & 511;
    int k = 2 * k2;
    float x0 = (k     < KB) ? B[(size_t)k * HDIM + n]       : 0.f;
    float x1 = (k + 1 < KB) ? B[(size_t)(k + 1) * HDIM + n] : 0.f;
    float h0 = __bfloat162float(__float2bfloat16(x0));
    float h1 = __bfloat162float(__float2bfloat16(x1));
    __nv_bfloat162 hp = __floats2bfloat162_rn(x0, x1);
    __nv_bfloat162 lp = __floats2bfloat162_rn(x0 - h0, x1 - h1);
    Bh[idx] = *reinterpret_cast<uint32_t*>(&hp);
    Bl[idx] = *reinterpret_cast<uint32_t*>(&lp);
}

// ================= 3-pass split-bf16 GEMM (m16n8k16) =================
#define TBM 128
#define TBN 64
#define ASTR 136
#define BSTR 72

__device__ __forceinline__ void mma_bf16(float* c, const uint32_t* a, const uint32_t* b) {
    asm("mma.sync.aligned.m16n8k16.row.col.f32.bf16.bf16.f32 "
        "{%0,%1,%2,%3}, {%4,%5,%6,%7}, {%8,%9}, {%0,%1,%2,%3};"
        : "+f"(c[0]), "+f"(c[1]), "+f"(c[2]), "+f"(c[3])
        : "r"(a[0]), "r"(a[1]), "r"(a[2]), "r"(a[3]), "r"(b[0]), "r"(b[1]));
}

struct SmemTiles {
    uint32_t As_hi[16 * ASTR];
    uint32_t As_lo[16 * ASTR];
    uint32_t Bs_hi[16 * BSTR];
    uint32_t Bs_lo[16 * BSTR];
};

__device__ __forceinline__ void stage_a(SmemTiles& S, float4 v, int k2, int m) {
    float h0 = __bfloat162float(__float2bfloat16(v.x));
    float h1 = __bfloat162float(__float2bfloat16(v.y));
    float h2 = __bfloat162float(__float2bfloat16(v.z));
    float h3 = __bfloat162float(__float2bfloat16(v.w));
    __nv_bfloat162 hp0 = __floats2bfloat162_rn(v.x, v.y);
    __nv_bfloat162 hp1 = __floats2bfloat162_rn(v.z, v.w);
    __nv_bfloat162 lp0 = __floats2bfloat162_rn(v.x - h0, v.y - h1);
    __nv_bfloat162 lp1 = __floats2bfloat162_rn(v.z - h2, v.w - h3);
    S.As_hi[(k2    ) * ASTR + m] = *reinterpret_cast<uint32_t*>(&hp0);
    S.As_hi[(k2 + 1) * ASTR + m] = *reinterpret_cast<uint32_t*>(&hp1);
    S.As_lo[(k2    ) * ASTR + m] = *reinterpret_cast<uint32_t*>(&lp0);
    S.As_lo[(k2 + 1) * ASTR + m] = *reinterpret_cast<uint32_t*>(&lp1);
}

// shared inner compute + epilogue
template <int ACT>
__device__ __forceinline__ void gemm_core(SmemTiles& S, float c[2][4][4],
                                          int wm, int wn, int lq, int lr) {
    #pragma unroll
    for (int ks2 = 0; ks2 < 16; ks2 += 8) {
        uint32_t ah[2][4], al[2][4], bh[4][2], bl[4][2];
        #pragma unroll
        for (int ma = 0; ma < 2; ma++) {
            int row = wm + ma * 16 + lq;
            int kA0 = (ks2 + lr) * ASTR, kA1 = (ks2 + lr + 4) * ASTR;
            ah[ma][0] = S.As_hi[kA0 + row];   ah[ma][1] = S.As_hi[kA0 + row + 8];
            ah[ma][2] = S.As_hi[kA1 + row];   ah[ma][3] = S.As_hi[kA1 + row + 8];
            al[ma][0] = S.As_lo[kA0 + row];   al[ma][1] = S.As_lo[kA0 + row + 8];
            al[ma][2] = S.As_lo[kA1 + row];   al[ma][3] = S.As_lo[kA1 + row + 8];
        }
        #pragma unroll
        for (int na = 0; na < 4; na++) {
            int ncol = wn + na * 8 + lq;
            int kB0 = (ks2 + lr) * BSTR, kB1 = (ks2 + lr + 4) * BSTR;
            bh[na][0] = S.Bs_hi[kB0 + ncol];  bh[na][1] = S.Bs_hi[kB1 + ncol];
            bl[na][0] = S.Bs_lo[kB0 + ncol];  bl[na][1] = S.Bs_lo[kB1 + ncol];
        }
        #pragma unroll
        for (int ma = 0; ma < 2; ma++) {
            #pragma unroll
            for (int na = 0; na < 4; na++) {
                mma_bf16(c[ma][na], ah[ma], bh[na]);
                mma_bf16(c[ma][na], ah[ma], bl[na]);
                mma_bf16(c[ma][na], al[ma], bh[na]);
            }
        }
    }
}

template <int ACT>
__device__ __forceinline__ void gemm_epilogue(float c[2][4][4], const float* bias,
                                              float* C, int M, int N,
                                              int row0, int col0, int wm, int wn,
                                              int lq, int lr) {
    #pragma unroll
    for (int na = 0; na < 4; na++) {
        int gn = col0 + wn + na * 8 + 2 * lr;
        float b0 = bias ? bias[gn]     : 0.f;
        float b1 = bias ? bias[gn + 1] : 0.f;
        #pragma unroll
        for (int ma = 0; ma < 2; ma++) {
            int gm = row0 + wm + ma * 16 + lq;
            float v0 = c[ma][na][0] + b0;
            float v1 = c[ma][na][1] + b1;
            float v2 = c[ma][na][2] + b0;
            float v3 = c[ma][na][3] + b1;
            if (ACT == 1) {
                v0 = fmaxf(v0, 0.f); v1 = fmaxf(v1, 0.f);
                v2 = fmaxf(v2, 0.f); v3 = fmaxf(v3, 0.f);
            }
            if (gm < M)
                *reinterpret_cast<float2*>(C + (size_t)gm * N + gn) = make_float2(v0, v1);
            if (gm + 8 < M)
                *reinterpret_cast<float2*>(C + (size_t)(gm + 8) * N + gn) = make_float2(v2, v3);
        }
    }
}

// ---- generic GEMM: A is a dense M x K fp32 matrix ----
template <int ACT>
__global__ __launch_bounds__(256, 2)
void gemm_split_bf16(const float* __restrict__ A, const uint32_t* __restrict__ Bh,
                     const uint32_t* __restrict__ Bl, const float* __restrict__ bias,
                     float* __restrict__ C, int M, int K, int KP, int N) {
    __shared__ SmemTiles S;
    const int tid  = threadIdx.x;
    const int wid  = tid >> 5;
    const int lane = tid & 31;
    const int lq   = lane >> 2, lr = lane & 3;
    const int wm   = (wid & 3) * 32, wn = (wid >> 2) * 32;
    const int row0 = blockIdx.y * TBM, col0 = blockIdx.x * TBN;

    float c[2][4][4] = {};
    const int mA = tid & 127, c4b = tid >> 7;
    const int rB = tid >> 4,  qB  = tid & 15;

    for (int k0 = 0; k0 < KP; k0 += 32) {
        #pragma unroll
        for (int it = 0; it < 4; it++) {
            int c4 = c4b + it * 2;
            int gm = row0 + mA, gk = k0 + c4 * 4;
            float4 v = make_float4(0.f, 0.f, 0.f, 0.f);
            if (gm < M && gk + 3 < K)
                v = *reinterpret_cast<const float4*>(A + (size_t)gm * K + gk);
            stage_a(S, v, c4 * 2, mA);
        }
        {
            size_t gidx = (size_t)((k0 >> 1) + rB) * N + col0 + qB * 4;
            *reinterpret_cast<uint4*>(&S.Bs_hi[rB * BSTR + qB * 4]) =
                *reinterpret_cast<const uint4*>(Bh + gidx);
            *reinterpret_cast<uint4*>(&S.Bs_lo[rB * BSTR + qB * 4]) =
                *reinterpret_cast<const uint4*>(Bl + gidx);
        }
        __syncthreads();
        gemm_core<ACT>(S, c, wm, wn, lq, lr);
        __syncthreads();
    }
    gemm_epilogue<ACT>(c, bias, C, M, N, row0, col0, wm, wn, lq, lr);
}

// ---- concat-fused GEMM: A row = [x(512) | goal(512) | info(5) | 0...] ----
__global__ __launch_bounds__(256, 2)
void gemm_split_bf16_cat(const float* __restrict__ xf, const float* __restrict__ goal,
                         const float* __restrict__ info,
                         const uint32_t* __restrict__ Bh, const uint32_t* __restrict__ Bl,
                         const float* __restrict__ bias, float* __restrict__ C,
                         int M, int KP, int N) {
    __shared__ SmemTiles S;
    const int tid  = threadIdx.x;
    const int wid  = tid >> 5;
    const int lane = tid & 31;
    const int lq   = lane >> 2, lr = lane & 3;
    const int wm   = (wid & 3) * 32, wn = (wid >> 2) * 32;
    const int row0 = blockIdx.y * TBM, col0 = blockIdx.x * TBN;

    float c[2][4][4] = {};
    const int mA = tid & 127, c4b = tid >> 7;
    const int rB = tid >> 4,  qB  = tid & 15;

    for (int k0 = 0; k0 < KP; k0 += 32) {
        #pragma unroll
        for (int it = 0; it < 4; it++) {
            int c4 = c4b + it * 2;
            int gm = row0 + mA, gk = k0 + c4 * 4;
            float4 v = make_float4(0.f, 0.f, 0.f, 0.f);
            if (gm < M) {
                if (gk < 512)
                    v = *reinterpret_cast<const float4*>(xf + (size_t)gm * 512 + gk);
                else if (gk < 1024)
                    v = *reinterpret_cast<const float4*>(goal + (size_t)gm * 512 + gk - 512);
                else if (gk == 1024) {
                    const float* ir = info + (size_t)gm * 5;
                    v = make_float4(ir[0], ir[1], ir[2], ir[3]);
                } else if (gk == 1028) {
                    v.x = info[(size_t)gm * 5 + 4];
                }
            }
            stage_a(S, v, c4 * 2, mA);
        }
        {
            size_t gidx = (size_t)((k0 >> 1) + rB) * N + col0 + qB * 4;
            *reinterpret_cast<uint4*>(&S.Bs_hi[rB * BSTR + qB * 4]) =
                *reinterpret_cast<const uint4*>(Bh + gidx);
            *reinterpret_cast<uint4*>(&S.Bs_lo[rB * BSTR + qB * 4]) =
                *reinterpret_cast<const uint4*>(Bl + gidx);
        }
        __syncthreads();
        gemm_core<1>(S, c, wm, wn, lq, lr);
        __syncthreads();
    }
    gemm_epilogue<1>(c, bias, C, M, N, row0, col0, wm, wn, lq, lr);
}

// ---------------- per-node dots ----------------
__global__ void row_dots(const float* __restrict__ hw, const float* __restrict__ a,
                         float* __restrict__ s, float* __restrict__ t, int n) {
    int warp = (blockIdx.x * blockDim.x + threadIdx.x) >> 5;
    int lane = threadIdx.x & 31;
    if (warp >= n) return;
    const float* row = hw + (size_t)warp * HDIM;
    float s1 = 0.f, s2 = 0.f;
    #pragma unroll 4
    for (int c = lane; c < HDIM; c += 32) {
        float h = row[c];
        s1 += h * a[c];
        s2 += h * a[HDIM + c];
    }
    #pragma unroll
    for (int o = 16; o; o >>= 1) {
        s1 += __shfl_down_sync(0xffffffffu, s1, o);
        s2 += __shfl_down_sync(0xffffffffu, s2, o);
    }
    if (lane == 0) { s[warp] = s1; t[warp] = s2; }
}

// ================= CSR build =================
__global__ void zero_i(int* __restrict__ p, int n) {
    int i = blockIdx.x * blockDim.x + threadIdx.x;
    if (i < n) p[i] = 0;
}

__global__ void csr_count(const int* __restrict__ src, int* __restrict__ cnt, int E) {
    int i = blockIdx.x * blockDim.x + threadIdx.x;
    if (i < E) atomicAdd(&cnt[src[i]], 1);
}

__global__ void csr_scan(const int* __restrict__ cnt, int* __restrict__ off, int n) {
    __shared__ int sh[1024];
    __shared__ int carry;
    int tid = threadIdx.x;
    if (tid == 0) carry = 0;
    __syncthreads();
    for (int base = 0; base < n; base += 1024) {
        int i = base + tid;
        int v = (i < n) ? cnt[i] : 0;
        sh[tid] = v;
        __syncthreads();
        for (int o = 1; o < 1024; o <<= 1) {
            int x = (tid >= o) ? sh[tid - o] : 0;
            __syncthreads();
            sh[tid] += x;
            __syncthreads();
        }
        if (i < n) off[i] = carry + sh[tid] - v;
        __syncthreads();
        if (tid == 0) carry += sh[1023];
        __syncthreads();
    }
    if (tid == 0) off[n] = carry;
}

__global__ void csr_place(const int* __restrict__ src, const int* __restrict__ dst,
                          const int* __restrict__ off, int* __restrict__ cur,
                          int* __restrict__ dsts, int* __restrict__ srcs, int E) {
    int i = blockIdx.x * blockDim.x + threadIdx.x;
    if (i >= E) return;
    int u = src[i];
    int p = off[u] + atomicAdd(&cur[u], 1);
    dsts[p] = dst[i];
    srcs[p] = u;
}

// ---------------- per-edge weights (once per layer, one exp per edge) ----------------
__global__ void edge_scores(const int* __restrict__ srcs, const int* __restrict__ dsts,
                            const float* __restrict__ s, const float* __restrict__ t,
                            float* __restrict__ e, int E) {
    int i = blockIdx.x * blockDim.x + threadIdx.x;
    if (i >= E) return;
    float sc = s[srcs[i]] + t[dsts[i]];
    float lr = sc > 0.f ? sc : 0.2f * sc;
    e[i] = expf(-lr);
}

// ---------------- GAT aggregation: pure gather + FMA ----------------
__global__ void gat_aggregate(const int* __restrict__ off, const int* __restrict__ dsts,
                              const float* __restrict__ e, const float* __restrict__ hw,
                              float* __restrict__ hout) {
    int u = blockIdx.x;
    int c = threadIdx.x;          // 0..127
    int beg = off[u], end = off[u + 1];
    float4 acc = make_float4(0.f, 0.f, 0.f, 0.f);
    float dsum = 0.f;
    for (int p = beg; p < end; p++) {
        int d = dsts[p];
        float ev = e[p];
        dsum += ev;
        float4 v = *(reinterpret_cast<const float4*>(hw + (size_t)d * HDIM) + c);
        acc.x += ev * v.x; acc.y += ev * v.y;
        acc.z += ev * v.z; acc.w += ev * v.w;
    }
    float inv = 1.f / (dsum + 1e-10f);
    float4 o;
    o.x = fmaxf(acc.x * inv, 0.f);
    o.y = fmaxf(acc.y * inv, 0.f);
    o.z = fmaxf(acc.z * inv, 0.f);
    o.w = fmaxf(acc.w * inv, 0.f);
    *(reinterpret_cast<float4*>(hout + (size_t)u * HDIM) + c) = o;
}

// ---------------- final GEMV + sigmoid ----------------
__global__ void gemv_sigmoid(const float* __restrict__ h2, const float* __restrict__ v3,
                             const float* __restrict__ vb3, float* __restrict__ out, int n) {
    int warp = (blockIdx.x * blockDim.x + threadIdx.x) >> 5;
    int lane = threadIdx.x & 31;
    if (warp >= n) return;
    const float* row = h2 + (size_t)warp * HDIM;
    float acc = 0.f;
    #pragma unroll 4
    for (int c = lane; c < HDIM; c += 32) acc += row[c] * v3[c];
    #pragma unroll
    for (int o = 16; o; o >>= 1) acc += __shfl_down_sync(0xffffffffu, acc, o);
    if (lane == 0) {
        float x = acc + vb3[0];
        out[warp] = 1.f / (1.f + expf(-x));
    }
}

// ---------------- host launcher ----------------
extern "C" void kernel_launch(void* const* d_in, const int* in_sizes, int n_in,
                              void* d_out, int out_size) {
    const float* feat = (const float*)d_in[0];
    const float* goal = (const float*)d_in[1];
    const float* info = (const float*)d_in[2];
    const int*   esrc = (const int*)d_in[3];
    const int*   edst = (const int*)d_in[4];
    const float* W1   = (const float*)d_in[5];
    const float* b1   = (const float*)d_in[6];
    const float* W2   = (const float*)d_in[7];
    const float* b2   = (const float*)d_in[8];
    const float* W3   = (const float*)d_in[9];
    const float* b3   = (const float*)d_in[10];
    const float* V1   = (const float*)d_in[11];
    const float* vb1  = (const float*)d_in[12];
    const float* V2   = (const float*)d_in[13];
    const float* vb2  = (const float*)d_in[14];
    const float* V3   = (const float*)d_in[15];
    const float* vb3  = (const float*)d_in[16];
    const float* gatW = (const float*)d_in[17];
    const float* gatA = (const float*)d_in[18];
    float* out = (float*)d_out;

    int E = in_sizes[3];
    if (E > E_CAP) E = E_CAP;
    const int n = N_NODES;

    float *h, *hw, *acc, *s, *t, *e;
    int *cnt, *off, *cur, *dsts, *srcs;
    uint32_t *Bh, *Bl;
    cudaGetSymbolAddress((void**)&h,   g_h);
    cudaGetSymbolAddress((void**)&hw,  g_hw);
    cudaGetSymbolAddress((void**)&acc, g_acc);
    cudaGetSymbolAddress((void**)&s,   g_s);
    cudaGetSymbolAddress((void**)&t,   g_t);
    cudaGetSymbolAddress((void**)&e,   g_e);
    cudaGetSymbolAddress((void**)&cnt, g_cnt);
    cudaGetSymbolAddress((void**)&off, g_off);
    cudaGetSymbolAddress((void**)&cur, g_cur);
    cudaGetSymbolAddress((void**)&dsts,g_dsts);
    cudaGetSymbolAddress((void**)&srcs,g_srcs);
    cudaGetSymbolAddress((void**)&Bh,  g_Bh);
    cudaGetSymbolAddress((void**)&Bl,  g_Bl);

    const dim3 gemm_grid(HDIM / TBN, (n + TBM - 1) / TBM);
    const int node_warp_blocks = (n * 32 + 255) / 256;
    const int edge_blocks = (E + 255) / 256;

    // ---- split all weights once ----
    {
        const int tpb = 256;
        int nf = K2_FEAT * HDIM, nh = K2_H * HDIM;
        split_w<<<(nf + tpb - 1) / tpb, tpb>>>(W1, Bh + (size_t)OFF_W1 * HDIM, Bl + (size_t)OFF_W1 * HDIM, FEAT, K2_FEAT);
        split_w<<<(nf + tpb - 1) / tpb, tpb>>>(V1, Bh + (size_t)OFF_V1 * HDIM, Bl + (size_t)OFF_V1 * HDIM, FEAT, K2_FEAT);
        split_w<<<(nh + tpb - 1) / tpb, tpb>>>(W2, Bh + (size_t)OFF_W2 * HDIM, Bl + (size_t)OFF_W2 * HDIM, HDIM, K2_H);
        split_w<<<(nh + tpb - 1) / tpb, tpb>>>(W3, Bh + (size_t)OFF_W3 * HDIM, Bl + (size_t)OFF_W3 * HDIM, HDIM, K2_H);
        split_w<<<(nh + tpb - 1) / tpb, tpb>>>(V2, Bh + (size_t)OFF_V2 * HDIM, Bl + (size_t)OFF_V2 * HDIM, HDIM, K2_H);
        for (int l = 0; l < NUM_GAT; l++)
            split_w<<<(nh + tpb - 1) / tpb, tpb>>>(gatW + (size_t)l * HDIM * HDIM,
                                                   Bh + (size_t)(OFF_GAT0 + l * K2_H) * HDIM,
                                                   Bl + (size_t)(OFF_GAT0 + l * K2_H) * HDIM, HDIM, K2_H);
    }

    // ---- CSR build ----
    zero_i<<<(n + 255) / 256, 256>>>(cnt, n);
    zero_i<<<(n + 255) / 256, 256>>>(cur, n);
    csr_count<<<edge_blocks, 256>>>(esrc, cnt, E);
    csr_scan<<<1, 1024>>>(cnt, off, n);
    csr_place<<<edge_blocks, 256>>>(esrc, edst, off, cur, dsts, srcs, E);

    const int KP_FEAT = 2 * K2_FEAT;   // 1056
    const int KP_H    = 2 * K2_H;      // 512

    // ---- input MLP (layer 3 has NO relu) ----
    gemm_split_bf16_cat<<<gemm_grid, 256>>>(feat, goal, info,
        Bh + (size_t)OFF_W1 * HDIM, Bl + (size_t)OFF_W1 * HDIM, b1, h, n, KP_FEAT, HDIM);
    gemm_split_bf16<1><<<gemm_grid, 256>>>(h,  Bh + (size_t)OFF_W2 * HDIM, Bl + (size_t)OFF_W2 * HDIM, b2, hw, n, HDIM, KP_H, HDIM);
    gemm_split_bf16<0><<<gemm_grid, 256>>>(hw, Bh + (size_t)OFF_W3 * HDIM, Bl + (size_t)OFF_W3 * HDIM, b3, h,  n, HDIM, KP_H, HDIM);

    // ---- GAT layers ----
    for (int l = 0; l < NUM_GAT; l++) {
        const float* al = gatA + (size_t)l * 2 * HDIM;
        gemm_split_bf16<0><<<gemm_grid, 256>>>(h, Bh + (size_t)(OFF_GAT0 + l * K2_H) * HDIM,
                                               Bl + (size_t)(OFF_GAT0 + l * K2_H) * HDIM,
                                               nullptr, hw, n, HDIM, KP_H, HDIM);
        row_dots<<<node_warp_blocks, 256>>>(hw, al, s, t, n);
        edge_scores<<<edge_blocks, 256>>>(srcs, dsts, s, t, e, E);
        gat_aggregate<<<n, 128>>>(off, dsts, e, hw, h);
    }

    // ---- output MLP ----
    gemm_split_bf16_cat<<<gemm_grid, 256>>>(h, goal, info,
        Bh + (size_t)OFF_V1 * HDIM, Bl + (size_t)OFF_V1 * HDIM, vb1, hw, n, KP_FEAT, HDIM);
    gemm_split_bf16<1><<<gemm_grid, 256>>>(hw, Bh + (size_t)OFF_V2 * HDIM, Bl + (size_t)OFF_V2 * HDIM, vb2, acc, n, HDIM, KP_H, HDIM);
    gemv_sigmoid<<<node_warp_blocks, 256>>>(acc, V3, vb3, out, n);
}

// round 9
// speedup vs baseline: 2.8490x; 1.0189x over previous
#include <cuda_runtime.h>
#include <cuda_bf16.h>
#include <math.h>
#include <stdint.h>

#define N_NODES 20000
#define HDIM    512
#define FEAT    1029
#define NUM_GAT 5
#define E_CAP   360000

// k2-row counts (bf16 pairs) per weight, padded to multiple of 16
#define K2_FEAT 528    // 33 chunks of 16 k2-rows (K=1056)
#define K2_H    256    // 16 chunks
#define OFF_W1   0
#define OFF_V1   (K2_FEAT)
#define OFF_W2   (2*K2_FEAT)
#define OFF_W3   (OFF_W2 + K2_H)
#define OFF_V2   (OFF_W3 + K2_H)
#define OFF_GAT0 (OFF_V2 + K2_H)
#define K2_TOTAL (OFF_GAT0 + 5*K2_H)

// ---------------- scratch (device globals; no allocation) ----------------
__device__ float    g_h   [(size_t)N_NODES * HDIM];
__device__ float    g_hw  [(size_t)N_NODES * HDIM];
__device__ float    g_acc [(size_t)N_NODES * HDIM];
__device__ float    g_s   [N_NODES];
__device__ float    g_t   [N_NODES];
__device__ int      g_cnt [N_NODES];
__device__ int      g_off [N_NODES + 1];
__device__ int      g_cur [N_NODES];
__device__ int      g_dsts[E_CAP];
__device__ int      g_srcs[E_CAP];
__device__ float    g_e   [E_CAP];
__device__ uint32_t g_Bh  [(size_t)K2_TOTAL * HDIM];   // bf16x2 hi, [k2][n]
__device__ uint32_t g_Bl  [(size_t)K2_TOTAL * HDIM];   // bf16x2 lo

// ---------------- weight split ----------------
__global__ void split_w(const float* __restrict__ B, uint32_t* __restrict__ Bh,
                        uint32_t* __restrict__ Bl, int KB, int k2rows) {
    int idx = blockIdx.x * blockDim.x + threadIdx.x;
    if (idx >= k2rows * HDIM) return;
    int k2 = idx >> 9, n = idx & 511;
    int k = 2 * k2;
    float x0 = (k     < KB) ? B[(size_t)k * HDIM + n]       : 0.f;
    float x1 = (k + 1 < KB) ? B[(size_t)(k + 1) * HDIM + n] : 0.f;
    float h0 = __bfloat162float(__float2bfloat16(x0));
    float h1 = __bfloat162float(__float2bfloat16(x1));
    __nv_bfloat162 hp = __floats2bfloat162_rn(x0, x1);
    __nv_bfloat162 lp = __floats2bfloat162_rn(x0 - h0, x1 - h1);
    Bh[idx] = *reinterpret_cast<uint32_t*>(&hp);
    Bl[idx] = *reinterpret_cast<uint32_t*>(&lp);
}

// ================= pipelined 3-pass split-bf16 GEMM (m16n8k16) =================
#define TBM 128
#define TBN 64
#define ASTR 136
#define BSTR 72
#define A_BUF_U32 (16 * ASTR)     // 2176 uint32 = 8704 B
#define B_BUF_U32 (16 * BSTR)     // 1152 uint32 = 4608 B
// dynamic smem layout (bytes)
#define SM_AH(s) ((s) * 8704)
#define SM_AL(s) (17408 + (s) * 8704)
#define SM_BH(s) (34816 + (s) * 4608)
#define SM_BL(s) (44032 + (s) * 4608)
#define SM_BYTES 53248

__device__ __forceinline__ uint32_t smem_u32(const void* p) {
    uint32_t a;
    asm("{ .reg .u64 t; cvta.to.shared.u64 t, %1; cvt.u32.u64 %0, t; }" : "=r"(a) : "l"(p));
    return a;
}

__device__ __forceinline__ void mma_bf16(float* c, const uint32_t* a, const uint32_t* b) {
    asm("mma.sync.aligned.m16n8k16.row.col.f32.bf16.bf16.f32 "
        "{%0,%1,%2,%3}, {%4,%5,%6,%7}, {%8,%9}, {%0,%1,%2,%3};"
        : "+f"(c[0]), "+f"(c[1]), "+f"(c[2]), "+f"(c[3])
        : "r"(a[0]), "r"(a[1]), "r"(a[2]), "r"(a[3]), "r"(b[0]), "r"(b[1]));
}

__device__ __forceinline__ void cp16(uint32_t dst, const void* src) {
    asm volatile("cp.async.cg.shared.global [%0], [%1], 16;" :: "r"(dst), "l"(src));
}

__device__ __forceinline__ void stage_a(uint32_t* AHp, uint32_t* ALp, float4 v, int k2, int m) {
    float h0 = __bfloat162float(__float2bfloat16(v.x));
    float h1 = __bfloat162float(__float2bfloat16(v.y));
    float h2 = __bfloat162float(__float2bfloat16(v.z));
    float h3 = __bfloat162float(__float2bfloat16(v.w));
    __nv_bfloat162 hp0 = __floats2bfloat162_rn(v.x, v.y);
    __nv_bfloat162 hp1 = __floats2bfloat162_rn(v.z, v.w);
    __nv_bfloat162 lp0 = __floats2bfloat162_rn(v.x - h0, v.y - h1);
    __nv_bfloat162 lp1 = __floats2bfloat162_rn(v.z - h2, v.w - h3);
    AHp[(k2    ) * ASTR + m] = *reinterpret_cast<uint32_t*>(&hp0);
    AHp[(k2 + 1) * ASTR + m] = *reinterpret_cast<uint32_t*>(&hp1);
    ALp[(k2    ) * ASTR + m] = *reinterpret_cast<uint32_t*>(&lp0);
    ALp[(k2 + 1) * ASTR + m] = *reinterpret_cast<uint32_t*>(&lp1);
}

__device__ __forceinline__ void gemm_core(const uint32_t* AHp, const uint32_t* ALp,
                                          const uint32_t* BHp, const uint32_t* BLp,
                                          float c[2][4][4], int wm, int wn, int lq, int lr) {
    #pragma unroll
    for (int ks2 = 0; ks2 < 16; ks2 += 8) {
        uint32_t ah[2][4], al[2][4], bh[4][2], bl[4][2];
        #pragma unroll
        for (int ma = 0; ma < 2; ma++) {
            int row = wm + ma * 16 + lq;
            int kA0 = (ks2 + lr) * ASTR, kA1 = (ks2 + lr + 4) * ASTR;
            ah[ma][0] = AHp[kA0 + row];   ah[ma][1] = AHp[kA0 + row + 8];
            ah[ma][2] = AHp[kA1 + row];   ah[ma][3] = AHp[kA1 + row + 8];
            al[ma][0] = ALp[kA0 + row];   al[ma][1] = ALp[kA0 + row + 8];
            al[ma][2] = ALp[kA1 + row];   al[ma][3] = ALp[kA1 + row + 8];
        }
        #pragma unroll
        for (int na = 0; na < 4; na++) {
            int ncol = wn + na * 8 + lq;
            int kB0 = (ks2 + lr) * BSTR, kB1 = (ks2 + lr + 4) * BSTR;
            bh[na][0] = BHp[kB0 + ncol];  bh[na][1] = BHp[kB1 + ncol];
            bl[na][0] = BLp[kB0 + ncol];  bl[na][1] = BLp[kB1 + ncol];
        }
        #pragma unroll
        for (int ma = 0; ma < 2; ma++) {
            #pragma unroll
            for (int na = 0; na < 4; na++) {
                mma_bf16(c[ma][na], ah[ma], bh[na]);
                mma_bf16(c[ma][na], ah[ma], bl[na]);
                mma_bf16(c[ma][na], al[ma], bh[na]);
            }
        }
    }
}

template <int ACT>
__device__ __forceinline__ void gemm_epilogue(float c[2][4][4], const float* bias,
                                              float* C, int M, int N, int row0, int col0,
                                              int wm, int wn, int lq, int lr) {
    #pragma unroll
    for (int na = 0; na < 4; na++) {
        int gn = col0 + wn + na * 8 + 2 * lr;
        float b0 = bias ? bias[gn]     : 0.f;
        float b1 = bias ? bias[gn + 1] : 0.f;
        #pragma unroll
        for (int ma = 0; ma < 2; ma++) {
            int gm = row0 + wm + ma * 16 + lq;
            float v0 = c[ma][na][0] + b0;
            float v1 = c[ma][na][1] + b1;
            float v2 = c[ma][na][2] + b0;
            float v3 = c[ma][na][3] + b1;
            if (ACT == 1) {
                v0 = fmaxf(v0, 0.f); v1 = fmaxf(v1, 0.f);
                v2 = fmaxf(v2, 0.f); v3 = fmaxf(v3, 0.f);
            }
            if (gm < M)
                *reinterpret_cast<float2*>(C + (size_t)gm * N + gn) = make_float2(v0, v1);
            if (gm + 8 < M)
                *reinterpret_cast<float2*>(C + (size_t)(gm + 8) * N + gn) = make_float2(v2, v3);
        }
    }
}

// CAT=0: A is dense M x Kdim fp32. CAT=1: A row = [xf(512)|goal(512)|info(5)|0..]
template <int ACT, int CAT>
__global__ __launch_bounds__(256, 2)
void gemm_pipe(const float* __restrict__ A, const float* __restrict__ goal,
               const float* __restrict__ info,
               const uint32_t* __restrict__ Bh, const uint32_t* __restrict__ Bl,
               const float* __restrict__ bias, float* __restrict__ C,
               int M, int Kdim, int nch) {
    extern __shared__ char smem[];
    const uint32_t sb = smem_u32(smem);
    const int tid  = threadIdx.x;
    const int wid  = tid >> 5;
    const int lane = tid & 31;
    const int lq   = lane >> 2, lr = lane & 3;
    const int wm   = (wid & 3) * 32, wn = (wid >> 2) * 32;
    const int row0 = blockIdx.y * TBM, col0 = blockIdx.x * TBN;

    float c[2][4][4] = {};

    const int mA  = tid & 127;
    const int c4b = tid >> 7;       // 0..1
    const int rB  = tid >> 4;       // 0..15
    const int qB  = tid & 15;       // 0..15
    const int gm  = row0 + mA;
    const bool mok = (gm < M);

    uint32_t pAH[2] = { sb + SM_AH(0), sb + SM_AH(1) };
    uint32_t pAL[2] = { sb + SM_AL(0), sb + SM_AL(1) };
    uint32_t pBH[2] = { sb + SM_BH(0), sb + SM_BH(1) };
    uint32_t pBL[2] = { sb + SM_BL(0), sb + SM_BL(1) };

    // ---- helpers as lambdas ----
    auto loadA = [&](int ch, float4* r) {
        int k0 = ch * 32;
        #pragma unroll
        for (int it = 0; it < 4; it++) {
            int c4 = c4b + it * 2;              // 0..7
            int gk = k0 + c4 * 4;
            float4 v = make_float4(0.f, 0.f, 0.f, 0.f);
            if (mok) {
                if (CAT == 0) {
                    if (gk + 3 < Kdim)
                        v = *reinterpret_cast<const float4*>(A + (size_t)gm * Kdim + gk);
                } else {
                    if (gk < 512)
                        v = *reinterpret_cast<const float4*>(A + (size_t)gm * 512 + gk);
                    else if (gk < 1024)
                        v = *reinterpret_cast<const float4*>(goal + (size_t)gm * 512 + gk - 512);
                    else if (gk == 1024) {
                        const float* ir = info + (size_t)gm * 5;
                        v = make_float4(ir[0], ir[1], ir[2], ir[3]);
                    } else if (gk == 1028) {
                        v.x = info[(size_t)gm * 5 + 4];
                    }
                }
            }
            r[it] = v;
        }
    };
    auto stsA = [&](int s, const float4* r) {
        uint32_t* AHp = reinterpret_cast<uint32_t*>(smem + SM_AH(s));
        uint32_t* ALp = reinterpret_cast<uint32_t*>(smem + SM_AL(s));
        #pragma unroll
        for (int it = 0; it < 4; it++) {
            int c4 = c4b + it * 2;
            stage_a(AHp, ALp, r[it], c4 * 2, mA);
        }
    };
    auto loadB = [&](int ch, int s) {
        size_t gidx = (size_t)(ch * 16 + rB) * HDIM + col0 + qB * 4;
        uint32_t dst = (uint32_t)((rB * BSTR + qB * 4) * 4);
        cp16(pBH[s] + dst, Bh + gidx);
        cp16(pBL[s] + dst, Bl + gidx);
        asm volatile("cp.async.commit_group;");
    };

    // ---- prologue: fill stage 0 ----
    float4 rA[4];
    loadA(0, rA);
    loadB(0, 0);
    stsA(0, rA);
    asm volatile("cp.async.wait_group 0;");
    __syncthreads();

    // ---- pipelined main loop ----
    for (int ch = 0; ch < nch; ch++) {
        int cur = ch & 1, nxt = cur ^ 1;
        bool more = (ch + 1 < nch);
        if (more) {
            loadA(ch + 1, rA);    // LDG in flight during compute
            loadB(ch + 1, nxt);   // cp.async in flight during compute
        }
        gemm_core(reinterpret_cast<uint32_t*>(smem + SM_AH(cur)),
                  reinterpret_cast<uint32_t*>(smem + SM_AL(cur)),
                  reinterpret_cast<uint32_t*>(smem + SM_BH(cur)),
                  reinterpret_cast<uint32_t*>(smem + SM_BL(cur)),
                  c, wm, wn, lq, lr);
        if (more) {
            stsA(nxt, rA);        // safe: nxt last read at ch-1, barrier passed
            asm volatile("cp.async.wait_group 0;");
        }
        __syncthreads();
    }

    gemm_epilogue<ACT>(c, bias, C, M, HDIM, row0, col0, wm, wn, lq, lr);
}

// ---------------- per-node dots ----------------
__global__ void row_dots(const float* __restrict__ hw, const float* __restrict__ a,
                         float* __restrict__ s, float* __restrict__ t, int n) {
    int warp = (blockIdx.x * blockDim.x + threadIdx.x) >> 5;
    int lane = threadIdx.x & 31;
    if (warp >= n) return;
    const float* row = hw + (size_t)warp * HDIM;
    float s1 = 0.f, s2 = 0.f;
    #pragma unroll 4
    for (int c = lane; c < HDIM; c += 32) {
        float h = row[c];
        s1 += h * a[c];
        s2 += h * a[HDIM + c];
    }
    #pragma unroll
    for (int o = 16; o; o >>= 1) {
        s1 += __shfl_down_sync(0xffffffffu, s1, o);
        s2 += __shfl_down_sync(0xffffffffu, s2, o);
    }
    if (lane == 0) { s[warp] = s1; t[warp] = s2; }
}

// ================= CSR build =================
__global__ void zero_i(int* __restrict__ p, int n) {
    int i = blockIdx.x * blockDim.x + threadIdx.x;
    if (i < n) p[i] = 0;
}
__global__ void csr_count(const int* __restrict__ src, int* __restrict__ cnt, int E) {
    int i = blockIdx.x * blockDim.x + threadIdx.x;
    if (i < E) atomicAdd(&cnt[src[i]], 1);
}
__global__ void csr_scan(const int* __restrict__ cnt, int* __restrict__ off, int n) {
    __shared__ int sh[1024];
    __shared__ int carry;
    int tid = threadIdx.x;
    if (tid == 0) carry = 0;
    __syncthreads();
    for (int base = 0; base < n; base += 1024) {
        int i = base + tid;
        int v = (i < n) ? cnt[i] : 0;
        sh[tid] = v;
        __syncthreads();
        for (int o = 1; o < 1024; o <<= 1) {
            int x = (tid >= o) ? sh[tid - o] : 0;
            __syncthreads();
            sh[tid] += x;
            __syncthreads();
        }
        if (i < n) off[i] = carry + sh[tid] - v;
        __syncthreads();
        if (tid == 0) carry += sh[1023];
        __syncthreads();
    }
    if (tid == 0) off[n] = carry;
}
__global__ void csr_place(const int* __restrict__ src, const int* __restrict__ dst,
                          const int* __restrict__ off, int* __restrict__ cur,
                          int* __restrict__ dsts, int* __restrict__ srcs, int E) {
    int i = blockIdx.x * blockDim.x + threadIdx.x;
    if (i >= E) return;
    int u = src[i];
    int p = off[u] + atomicAdd(&cur[u], 1);
    dsts[p] = dst[i];
    srcs[p] = u;
}

// ---------------- per-edge weights ----------------
__global__ void edge_scores(const int* __restrict__ srcs, const int* __restrict__ dsts,
                            const float* __restrict__ s, const float* __restrict__ t,
                            float* __restrict__ e, int E) {
    int i = blockIdx.x * blockDim.x + threadIdx.x;
    if (i >= E) return;
    float sc = s[srcs[i]] + t[dsts[i]];
    float lr = sc > 0.f ? sc : 0.2f * sc;
    e[i] = expf(-lr);
}

// ---------------- GAT aggregation ----------------
__global__ void gat_aggregate(const int* __restrict__ off, const int* __restrict__ dsts,
                              const float* __restrict__ e, const float* __restrict__ hw,
                              float* __restrict__ hout) {
    int u = blockIdx.x;
    int c = threadIdx.x;
    int beg = off[u], end = off[u + 1];
    float4 acc = make_float4(0.f, 0.f, 0.f, 0.f);
    float dsum = 0.f;
    for (int p = beg; p < end; p++) {
        int d = dsts[p];
        float ev = e[p];
        dsum += ev;
        float4 v = *(reinterpret_cast<const float4*>(hw + (size_t)d * HDIM) + c);
        acc.x += ev * v.x; acc.y += ev * v.y;
        acc.z += ev * v.z; acc.w += ev * v.w;
    }
    float inv = 1.f / (dsum + 1e-10f);
    float4 o;
    o.x = fmaxf(acc.x * inv, 0.f);
    o.y = fmaxf(acc.y * inv, 0.f);
    o.z = fmaxf(acc.z * inv, 0.f);
    o.w = fmaxf(acc.w * inv, 0.f);
    *(reinterpret_cast<float4*>(hout + (size_t)u * HDIM) + c) = o;
}

// ---------------- final GEMV + sigmoid ----------------
__global__ void gemv_sigmoid(const float* __restrict__ h2, const float* __restrict__ v3,
                             const float* __restrict__ vb3, float* __restrict__ out, int n) {
    int warp = (blockIdx.x * blockDim.x + threadIdx.x) >> 5;
    int lane = threadIdx.x & 31;
    if (warp >= n) return;
    const float* row = h2 + (size_t)warp * HDIM;
    float acc = 0.f;
    #pragma unroll 4
    for (int c = lane; c < HDIM; c += 32) acc += row[c] * v3[c];
    #pragma unroll
    for (int o = 16; o; o >>= 1) acc += __shfl_down_sync(0xffffffffu, acc, o);
    if (lane == 0) {
        float x = acc + vb3[0];
        out[warp] = 1.f / (1.f + expf(-x));
    }
}

// ---------------- host launcher ----------------
extern "C" void kernel_launch(void* const* d_in, const int* in_sizes, int n_in,
                              void* d_out, int out_size) {
    const float* feat = (const float*)d_in[0];
    const float* goal = (const float*)d_in[1];
    const float* info = (const float*)d_in[2];
    const int*   esrc = (const int*)d_in[3];
    const int*   edst = (const int*)d_in[4];
    const float* W1   = (const float*)d_in[5];
    const float* b1   = (const float*)d_in[6];
    const float* W2   = (const float*)d_in[7];
    const float* b2   = (const float*)d_in[8];
    const float* W3   = (const float*)d_in[9];
    const float* b3   = (const float*)d_in[10];
    const float* V1   = (const float*)d_in[11];
    const float* vb1  = (const float*)d_in[12];
    const float* V2   = (const float*)d_in[13];
    const float* vb2  = (const float*)d_in[14];
    const float* V3   = (const float*)d_in[15];
    const float* vb3  = (const float*)d_in[16];
    const float* gatW = (const float*)d_in[17];
    const float* gatA = (const float*)d_in[18];
    float* out = (float*)d_out;

    int E = in_sizes[3];
    if (E > E_CAP) E = E_CAP;
    const int n = N_NODES;

    float *h, *hw, *acc, *s, *t, *e;
    int *cnt, *off, *cur, *dsts, *srcs;
    uint32_t *Bh, *Bl;
    cudaGetSymbolAddress((void**)&h,   g_h);
    cudaGetSymbolAddress((void**)&hw,  g_hw);
    cudaGetSymbolAddress((void**)&acc, g_acc);
    cudaGetSymbolAddress((void**)&s,   g_s);
    cudaGetSymbolAddress((void**)&t,   g_t);
    cudaGetSymbolAddress((void**)&e,   g_e);
    cudaGetSymbolAddress((void**)&cnt, g_cnt);
    cudaGetSymbolAddress((void**)&off, g_off);
    cudaGetSymbolAddress((void**)&cur, g_cur);
    cudaGetSymbolAddress((void**)&dsts,g_dsts);
    cudaGetSymbolAddress((void**)&srcs,g_srcs);
    cudaGetSymbolAddress((void**)&Bh,  g_Bh);
    cudaGetSymbolAddress((void**)&Bl,  g_Bl);

    static bool attr_done = false;
    if (!attr_done) {
        cudaFuncSetAttribute(gemm_pipe<0,0>, cudaFuncAttributeMaxDynamicSharedMemorySize, SM_BYTES);
        cudaFuncSetAttribute(gemm_pipe<1,0>, cudaFuncAttributeMaxDynamicSharedMemorySize, SM_BYTES);
        cudaFuncSetAttribute(gemm_pipe<1,1>, cudaFuncAttributeMaxDynamicSharedMemorySize, SM_BYTES);
        attr_done = true;
    }

    const dim3 gg(HDIM / TBN, (n + TBM - 1) / TBM);   // 8 x 157
    const int node_warp_blocks = (n * 32 + 255) / 256;
    const int edge_blocks = (E + 255) / 256;

    // ---- split all weights once ----
    {
        const int tpb = 256;
        int nf = K2_FEAT * HDIM, nh = K2_H * HDIM;
        split_w<<<(nf + tpb - 1) / tpb, tpb>>>(W1, Bh + (size_t)OFF_W1 * HDIM, Bl + (size_t)OFF_W1 * HDIM, FEAT, K2_FEAT);
        split_w<<<(nf + tpb - 1) / tpb, tpb>>>(V1, Bh + (size_t)OFF_V1 * HDIM, Bl + (size_t)OFF_V1 * HDIM, FEAT, K2_FEAT);
        split_w<<<(nh + tpb - 1) / tpb, tpb>>>(W2, Bh + (size_t)OFF_W2 * HDIM, Bl + (size_t)OFF_W2 * HDIM, HDIM, K2_H);
        split_w<<<(nh + tpb - 1) / tpb, tpb>>>(W3, Bh + (size_t)OFF_W3 * HDIM, Bl + (size_t)OFF_W3 * HDIM, HDIM, K2_H);
        split_w<<<(nh + tpb - 1) / tpb, tpb>>>(V2, Bh + (size_t)OFF_V2 * HDIM, Bl + (size_t)OFF_V2 * HDIM, HDIM, K2_H);
        for (int l = 0; l < NUM_GAT; l++)
            split_w<<<(nh + tpb - 1) / tpb, tpb>>>(gatW + (size_t)l * HDIM * HDIM,
                                                   Bh + (size_t)(OFF_GAT0 + l * K2_H) * HDIM,
                                                   Bl + (size_t)(OFF_GAT0 + l * K2_H) * HDIM, HDIM, K2_H);
    }

    // ---- CSR build ----
    zero_i<<<(n + 255) / 256, 256>>>(cnt, n);
    zero_i<<<(n + 255) / 256, 256>>>(cur, n);
    csr_count<<<edge_blocks, 256>>>(esrc, cnt, E);
    csr_scan<<<1, 1024>>>(cnt, off, n);
    csr_place<<<edge_blocks, 256>>>(esrc, edst, off, cur, dsts, srcs, E);

    const int NCH_F = K2_FEAT / 16;   // 33
    const int NCH_H = K2_H / 16;      // 16

    // ---- input MLP (layer 3 has NO relu) ----
    gemm_pipe<1,1><<<gg, 256, SM_BYTES>>>(feat, goal, info,
        Bh + (size_t)OFF_W1 * HDIM, Bl + (size_t)OFF_W1 * HDIM, b1, h, n, FEAT, NCH_F);
    gemm_pipe<1,0><<<gg, 256, SM_BYTES>>>(h, nullptr, nullptr,
        Bh + (size_t)OFF_W2 * HDIM, Bl + (size_t)OFF_W2 * HDIM, b2, hw, n, HDIM, NCH_H);
    gemm_pipe<0,0><<<gg, 256, SM_BYTES>>>(hw, nullptr, nullptr,
        Bh + (size_t)OFF_W3 * HDIM, Bl + (size_t)OFF_W3 * HDIM, b3, h, n, HDIM, NCH_H);

    // ---- GAT layers ----
    for (int l = 0; l < NUM_GAT; l++) {
        const float* al = gatA + (size_t)l * 2 * HDIM;
        gemm_pipe<0,0><<<gg, 256, SM_BYTES>>>(h, nullptr, nullptr,
            Bh + (size_t)(OFF_GAT0 + l * K2_H) * HDIM,
            Bl + (size_t)(OFF_GAT0 + l * K2_H) * HDIM,
            nullptr, hw, n, HDIM, NCH_H);
        row_dots<<<node_warp_blocks, 256>>>(hw, al, s, t, n);
        edge_scores<<<edge_blocks, 256>>>(srcs, dsts, s, t, e, E);
        gat_aggregate<<<n, 128>>>(off, dsts, e, hw, h);
    }

    // ---- output MLP ----
    gemm_pipe<1,1><<<gg, 256, SM_BYTES>>>(h, goal, info,
        Bh + (size_t)OFF_V1 * HDIM, Bl + (size_t)OFF_V1 * HDIM, vb1, hw, n, FEAT, NCH_F);
    gemm_pipe<1,0><<<gg, 256, SM_BYTES>>>(hw, nullptr, nullptr,
        Bh + (size_t)OFF_V2 * HDIM, Bl + (size_t)OFF_V2 * HDIM, vb2, acc, n, HDIM, NCH_H);
    gemv_sigmoid<<<node_warp_blocks, 256>>>(acc, V3, vb3, out, n);
}

// round 10
// speedup vs baseline: 4.4280x; 1.5542x over previous
#include <cuda_runtime.h>
#include <cuda_bf16.h>
#include <math.h>
#include <stdint.h>

#define N_NODES 20000
#define MPAD    20096     // 157*128, so GEMM A-staging never goes OOB
#define HDIM    512
#define FEAT    1029
#define NUM_GAT 5
#define E_CAP   360000

// k2-row counts (bf16 pairs) per weight, padded to multiple of 16
#define K2_FEAT 528    // 33 chunks of 16 k2-rows (K=1056)
#define K2_H    256    // 16 chunks
#define OFF_W1   0
#define OFF_V1   (K2_FEAT)
#define OFF_W2   (2*K2_FEAT)
#define OFF_W3   (OFF_W2 + K2_H)
#define OFF_V2   (OFF_W3 + K2_H)
#define OFF_GAT0 (OFF_V2 + K2_H)
#define K2_TOTAL (OFF_GAT0 + 5*K2_H)

// ---------------- scratch (device globals; no allocation) ----------------
__device__ float    g_h   [(size_t)N_NODES * HDIM];
__device__ float    g_hw  [(size_t)N_NODES * HDIM];
__device__ float    g_acc [(size_t)N_NODES * HDIM];
__device__ float    g_s   [N_NODES];
__device__ float    g_t   [N_NODES];
__device__ int      g_cnt [N_NODES];
__device__ int      g_off [N_NODES + 1];
__device__ int      g_cur [N_NODES];
__device__ int      g_dsts[E_CAP];
__device__ int      g_srcs[E_CAP];
__device__ float    g_e   [E_CAP];
__device__ uint32_t g_Bh  [(size_t)K2_TOTAL * HDIM];   // weights: bf16x2 hi, [k2][n]
__device__ uint32_t g_Bl  [(size_t)K2_TOTAL * HDIM];
__device__ uint32_t g_Ah  [(size_t)K2_FEAT * MPAD];    // activations: bf16x2 hi, [k2][m]
__device__ uint32_t g_Al  [(size_t)K2_FEAT * MPAD];

// ---------------- split ALL weights in one launch ----------------
__global__ void split_all(const float* __restrict__ W1, const float* __restrict__ V1,
                          const float* __restrict__ W2, const float* __restrict__ W3,
                          const float* __restrict__ V2, const float* __restrict__ gatW,
                          uint32_t* __restrict__ Bh, uint32_t* __restrict__ Bl) {
    int idx = blockIdx.x * blockDim.x + threadIdx.x;
    if (idx >= K2_TOTAL * HDIM) return;
    int k2g = idx >> 9, n = idx & 511;
    const float* src; int KB, k2l;
    if (k2g < K2_FEAT)            { src = W1; k2l = k2g;            KB = FEAT; }
    else if (k2g < 2 * K2_FEAT)   { src = V1; k2l = k2g - K2_FEAT;  KB = FEAT; }
    else {
        int r = k2g - 2 * K2_FEAT;
        int w = r >> 8; k2l = r & 255; KB = HDIM;
        src = (w == 0) ? W2 : (w == 1) ? W3 : (w == 2) ? V2
                                            : gatW + (size_t)(w - 3) * HDIM * HDIM;
    }
    int k = 2 * k2l;
    float x0 = (k     < KB) ? src[(size_t)k * HDIM + n]       : 0.f;
    float x1 = (k + 1 < KB) ? src[(size_t)(k + 1) * HDIM + n] : 0.f;
    float h0 = __bfloat162float(__float2bfloat16(x0));
    float h1 = __bfloat162float(__float2bfloat16(x1));
    __nv_bfloat162 hp = __floats2bfloat162_rn(x0, x1);
    __nv_bfloat162 lp = __floats2bfloat162_rn(x0 - h0, x1 - h1);
    Bh[idx] = *reinterpret_cast<uint32_t*>(&hp);
    Bl[idx] = *reinterpret_cast<uint32_t*>(&lp);
}

// ---------------- activation convert: fp32 [m][k] -> split bf16x2 [k2][Mpad] ----------
// CAT=1: row = [A(512) | goal(512) | info(5) | 0...]
template <int CAT>
__global__ __launch_bounds__(256)
void conv_a(const float* __restrict__ A, const float* __restrict__ goal,
            const float* __restrict__ info, uint32_t* __restrict__ Ah,
            uint32_t* __restrict__ Al, int M, int Kdim) {
    __shared__ float tile[128][33];
    const int tid = threadIdx.x;
    const int m0 = blockIdx.x * 128;
    const int k0 = blockIdx.y * 32;
    const int ml = tid & 127, half = tid >> 7;
    const int gm = m0 + ml;
    #pragma unroll
    for (int i = 0; i < 4; i++) {
        int kk = k0 + half * 16 + i * 4;
        float4 v = make_float4(0.f, 0.f, 0.f, 0.f);
        if (gm < M) {
            if (CAT == 0) {
                if (kk + 3 < Kdim)
                    v = *reinterpret_cast<const float4*>(A + (size_t)gm * Kdim + kk);
            } else {
                if (kk < 512)
                    v = *reinterpret_cast<const float4*>(A + (size_t)gm * 512 + kk);
                else if (kk < 1024)
                    v = *reinterpret_cast<const float4*>(goal + (size_t)gm * 512 + kk - 512);
                else if (kk == 1024) {
                    const float* ir = info + (size_t)gm * 5;
                    v = make_float4(ir[0], ir[1], ir[2], ir[3]);
                } else if (kk == 1028) {
                    v.x = info[(size_t)gm * 5 + 4];
                }
            }
        }
        int cb = half * 16 + i * 4;
        tile[ml][cb + 0] = v.x; tile[ml][cb + 1] = v.y;
        tile[ml][cb + 2] = v.z; tile[ml][cb + 3] = v.w;
    }
    __syncthreads();
    const int k2l = tid >> 4, mq = tid & 15;
    const size_t k2g = blockIdx.y * 16 + k2l;
    #pragma unroll
    for (int j = 0; j < 8; j++) {
        int m = mq + j * 16;
        float x0 = tile[m][2 * k2l], x1 = tile[m][2 * k2l + 1];
        float h0 = __bfloat162float(__float2bfloat16(x0));
        float h1 = __bfloat162float(__float2bfloat16(x1));
        __nv_bfloat162 hp = __floats2bfloat162_rn(x0, x1);
        __nv_bfloat162 lp = __floats2bfloat162_rn(x0 - h0, x1 - h1);
        size_t o = k2g * MPAD + m0 + m;
        Ah[o] = *reinterpret_cast<uint32_t*>(&hp);
        Al[o] = *reinterpret_cast<uint32_t*>(&lp);
    }
}

// ================= pure-cp.async pipelined 3-pass split-bf16 GEMM =================
#define TBM 128
#define TBN 64
#define ASTR 136
#define BSTR 72
// dynamic smem layout (bytes)
#define SM_AH(s) ((s) * 8704)
#define SM_AL(s) (17408 + (s) * 8704)
#define SM_BH(s) (34816 + (s) * 4608)
#define SM_BL(s) (44032 + (s) * 4608)
#define SM_BYTES 53248

__device__ __forceinline__ uint32_t smem_u32(const void* p) {
    uint32_t a;
    asm("{ .reg .u64 t; cvta.to.shared.u64 t, %1; cvt.u32.u64 %0, t; }" : "=r"(a) : "l"(p));
    return a;
}
__device__ __forceinline__ void mma_bf16(float* c, const uint32_t* a, const uint32_t* b) {
    asm("mma.sync.aligned.m16n8k16.row.col.f32.bf16.bf16.f32 "
        "{%0,%1,%2,%3}, {%4,%5,%6,%7}, {%8,%9}, {%0,%1,%2,%3};"
        : "+f"(c[0]), "+f"(c[1]), "+f"(c[2]), "+f"(c[3])
        : "r"(a[0]), "r"(a[1]), "r"(a[2]), "r"(a[3]), "r"(b[0]), "r"(b[1]));
}
__device__ __forceinline__ void cp16(uint32_t dst, const void* src) {
    asm volatile("cp.async.cg.shared.global [%0], [%1], 16;" :: "r"(dst), "l"(src));
}

__device__ __forceinline__ void gemm_core(const uint32_t* AHp, const uint32_t* ALp,
                                          const uint32_t* BHp, const uint32_t* BLp,
                                          float c[2][4][4], int wm, int wn, int lq, int lr) {
    #pragma unroll
    for (int ks2 = 0; ks2 < 16; ks2 += 8) {
        uint32_t ah[2][4], al[2][4], bh[4][2], bl[4][2];
        #pragma unroll
        for (int ma = 0; ma < 2; ma++) {
            int row = wm + ma * 16 + lq;
            int kA0 = (ks2 + lr) * ASTR, kA1 = (ks2 + lr + 4) * ASTR;
            ah[ma][0] = AHp[kA0 + row];   ah[ma][1] = AHp[kA0 + row + 8];
            ah[ma][2] = AHp[kA1 + row];   ah[ma][3] = AHp[kA1 + row + 8];
            al[ma][0] = ALp[kA0 + row];   al[ma][1] = ALp[kA0 + row + 8];
            al[ma][2] = ALp[kA1 + row];   al[ma][3] = ALp[kA1 + row + 8];
        }
        #pragma unroll
        for (int na = 0; na < 4; na++) {
            int ncol = wn + na * 8 + lq;
            int kB0 = (ks2 + lr) * BSTR, kB1 = (ks2 + lr + 4) * BSTR;
            bh[na][0] = BHp[kB0 + ncol];  bh[na][1] = BHp[kB1 + ncol];
            bl[na][0] = BLp[kB0 + ncol];  bl[na][1] = BLp[kB1 + ncol];
        }
        #pragma unroll
        for (int ma = 0; ma < 2; ma++) {
            #pragma unroll
            for (int na = 0; na < 4; na++) {
                mma_bf16(c[ma][na], ah[ma], bh[na]);
                mma_bf16(c[ma][na], ah[ma], bl[na]);
                mma_bf16(c[ma][na], al[ma], bh[na]);
            }
        }
    }
}

template <int ACT>
__device__ __forceinline__ void gemm_epilogue(float c[2][4][4], const float* bias,
                                              float* C, int M, int row0, int col0,
                                              int wm, int wn, int lq, int lr) {
    #pragma unroll
    for (int na = 0; na < 4; na++) {
        int gn = col0 + wn + na * 8 + 2 * lr;
        float b0 = bias ? bias[gn]     : 0.f;
        float b1 = bias ? bias[gn + 1] : 0.f;
        #pragma unroll
        for (int ma = 0; ma < 2; ma++) {
            int gm = row0 + wm + ma * 16 + lq;
            float v0 = c[ma][na][0] + b0;
            float v1 = c[ma][na][1] + b1;
            float v2 = c[ma][na][2] + b0;
            float v3 = c[ma][na][3] + b1;
            if (ACT == 1) {
                v0 = fmaxf(v0, 0.f); v1 = fmaxf(v1, 0.f);
                v2 = fmaxf(v2, 0.f); v3 = fmaxf(v3, 0.f);
            }
            if (gm < M)
                *reinterpret_cast<float2*>(C + (size_t)gm * HDIM + gn) = make_float2(v0, v1);
            if (gm + 8 < M)
                *reinterpret_cast<float2*>(C + (size_t)(gm + 8) * HDIM + gn) = make_float2(v2, v3);
        }
    }
}

template <int ACT>
__global__ __launch_bounds__(256, 2)
void gemm_pp(const uint32_t* __restrict__ Ah, const uint32_t* __restrict__ Al,
             const uint32_t* __restrict__ Bh, const uint32_t* __restrict__ Bl,
             const float* __restrict__ bias, float* __restrict__ C, int M, int nch) {
    extern __shared__ char smem[];
    const uint32_t sb = smem_u32(smem);
    const int tid  = threadIdx.x;
    const int wid  = tid >> 5;
    const int lane = tid & 31;
    const int lq   = lane >> 2, lr = lane & 3;
    const int wm   = (wid & 3) * 32, wn = (wid >> 2) * 32;
    const int row0 = blockIdx.y * TBM, col0 = blockIdx.x * TBN;

    float c[2][4][4] = {};

    const int rA = tid >> 5;      // reuse wid? keep distinct names for clarity
    (void)rA;
    const int rB  = tid >> 4;     // 0..15
    const int qB  = tid & 15;     // 0..15

    auto loadStage = [&](int ch, int s) {
        // A: 16 k2-rows x 128 m words -> 512 uint4 per buffer, 2 per thread
        #pragma unroll
        for (int it = 0; it < 2; it++) {
            int f = tid + it * 256;
            int r2 = f >> 5, qm = f & 31;
            size_t gidx = (size_t)(ch * 16 + r2) * MPAD + row0 + qm * 4;
            uint32_t dst = (uint32_t)((r2 * ASTR + qm * 4) * 4);
            cp16(sb + SM_AH(s) + dst, Ah + gidx);
            cp16(sb + SM_AL(s) + dst, Al + gidx);
        }
        // B: 16 k2-rows x 64 n words -> 256 uint4 per buffer, 1 per thread
        {
            size_t gidx = (size_t)(ch * 16 + rB) * HDIM + col0 + qB * 4;
            uint32_t dst = (uint32_t)((rB * BSTR + qB * 4) * 4);
            cp16(sb + SM_BH(s) + dst, Bh + gidx);
            cp16(sb + SM_BL(s) + dst, Bl + gidx);
        }
        asm volatile("cp.async.commit_group;");
    };

    loadStage(0, 0);

    for (int ch = 0; ch < nch; ch++) {
        int cur = ch & 1, nxt = cur ^ 1;
        bool more = (ch + 1 < nch);
        if (more) {
            loadStage(ch + 1, nxt);
            asm volatile("cp.async.wait_group 1;");   // stage cur complete; next in flight
        } else {
            asm volatile("cp.async.wait_group 0;");
        }
        __syncthreads();
        gemm_core(reinterpret_cast<uint32_t*>(smem + SM_AH(cur)),
                  reinterpret_cast<uint32_t*>(smem + SM_AL(cur)),
                  reinterpret_cast<uint32_t*>(smem + SM_BH(cur)),
                  reinterpret_cast<uint32_t*>(smem + SM_BL(cur)),
                  c, wm, wn, lq, lr);
        __syncthreads();   // all warps done reading cur before it is overwritten at ch+2
    }

    gemm_epilogue<ACT>(c, bias, C, M, row0, col0, wm, wn, lq, lr);
}

// ---------------- per-node dots ----------------
__global__ void row_dots(const float* __restrict__ hw, const float* __restrict__ a,
                         float* __restrict__ s, float* __restrict__ t, int n) {
    int warp = (blockIdx.x * blockDim.x + threadIdx.x) >> 5;
    int lane = threadIdx.x & 31;
    if (warp >= n) return;
    const float* row = hw + (size_t)warp * HDIM;
    float s1 = 0.f, s2 = 0.f;
    #pragma unroll 4
    for (int c = lane; c < HDIM; c += 32) {
        float h = row[c];
        s1 += h * a[c];
        s2 += h * a[HDIM + c];
    }
    #pragma unroll
    for (int o = 16; o; o >>= 1) {
        s1 += __shfl_down_sync(0xffffffffu, s1, o);
        s2 += __shfl_down_sync(0xffffffffu, s2, o);
    }
    if (lane == 0) { s[warp] = s1; t[warp] = s2; }
}

// ================= CSR build =================
__global__ void zero2(int* __restrict__ a, int* __restrict__ b, int n) {
    int i = blockIdx.x * blockDim.x + threadIdx.x;
    if (i < n) { a[i] = 0; b[i] = 0; }
}
__global__ void csr_count(const int* __restrict__ src, int* __restrict__ cnt, int E) {
    int i = blockIdx.x * blockDim.x + threadIdx.x;
    if (i < E) atomicAdd(&cnt[src[i]], 1);
}
__global__ void csr_scan(const int* __restrict__ cnt, int* __restrict__ off, int n) {
    __shared__ int sh[1024];
    __shared__ int carry;
    int tid = threadIdx.x;
    if (tid == 0) carry = 0;
    __syncthreads();
    for (int base = 0; base < n; base += 1024) {
        int i = base + tid;
        int v = (i < n) ? cnt[i] : 0;
        sh[tid] = v;
        __syncthreads();
        for (int o = 1; o < 1024; o <<= 1) {
            int x = (tid >= o) ? sh[tid - o] : 0;
            __syncthreads();
            sh[tid] += x;
            __syncthreads();
        }
        if (i < n) off[i] = carry + sh[tid] - v;
        __syncthreads();
        if (tid == 0) carry += sh[1023];
        __syncthreads();
    }
    if (tid == 0) off[n] = carry;
}
__global__ void csr_place(const int* __restrict__ src, const int* __restrict__ dst,
                          const int* __restrict__ off, int* __restrict__ cur,
                          int* __restrict__ dsts, int* __restrict__ srcs, int E) {
    int i = blockIdx.x * blockDim.x + threadIdx.x;
    if (i >= E) return;
    int u = src[i];
    int p = off[u] + atomicAdd(&cur[u], 1);
    dsts[p] = dst[i];
    srcs[p] = u;
}

// ---------------- per-edge weights ----------------
__global__ void edge_scores(const int* __restrict__ srcs, const int* __restrict__ dsts,
                            const float* __restrict__ s, const float* __restrict__ t,
                            float* __restrict__ e, int E) {
    int i = blockIdx.x * blockDim.x + threadIdx.x;
    if (i >= E) return;
    float sc = s[srcs[i]] + t[dsts[i]];
    float lr = sc > 0.f ? sc : 0.2f * sc;
    e[i] = expf(-lr);
}

// ---------------- GAT aggregation ----------------
__global__ void gat_aggregate(const int* __restrict__ off, const int* __restrict__ dsts,
                              const float* __restrict__ e, const float* __restrict__ hw,
                              float* __restrict__ hout) {
    int u = blockIdx.x;
    int c = threadIdx.x;
    int beg = off[u], end = off[u + 1];
    float4 acc = make_float4(0.f, 0.f, 0.f, 0.f);
    float dsum = 0.f;
    for (int p = beg; p < end; p++) {
        int d = dsts[p];
        float ev = e[p];
        dsum += ev;
        float4 v = *(reinterpret_cast<const float4*>(hw + (size_t)d * HDIM) + c);
        acc.x += ev * v.x; acc.y += ev * v.y;
        acc.z += ev * v.z; acc.w += ev * v.w;
    }
    float inv = 1.f / (dsum + 1e-10f);
    float4 o;
    o.x = fmaxf(acc.x * inv, 0.f);
    o.y = fmaxf(acc.y * inv, 0.f);
    o.z = fmaxf(acc.z * inv, 0.f);
    o.w = fmaxf(acc.w * inv, 0.f);
    *(reinterpret_cast<float4*>(hout + (size_t)u * HDIM) + c) = o;
}

// ---------------- final GEMV + sigmoid ----------------
__global__ void gemv_sigmoid(const float* __restrict__ h2, const float* __restrict__ v3,
                             const float* __restrict__ vb3, float* __restrict__ out, int n) {
    int warp = (blockIdx.x * blockDim.x + threadIdx.x) >> 5;
    int lane = threadIdx.x & 31;
    if (warp >= n) return;
    const float* row = h2 + (size_t)warp * HDIM;
    float acc = 0.f;
    #pragma unroll 4
    for (int c = lane; c < HDIM; c += 32) acc += row[c] * v3[c];
    #pragma unroll
    for (int o = 16; o; o >>= 1) acc += __shfl_down_sync(0xffffffffu, acc, o);
    if (lane == 0) {
        float x = acc + vb3[0];
        out[warp] = 1.f / (1.f + expf(-x));
    }
}

// ---------------- host launcher ----------------
extern "C" void kernel_launch(void* const* d_in, const int* in_sizes, int n_in,
                              void* d_out, int out_size) {
    const float* feat = (const float*)d_in[0];
    const float* goal = (const float*)d_in[1];
    const float* info = (const float*)d_in[2];
    const int*   esrc = (const int*)d_in[3];
    const int*   edst = (const int*)d_in[4];
    const float* W1   = (const float*)d_in[5];
    const float* b1   = (const float*)d_in[6];
    const float* W2   = (const float*)d_in[7];
    const float* b2   = (const float*)d_in[8];
    const float* W3   = (const float*)d_in[9];
    const float* b3   = (const float*)d_in[10];
    const float* V1   = (const float*)d_in[11];
    const float* vb1  = (const float*)d_in[12];
    const float* V2   = (const float*)d_in[13];
    const float* vb2  = (const float*)d_in[14];
    const float* V3   = (const float*)d_in[15];
    const float* vb3  = (const float*)d_in[16];
    const float* gatW = (const float*)d_in[17];
    const float* gatA = (const float*)d_in[18];
    float* out = (float*)d_out;

    int E = in_sizes[3];
    if (E > E_CAP) E = E_CAP;
    const int n = N_NODES;

    float *h, *hw, *acc, *s, *t, *e;
    int *cnt, *off, *cur, *dsts, *srcs;
    uint32_t *Bh, *Bl, *Ah, *Al;
    cudaGetSymbolAddress((void**)&h,   g_h);
    cudaGetSymbolAddress((void**)&hw,  g_hw);
    cudaGetSymbolAddress((void**)&acc, g_acc);
    cudaGetSymbolAddress((void**)&s,   g_s);
    cudaGetSymbolAddress((void**)&t,   g_t);
    cudaGetSymbolAddress((void**)&e,   g_e);
    cudaGetSymbolAddress((void**)&cnt, g_cnt);
    cudaGetSymbolAddress((void**)&off, g_off);
    cudaGetSymbolAddress((void**)&cur, g_cur);
    cudaGetSymbolAddress((void**)&dsts,g_dsts);
    cudaGetSymbolAddress((void**)&srcs,g_srcs);
    cudaGetSymbolAddress((void**)&Bh,  g_Bh);
    cudaGetSymbolAddress((void**)&Bl,  g_Bl);
    cudaGetSymbolAddress((void**)&Ah,  g_Ah);
    cudaGetSymbolAddress((void**)&Al,  g_Al);

    static bool attr_done = false;
    if (!attr_done) {
        cudaFuncSetAttribute(gemm_pp<0>, cudaFuncAttributeMaxDynamicSharedMemorySize, SM_BYTES);
        cudaFuncSetAttribute(gemm_pp<1>, cudaFuncAttributeMaxDynamicSharedMemorySize, SM_BYTES);
        attr_done = true;
    }

    const dim3 gg(HDIM / TBN, (n + TBM - 1) / TBM);   // 8 x 157
    const dim3 cg_f(157, K2_FEAT / 16);               // cat conv: 33 k-blocks
    const dim3 cg_h(157, K2_H / 16);                  // H conv: 16 k-blocks
    const int node_warp_blocks = (n * 32 + 255) / 256;
    const int edge_blocks = (E + 255) / 256;

    #define BW(o) (Bh + (size_t)(o) * HDIM), (Bl + (size_t)(o) * HDIM)

    // launches 1-5 (so launch #6 = first big GEMM, which ncu -s 5 -c 1 captures)
    split_all<<<(K2_TOTAL * HDIM + 255) / 256, 256>>>(W1, V1, W2, W3, V2, gatW, Bh, Bl);
    zero2<<<(n + 255) / 256, 256>>>(cnt, cur, n);
    csr_count<<<edge_blocks, 256>>>(esrc, cnt, E);
    csr_scan<<<1, 1024>>>(cnt, off, n);
    conv_a<1><<<cg_f, 256>>>(feat, goal, info, Ah, Al, n, FEAT);

    // ---- input MLP (layer 3 has NO relu) ----
    gemm_pp<1><<<gg, 256, SM_BYTES>>>(Ah, Al, BW(OFF_W1), b1, h, n, K2_FEAT / 16);
    conv_a<0><<<cg_h, 256>>>(h, nullptr, nullptr, Ah, Al, n, HDIM);
    gemm_pp<1><<<gg, 256, SM_BYTES>>>(Ah, Al, BW(OFF_W2), b2, hw, n, K2_H / 16);
    conv_a<0><<<cg_h, 256>>>(hw, nullptr, nullptr, Ah, Al, n, HDIM);
    gemm_pp<0><<<gg, 256, SM_BYTES>>>(Ah, Al, BW(OFF_W3), b3, h, n, K2_H / 16);

    csr_place<<<edge_blocks, 256>>>(esrc, edst, off, cur, dsts, srcs, E);

    // ---- GAT layers ----
    for (int l = 0; l < NUM_GAT; l++) {
        const float* al = gatA + (size_t)l * 2 * HDIM;
        conv_a<0><<<cg_h, 256>>>(h, nullptr, nullptr, Ah, Al, n, HDIM);
        gemm_pp<0><<<gg, 256, SM_BYTES>>>(Ah, Al, BW(OFF_GAT0 + l * K2_H), nullptr, hw, n, K2_H / 16);
        row_dots<<<node_warp_blocks, 256>>>(hw, al, s, t, n);
        edge_scores<<<edge_blocks, 256>>>(srcs, dsts, s, t, e, E);
        gat_aggregate<<<n, 128>>>(off, dsts, e, hw, h);
    }

    // ---- output MLP ----
    conv_a<1><<<cg_f, 256>>>(h, goal, info, Ah, Al, n, FEAT);
    gemm_pp<1><<<gg, 256, SM_BYTES>>>(Ah, Al, BW(OFF_V1), vb1, hw, n, K2_FEAT / 16);
    conv_a<0><<<cg_h, 256>>>(hw, nullptr, nullptr, Ah, Al, n, HDIM);
    gemm_pp<1><<<gg, 256, SM_BYTES>>>(Ah, Al, BW(OFF_V2), vb2, acc, n, K2_H / 16);
    gemv_sigmoid<<<node_warp_blocks, 256>>>(acc, V3, vb3, out, n);
}

// round 11
// speedup vs baseline: 4.6214x; 1.0437x over previous
#include <cuda_runtime.h>
#include <cuda_bf16.h>
#include <math.h>
#include <stdint.h>

#define N_NODES 20000
#define MPAD    20096     // 157*128
#define HDIM    512
#define FEAT    1029
#define NUM_GAT 5
#define E_CAP   360000

#define K2_FEAT 528    // 33 chunks of 16 k2-rows (K=1056)
#define K2_H    256    // 16 chunks
#define OFF_W1   0
#define OFF_V1   (K2_FEAT)
#define OFF_W2   (2*K2_FEAT)
#define OFF_W3   (OFF_W2 + K2_H)
#define OFF_V2   (OFF_W3 + K2_H)
#define OFF_GAT0 (OFF_V2 + K2_H)
#define K2_TOTAL (OFF_GAT0 + 5*K2_H)

// ---------------- scratch (device globals; no allocation) ----------------
__device__ float    g_h   [(size_t)N_NODES * HDIM];
__device__ float    g_hw  [(size_t)N_NODES * HDIM];
__device__ float    g_acc [(size_t)N_NODES * HDIM];
__device__ float    g_s   [N_NODES];
__device__ float    g_t   [N_NODES];
__device__ int      g_cnt [N_NODES];
__device__ int      g_off [N_NODES + 1];
__device__ int      g_cur [N_NODES];
__device__ int      g_dsts[E_CAP];
__device__ int      g_srcs[E_CAP];
__device__ float    g_e   [E_CAP];
__device__ uint32_t g_Bh  [(size_t)K2_TOTAL * HDIM];
__device__ uint32_t g_Bl  [(size_t)K2_TOTAL * HDIM];
__device__ uint32_t g_A1h [(size_t)K2_FEAT * MPAD];   // big A buffer (cat GEMMs)
__device__ uint32_t g_A1l [(size_t)K2_FEAT * MPAD];
__device__ uint32_t g_A2h [(size_t)K2_H * MPAD];      // H-dim A buffer
__device__ uint32_t g_A2l [(size_t)K2_H * MPAD];

// ---------------- split ALL weights in one launch ----------------
__global__ void split_all(const float* __restrict__ W1, const float* __restrict__ V1,
                          const float* __restrict__ W2, const float* __restrict__ W3,
                          const float* __restrict__ V2, const float* __restrict__ gatW,
                          uint32_t* __restrict__ Bh, uint32_t* __restrict__ Bl) {
    int idx = blockIdx.x * blockDim.x + threadIdx.x;
    if (idx >= K2_TOTAL * HDIM) return;
    int k2g = idx >> 9, n = idx & 511;
    const float* src; int KB, k2l;
    if (k2g < K2_FEAT)            { src = W1; k2l = k2g;            KB = FEAT; }
    else if (k2g < 2 * K2_FEAT)   { src = V1; k2l = k2g - K2_FEAT;  KB = FEAT; }
    else {
        int r = k2g - 2 * K2_FEAT;
        int w = r >> 8; k2l = r & 255; KB = HDIM;
        src = (w == 0) ? W2 : (w == 1) ? W3 : (w == 2) ? V2
                                            : gatW + (size_t)(w - 3) * HDIM * HDIM;
    }
    int k = 2 * k2l;
    float x0 = (k     < KB) ? src[(size_t)k * HDIM + n]       : 0.f;
    float x1 = (k + 1 < KB) ? src[(size_t)(k + 1) * HDIM + n] : 0.f;
    float h0 = __bfloat162float(__float2bfloat16(x0));
    float h1 = __bfloat162float(__float2bfloat16(x1));
    __nv_bfloat162 hp = __floats2bfloat162_rn(x0, x1);
    __nv_bfloat162 lp = __floats2bfloat162_rn(x0 - h0, x1 - h1);
    Bh[idx] = *reinterpret_cast<uint32_t*>(&hp);
    Bl[idx] = *reinterpret_cast<uint32_t*>(&lp);
}

// ---------------- activation convert fp32 -> split bf16x2 [k2][MPAD] ----------
// CAT=1: row = [A(512) | goal(512) | info(5) | 0...]
template <int CAT>
__global__ __launch_bounds__(256)
void conv_a(const float* __restrict__ A, const float* __restrict__ goal,
            const float* __restrict__ info, uint32_t* __restrict__ Ah,
            uint32_t* __restrict__ Al, int M, int Kdim) {
    __shared__ float tile[128][33];
    const int tid = threadIdx.x;
    const int m0 = blockIdx.x * 128;
    const int k0 = blockIdx.y * 32;
    const int ml = tid & 127, half = tid >> 7;
    const int gm = m0 + ml;
    #pragma unroll
    for (int i = 0; i < 4; i++) {
        int kk = k0 + half * 16 + i * 4;
        float4 v = make_float4(0.f, 0.f, 0.f, 0.f);
        if (gm < M) {
            if (CAT == 0) {
                if (kk + 3 < Kdim)
                    v = *reinterpret_cast<const float4*>(A + (size_t)gm * Kdim + kk);
            } else {
                if (kk < 512)
                    v = *reinterpret_cast<const float4*>(A + (size_t)gm * 512 + kk);
                else if (kk < 1024)
                    v = *reinterpret_cast<const float4*>(goal + (size_t)gm * 512 + kk - 512);
                else if (kk == 1024) {
                    const float* ir = info + (size_t)gm * 5;
                    v = make_float4(ir[0], ir[1], ir[2], ir[3]);
                } else if (kk == 1028) {
                    v.x = info[(size_t)gm * 5 + 4];
                }
            }
        }
        int cb = half * 16 + i * 4;
        tile[ml][cb + 0] = v.x; tile[ml][cb + 1] = v.y;
        tile[ml][cb + 2] = v.z; tile[ml][cb + 3] = v.w;
    }
    __syncthreads();
    const int k2l = tid >> 4, mq = tid & 15;
    const size_t k2g = blockIdx.y * 16 + k2l;
    #pragma unroll
    for (int j = 0; j < 8; j++) {
        int m = mq + j * 16;
        float x0 = tile[m][2 * k2l], x1 = tile[m][2 * k2l + 1];
        float h0 = __bfloat162float(__float2bfloat16(x0));
        float h1 = __bfloat162float(__float2bfloat16(x1));
        __nv_bfloat162 hp = __floats2bfloat162_rn(x0, x1);
        __nv_bfloat162 lp = __floats2bfloat162_rn(x0 - h0, x1 - h1);
        size_t o = k2g * MPAD + m0 + m;
        Ah[o] = *reinterpret_cast<uint32_t*>(&hp);
        Al[o] = *reinterpret_cast<uint32_t*>(&lp);
    }
}

// ================= pipelined split-bf16 GEMM, block 128x128, warp 32x64 =========
#define TBM 128
#define TBN 128
#define ASTR 136
#define BSTR 136
// dynamic smem (bytes): 4 buffers x 2 stages x 8704
#define SM_AH(s) ((s) * 8704)
#define SM_AL(s) (17408 + (s) * 8704)
#define SM_BH(s) (34816 + (s) * 8704)
#define SM_BL(s) (52224 + (s) * 8704)
#define SM_BYTES 69632

__device__ __forceinline__ uint32_t smem_u32(const void* p) {
    uint32_t a;
    asm("{ .reg .u64 t; cvta.to.shared.u64 t, %1; cvt.u32.u64 %0, t; }" : "=r"(a) : "l"(p));
    return a;
}
__device__ __forceinline__ void mma_bf16(float* c, const uint32_t* a, const uint32_t* b) {
    asm("mma.sync.aligned.m16n8k16.row.col.f32.bf16.bf16.f32 "
        "{%0,%1,%2,%3}, {%4,%5,%6,%7}, {%8,%9}, {%0,%1,%2,%3};"
        : "+f"(c[0]), "+f"(c[1]), "+f"(c[2]), "+f"(c[3])
        : "r"(a[0]), "r"(a[1]), "r"(a[2]), "r"(a[3]), "r"(b[0]), "r"(b[1]));
}
__device__ __forceinline__ void cp16(uint32_t dst, const void* src) {
    asm volatile("cp.async.cg.shared.global [%0], [%1], 16;" :: "r"(dst), "l"(src));
}

// OUT: 0 = fp32 C ; 1 = split bf16x2 to Aoh/Aol ([k2][MPAD])
template <int ACT, int OUT>
__global__ __launch_bounds__(256, 2)
void gemm_pp(const uint32_t* __restrict__ Ah, const uint32_t* __restrict__ Al,
             const uint32_t* __restrict__ Bh, const uint32_t* __restrict__ Bl,
             const float* __restrict__ bias, float* __restrict__ C,
             uint32_t* __restrict__ Aoh, uint32_t* __restrict__ Aol,
             int M, int nch) {
    extern __shared__ char smem[];
    const uint32_t sb = smem_u32(smem);
    const int tid  = threadIdx.x;
    const int wid  = tid >> 5;
    const int lane = tid & 31;
    const int lq   = lane >> 2, lr = lane & 3;
    const int wm   = (wid & 3) * 32;    // 0,32,64,96
    const int wn   = (wid >> 2) * 64;   // 0,64
    const int row0 = blockIdx.y * TBM, col0 = blockIdx.x * TBN;

    float c[2][8][4] = {};

    auto loadStage = [&](int ch, int s) {
        #pragma unroll
        for (int it = 0; it < 2; it++) {
            int f = tid + it * 256;
            int r2 = f >> 5, q = f & 31;
            // A: 16 k2-rows x 128 m-words
            size_t gA = (size_t)(ch * 16 + r2) * MPAD + row0 + q * 4;
            uint32_t dA = (uint32_t)((r2 * ASTR + q * 4) * 4);
            cp16(sb + SM_AH(s) + dA, Ah + gA);
            cp16(sb + SM_AL(s) + dA, Al + gA);
            // B: 16 k2-rows x 128 n-words
            size_t gB = (size_t)(ch * 16 + r2) * HDIM + col0 + q * 4;
            uint32_t dB = (uint32_t)((r2 * BSTR + q * 4) * 4);
            cp16(sb + SM_BH(s) + dB, Bh + gB);
            cp16(sb + SM_BL(s) + dB, Bl + gB);
        }
        asm volatile("cp.async.commit_group;");
    };

    loadStage(0, 0);

    for (int ch = 0; ch < nch; ch++) {
        int cur = ch & 1, nxt = cur ^ 1;
        bool more = (ch + 1 < nch);
        if (more) {
            loadStage(ch + 1, nxt);
            asm volatile("cp.async.wait_group 1;");
        } else {
            asm volatile("cp.async.wait_group 0;");
        }
        __syncthreads();

        const uint32_t* AHp = reinterpret_cast<uint32_t*>(smem + SM_AH(cur));
        const uint32_t* ALp = reinterpret_cast<uint32_t*>(smem + SM_AL(cur));
        const uint32_t* BHp = reinterpret_cast<uint32_t*>(smem + SM_BH(cur));
        const uint32_t* BLp = reinterpret_cast<uint32_t*>(smem + SM_BL(cur));

        #pragma unroll
        for (int ks2 = 0; ks2 < 16; ks2 += 8) {
            uint32_t ah[2][4], al[2][4];
            #pragma unroll
            for (int ma = 0; ma < 2; ma++) {
                int row = wm + ma * 16 + lq;
                int kA0 = (ks2 + lr) * ASTR, kA1 = (ks2 + lr + 4) * ASTR;
                ah[ma][0] = AHp[kA0 + row];   ah[ma][1] = AHp[kA0 + row + 8];
                ah[ma][2] = AHp[kA1 + row];   ah[ma][3] = AHp[kA1 + row + 8];
                al[ma][0] = ALp[kA0 + row];   al[ma][1] = ALp[kA0 + row + 8];
                al[ma][2] = ALp[kA1 + row];   al[ma][3] = ALp[kA1 + row + 8];
            }
            #pragma unroll
            for (int ng = 0; ng < 2; ng++) {
                uint32_t bh[4][2], bl[4][2];
                #pragma unroll
                for (int nb = 0; nb < 4; nb++) {
                    int ncol = wn + (ng * 4 + nb) * 8 + lq;
                    int kB0 = (ks2 + lr) * BSTR, kB1 = (ks2 + lr + 4) * BSTR;
                    bh[nb][0] = BHp[kB0 + ncol];  bh[nb][1] = BHp[kB1 + ncol];
                    bl[nb][0] = BLp[kB0 + ncol];  bl[nb][1] = BLp[kB1 + ncol];
                }
                #pragma unroll
                for (int ma = 0; ma < 2; ma++) {
                    #pragma unroll
                    for (int nb = 0; nb < 4; nb++) {
                        float* cc = c[ma][ng * 4 + nb];
                        mma_bf16(cc, ah[ma], bh[nb]);
                        mma_bf16(cc, ah[ma], bl[nb]);
                        mma_bf16(cc, al[ma], bh[nb]);
                    }
                }
            }
        }
        __syncthreads();
    }

    // ---- epilogue: c regs map (row lq / lq+8, cols 2lr / 2lr+1) ----
    #pragma unroll
    for (int na = 0; na < 8; na++) {
        int gn = col0 + wn + na * 8 + 2 * lr;      // even
        float b0 = bias ? bias[gn]     : 0.f;
        float b1 = bias ? bias[gn + 1] : 0.f;
        #pragma unroll
        for (int ma = 0; ma < 2; ma++) {
            int gm = row0 + wm + ma * 16 + lq;
            float v0 = c[ma][na][0] + b0;
            float v1 = c[ma][na][1] + b1;
            float v2 = c[ma][na][2] + b0;
            float v3 = c[ma][na][3] + b1;
            if (ACT == 1) {
                v0 = fmaxf(v0, 0.f); v1 = fmaxf(v1, 0.f);
                v2 = fmaxf(v2, 0.f); v3 = fmaxf(v3, 0.f);
            }
            if (OUT == 0) {
                if (gm < M)
                    *reinterpret_cast<float2*>(C + (size_t)gm * HDIM + gn) = make_float2(v0, v1);
                if (gm + 8 < M)
                    *reinterpret_cast<float2*>(C + (size_t)(gm + 8) * HDIM + gn) = make_float2(v2, v3);
            } else {
                size_t o = (size_t)(gn >> 1) * MPAD;
                float h0 = __bfloat162float(__float2bfloat16(v0));
                float h1 = __bfloat162float(__float2bfloat16(v1));
                __nv_bfloat162 hp = __floats2bfloat162_rn(v0, v1);
                __nv_bfloat162 lp = __floats2bfloat162_rn(v0 - h0, v1 - h1);
                Aoh[o + gm] = *reinterpret_cast<uint32_t*>(&hp);
                Aol[o + gm] = *reinterpret_cast<uint32_t*>(&lp);
                float h2 = __bfloat162float(__float2bfloat16(v2));
                float h3 = __bfloat162float(__float2bfloat16(v3));
                __nv_bfloat162 hp2 = __floats2bfloat162_rn(v2, v3);
                __nv_bfloat162 lp2 = __floats2bfloat162_rn(v2 - h2, v3 - h3);
                Aoh[o + gm + 8] = *reinterpret_cast<uint32_t*>(&hp2);
                Aol[o + gm + 8] = *reinterpret_cast<uint32_t*>(&lp2);
            }
        }
    }
}

// ---------------- per-node dots ----------------
__global__ void row_dots(const float* __restrict__ hw, const float* __restrict__ a,
                         float* __restrict__ s, float* __restrict__ t, int n) {
    int warp = (blockIdx.x * blockDim.x + threadIdx.x) >> 5;
    int lane = threadIdx.x & 31;
    if (warp >= n) return;
    const float* row = hw + (size_t)warp * HDIM;
    float s1 = 0.f, s2 = 0.f;
    #pragma unroll 4
    for (int c = lane; c < HDIM; c += 32) {
        float h = row[c];
        s1 += h * a[c];
        s2 += h * a[HDIM + c];
    }
    #pragma unroll
    for (int o = 16; o; o >>= 1) {
        s1 += __shfl_down_sync(0xffffffffu, s1, o);
        s2 += __shfl_down_sync(0xffffffffu, s2, o);
    }
    if (lane == 0) { s[warp] = s1; t[warp] = s2; }
}

// ================= CSR build =================
__global__ void zero2(int* __restrict__ a, int* __restrict__ b, int n) {
    int i = blockIdx.x * blockDim.x + threadIdx.x;
    if (i < n) { a[i] = 0; b[i] = 0; }
}
__global__ void csr_count(const int* __restrict__ src, int* __restrict__ cnt, int E) {
    int i = blockIdx.x * blockDim.x + threadIdx.x;
    if (i < E) atomicAdd(&cnt[src[i]], 1);
}
// 1024 threads, each scans a 20-element segment serially; one block scan.
__global__ void csr_scan(const int* __restrict__ cnt, int* __restrict__ off, int n) {
    __shared__ int sh[1024];
    const int tid = threadIdx.x;
    const int seg = (n + 1023) / 1024;          // 20
    const int beg = tid * seg;
    int local[20];
    int sum = 0;
    #pragma unroll
    for (int j = 0; j < 20; j++) {
        int i = beg + j;
        int v = (j < seg && i < n) ? cnt[i] : 0;
        local[j] = sum;                          // exclusive within segment
        sum += v;
    }
    sh[tid] = sum;
    __syncthreads();
    #pragma unroll
    for (int o = 1; o < 1024; o <<= 1) {
        int x = (tid >= o) ? sh[tid - o] : 0;
        __syncthreads();
        sh[tid] += x;
        __syncthreads();
    }
    int base = (tid > 0) ? sh[tid - 1] : 0;
    #pragma unroll
    for (int j = 0; j < 20; j++) {
        int i = beg + j;
        if (j < seg && i < n) off[i] = base + local[j];
    }
    if (tid == 1023) off[n] = sh[1023];
}
__global__ void csr_place(const int* __restrict__ src, const int* __restrict__ dst,
                          const int* __restrict__ off, int* __restrict__ cur,
                          int* __restrict__ dsts, int* __restrict__ srcs, int E) {
    int i = blockIdx.x * blockDim.x + threadIdx.x;
    if (i >= E) return;
    int u = src[i];
    int p = off[u] + atomicAdd(&cur[u], 1);
    dsts[p] = dst[i];
    srcs[p] = u;
}

// ---------------- per-edge weights ----------------
__global__ void edge_scores(const int* __restrict__ srcs, const int* __restrict__ dsts,
                            const float* __restrict__ s, const float* __restrict__ t,
                            float* __restrict__ e, int E) {
    int i = blockIdx.x * blockDim.x + threadIdx.x;
    if (i >= E) return;
    float sc = s[srcs[i]] + t[dsts[i]];
    float lr = sc > 0.f ? sc : 0.2f * sc;
    e[i] = expf(-lr);
}

// ---------------- GAT aggregation ----------------
__global__ void gat_aggregate(const int* __restrict__ off, const int* __restrict__ dsts,
                              const float* __restrict__ e, const float* __restrict__ hw,
                              float* __restrict__ hout) {
    int u = blockIdx.x;
    int c = threadIdx.x;
    int beg = off[u], end = off[u + 1];
    float4 acc = make_float4(0.f, 0.f, 0.f, 0.f);
    float dsum = 0.f;
    for (int p = beg; p < end; p++) {
        int d = dsts[p];
        float ev = e[p];
        dsum += ev;
        float4 v = *(reinterpret_cast<const float4*>(hw + (size_t)d * HDIM) + c);
        acc.x += ev * v.x; acc.y += ev * v.y;
        acc.z += ev * v.z; acc.w += ev * v.w;
    }
    float inv = 1.f / (dsum + 1e-10f);
    float4 o;
    o.x = fmaxf(acc.x * inv, 0.f);
    o.y = fmaxf(acc.y * inv, 0.f);
    o.z = fmaxf(acc.z * inv, 0.f);
    o.w = fmaxf(acc.w * inv, 0.f);
    *(reinterpret_cast<float4*>(hout + (size_t)u * HDIM) + c) = o;
}

// ---------------- final GEMV + sigmoid ----------------
__global__ void gemv_sigmoid(const float* __restrict__ h2, const float* __restrict__ v3,
                             const float* __restrict__ vb3, float* __restrict__ out, int n) {
    int warp = (blockIdx.x * blockDim.x + threadIdx.x) >> 5;
    int lane = threadIdx.x & 31;
    if (warp >= n) return;
    const float* row = h2 + (size_t)warp * HDIM;
    float acc = 0.f;
    #pragma unroll 4
    for (int c = lane; c < HDIM; c += 32) acc += row[c] * v3[c];
    #pragma unroll
    for (int o = 16; o; o >>= 1) acc += __shfl_down_sync(0xffffffffu, acc, o);
    if (lane == 0) {
        float x = acc + vb3[0];
        out[warp] = 1.f / (1.f + expf(-x));
    }
}

// ---------------- host launcher ----------------
extern "C" void kernel_launch(void* const* d_in, const int* in_sizes, int n_in,
                              void* d_out, int out_size) {
    const float* feat = (const float*)d_in[0];
    const float* goal = (const float*)d_in[1];
    const float* info = (const float*)d_in[2];
    const int*   esrc = (const int*)d_in[3];
    const int*   edst = (const int*)d_in[4];
    const float* W1   = (const float*)d_in[5];
    const float* b1   = (const float*)d_in[6];
    const float* W2   = (const float*)d_in[7];
    const float* b2   = (const float*)d_in[8];
    const float* W3   = (const float*)d_in[9];
    const float* b3   = (const float*)d_in[10];
    const float* V1   = (const float*)d_in[11];
    const float* vb1  = (const float*)d_in[12];
    const float* V2   = (const float*)d_in[13];
    const float* vb2  = (const float*)d_in[14];
    const float* V3   = (const float*)d_in[15];
    const float* vb3  = (const float*)d_in[16];
    const float* gatW = (const float*)d_in[17];
    const float* gatA = (const float*)d_in[18];
    float* out = (float*)d_out;

    int E = in_sizes[3];
    if (E > E_CAP) E = E_CAP;
    const int n = N_NODES;

    float *h, *hw, *acc, *s, *t, *e;
    int *cnt, *off, *cur, *dsts, *srcs;
    uint32_t *Bh, *Bl, *A1h, *A1l, *A2h, *A2l;
    cudaGetSymbolAddress((void**)&h,   g_h);
    cudaGetSymbolAddress((void**)&hw,  g_hw);
    cudaGetSymbolAddress((void**)&acc, g_acc);
    cudaGetSymbolAddress((void**)&s,   g_s);
    cudaGetSymbolAddress((void**)&t,   g_t);
    cudaGetSymbolAddress((void**)&e,   g_e);
    cudaGetSymbolAddress((void**)&cnt, g_cnt);
    cudaGetSymbolAddress((void**)&off, g_off);
    cudaGetSymbolAddress((void**)&cur, g_cur);
    cudaGetSymbolAddress((void**)&dsts,g_dsts);
    cudaGetSymbolAddress((void**)&srcs,g_srcs);
    cudaGetSymbolAddress((void**)&Bh,  g_Bh);
    cudaGetSymbolAddress((void**)&Bl,  g_Bl);
    cudaGetSymbolAddress((void**)&A1h, g_A1h);
    cudaGetSymbolAddress((void**)&A1l, g_A1l);
    cudaGetSymbolAddress((void**)&A2h, g_A2h);
    cudaGetSymbolAddress((void**)&A2l, g_A2l);

    static bool attr_done = false;
    if (!attr_done) {
        cudaFuncSetAttribute(gemm_pp<0,0>, cudaFuncAttributeMaxDynamicSharedMemorySize, SM_BYTES);
        cudaFuncSetAttribute(gemm_pp<1,0>, cudaFuncAttributeMaxDynamicSharedMemorySize, SM_BYTES);
        cudaFuncSetAttribute(gemm_pp<0,1>, cudaFuncAttributeMaxDynamicSharedMemorySize, SM_BYTES);
        cudaFuncSetAttribute(gemm_pp<1,1>, cudaFuncAttributeMaxDynamicSharedMemorySize, SM_BYTES);
        attr_done = true;
    }

    const dim3 gg(HDIM / TBN, (n + TBM - 1) / TBM);   // 4 x 157
    const dim3 cg_f(157, K2_FEAT / 16);
    const dim3 cg_h(157, K2_H / 16);
    const int node_warp_blocks = (n * 32 + 255) / 256;
    const int edge_blocks = (E + 255) / 256;

    #define BW(o) (Bh + (size_t)(o) * HDIM), (Bl + (size_t)(o) * HDIM)

    // ---- input chain (GEMM at my launch #4 for ncu capture) ----
    split_all<<<(K2_TOTAL * HDIM + 255) / 256, 256>>>(W1, V1, W2, W3, V2, gatW, Bh, Bl);
    conv_a<1><<<cg_f, 256>>>(feat, goal, info, A1h, A1l, n, FEAT);
    gemm_pp<1,1><<<gg, 256, SM_BYTES>>>(A1h, A1l, BW(OFF_W1), b1, nullptr, A2h, A2l, n, K2_FEAT / 16);
    gemm_pp<1,1><<<gg, 256, SM_BYTES>>>(A2h, A2l, BW(OFF_W2), b2, nullptr, A1h, A1l, n, K2_H / 16);
    gemm_pp<0,1><<<gg, 256, SM_BYTES>>>(A1h, A1l, BW(OFF_W3), b3, nullptr, A2h, A2l, n, K2_H / 16);

    // ---- CSR build ----
    zero2<<<(n + 255) / 256, 256>>>(cnt, cur, n);
    csr_count<<<edge_blocks, 256>>>(esrc, cnt, E);
    csr_scan<<<1, 1024>>>(cnt, off, n);
    csr_place<<<edge_blocks, 256>>>(esrc, edst, off, cur, dsts, srcs, E);

    // ---- GAT layers: gemm reads A2 -> hw ; aggregate -> h ; conv h -> A2 ----
    for (int l = 0; l < NUM_GAT; l++) {
        const float* al = gatA + (size_t)l * 2 * HDIM;
        gemm_pp<0,0><<<gg, 256, SM_BYTES>>>(A2h, A2l, BW(OFF_GAT0 + l * K2_H),
                                            nullptr, hw, nullptr, nullptr, n, K2_H / 16);
        row_dots<<<node_warp_blocks, 256>>>(hw, al, s, t, n);
        edge_scores<<<edge_blocks, 256>>>(srcs, dsts, s, t, e, E);
        gat_aggregate<<<n, 128>>>(off, dsts, e, hw, h);
        if (l < NUM_GAT - 1)
            conv_a<0><<<cg_h, 256>>>(h, nullptr, nullptr, A2h, A2l, n, HDIM);
    }

    // ---- output MLP ----
    conv_a<1><<<cg_f, 256>>>(h, goal, info, A1h, A1l, n, FEAT);
    gemm_pp<1,1><<<gg, 256, SM_BYTES>>>(A1h, A1l, BW(OFF_V1), vb1, nullptr, A2h, A2l, n, K2_FEAT / 16);
    gemm_pp<1,0><<<gg, 256, SM_BYTES>>>(A2h, A2l, BW(OFF_V2), vb2, acc, nullptr, nullptr, n, K2_H / 16);
    gemv_sigmoid<<<node_warp_blocks, 256>>>(acc, V3, vb3, out, n);
}

// round 12
// speedup vs baseline: 4.7069x; 1.0185x over previous
#include <cuda_runtime.h>
#include <cuda_bf16.h>
#include <math.h>
#include <stdint.h>

#define N_NODES 20000
#define MPAD    20096     // 157*128
#define HDIM    512
#define FEAT    1029
#define NUM_GAT 5
#define E_CAP   360000

#define K2_FEAT 528    // 33 chunks of 16 k2-rows (K=1056)
#define K2_H    256    // 16 chunks
#define OFF_W1   0
#define OFF_V1   (K2_FEAT)
#define OFF_W2   (2*K2_FEAT)
#define OFF_W3   (OFF_W2 + K2_H)
#define OFF_V2   (OFF_W3 + K2_H)
#define OFF_GAT0 (OFF_V2 + K2_H)
#define K2_TOTAL (OFF_GAT0 + 5*K2_H)

// ---------------- scratch (device globals; no allocation) ----------------
__device__ float    g_h   [(size_t)N_NODES * HDIM];
__device__ float    g_hw  [(size_t)N_NODES * HDIM];
__device__ float    g_acc [(size_t)N_NODES * HDIM];
__device__ float    g_s   [N_NODES];
__device__ float    g_t   [N_NODES];
__device__ int      g_cnt [N_NODES];
__device__ int      g_off [N_NODES + 1];
__device__ int      g_cur [N_NODES];
__device__ int      g_dsts[E_CAP];
__device__ int      g_srcs[E_CAP];
__device__ float    g_e   [E_CAP];
__device__ uint32_t g_Bh  [(size_t)K2_TOTAL * HDIM];
__device__ uint32_t g_Bl  [(size_t)K2_TOTAL * HDIM];
__device__ uint32_t g_A1h [(size_t)K2_FEAT * MPAD];
__device__ uint32_t g_A1l [(size_t)K2_FEAT * MPAD];
__device__ uint32_t g_A2h [(size_t)K2_H * MPAD];
__device__ uint32_t g_A2l [(size_t)K2_H * MPAD];

// ---------------- split ALL weights in one launch ----------------
__global__ void split_all(const float* __restrict__ W1, const float* __restrict__ V1,
                          const float* __restrict__ W2, const float* __restrict__ W3,
                          const float* __restrict__ V2, const float* __restrict__ gatW,
                          uint32_t* __restrict__ Bh, uint32_t* __restrict__ Bl) {
    int idx = blockIdx.x * blockDim.x + threadIdx.x;
    if (idx >= K2_TOTAL * HDIM) return;
    int k2g = idx >> 9, n = idx & 511;
    const float* src; int KB, k2l;
    if (k2g < K2_FEAT)            { src = W1; k2l = k2g;            KB = FEAT; }
    else if (k2g < 2 * K2_FEAT)   { src = V1; k2l = k2g - K2_FEAT;  KB = FEAT; }
    else {
        int r = k2g - 2 * K2_FEAT;
        int w = r >> 8; k2l = r & 255; KB = HDIM;
        src = (w == 0) ? W2 : (w == 1) ? W3 : (w == 2) ? V2
                                            : gatW + (size_t)(w - 3) * HDIM * HDIM;
    }
    int k = 2 * k2l;
    float x0 = (k     < KB) ? src[(size_t)k * HDIM + n]       : 0.f;
    float x1 = (k + 1 < KB) ? src[(size_t)(k + 1) * HDIM + n] : 0.f;
    float h0 = __bfloat162float(__float2bfloat16(x0));
    float h1 = __bfloat162float(__float2bfloat16(x1));
    __nv_bfloat162 hp = __floats2bfloat162_rn(x0, x1);
    __nv_bfloat162 lp = __floats2bfloat162_rn(x0 - h0, x1 - h1);
    Bh[idx] = *reinterpret_cast<uint32_t*>(&hp);
    Bl[idx] = *reinterpret_cast<uint32_t*>(&lp);
}

// ---------------- activation convert fp32 -> split bf16x2 [k2][MPAD] ----------
template <int CAT>
__global__ __launch_bounds__(256)
void conv_a(const float* __restrict__ A, const float* __restrict__ goal,
            const float* __restrict__ info, uint32_t* __restrict__ Ah,
            uint32_t* __restrict__ Al, int M, int Kdim) {
    __shared__ float tile[128][33];
    const int tid = threadIdx.x;
    const int m0 = blockIdx.x * 128;
    const int k0 = blockIdx.y * 32;
    const int ml = tid & 127, half = tid >> 7;
    const int gm = m0 + ml;
    #pragma unroll
    for (int i = 0; i < 4; i++) {
        int kk = k0 + half * 16 + i * 4;
        float4 v = make_float4(0.f, 0.f, 0.f, 0.f);
        if (gm < M) {
            if (CAT == 0) {
                if (kk + 3 < Kdim)
                    v = *reinterpret_cast<const float4*>(A + (size_t)gm * Kdim + kk);
            } else {
                if (kk < 512)
                    v = *reinterpret_cast<const float4*>(A + (size_t)gm * 512 + kk);
                else if (kk < 1024)
                    v = *reinterpret_cast<const float4*>(goal + (size_t)gm * 512 + kk - 512);
                else if (kk == 1024) {
                    const float* ir = info + (size_t)gm * 5;
                    v = make_float4(ir[0], ir[1], ir[2], ir[3]);
                } else if (kk == 1028) {
                    v.x = info[(size_t)gm * 5 + 4];
                }
            }
        }
        int cb = half * 16 + i * 4;
        tile[ml][cb + 0] = v.x; tile[ml][cb + 1] = v.y;
        tile[ml][cb + 2] = v.z; tile[ml][cb + 3] = v.w;
    }
    __syncthreads();
    const int k2l = tid >> 4, mq = tid & 15;
    const size_t k2g = blockIdx.y * 16 + k2l;
    #pragma unroll
    for (int j = 0; j < 8; j++) {
        int m = mq + j * 16;
        float x0 = tile[m][2 * k2l], x1 = tile[m][2 * k2l + 1];
        float h0 = __bfloat162float(__float2bfloat16(x0));
        float h1 = __bfloat162float(__float2bfloat16(x1));
        __nv_bfloat162 hp = __floats2bfloat162_rn(x0, x1);
        __nv_bfloat162 lp = __floats2bfloat162_rn(x0 - h0, x1 - h1);
        size_t o = k2g * MPAD + m0 + m;
        Ah[o] = *reinterpret_cast<uint32_t*>(&hp);
        Al[o] = *reinterpret_cast<uint32_t*>(&lp);
    }
}

// ================= pipelined split-bf16 GEMM, block 128x128, warp 32x64 =========
#define TBM 128
#define TBN 128
#define ASTR 136
#define BSTR 136
#define SM_AH(s) ((s) * 8704)
#define SM_AL(s) (17408 + (s) * 8704)
#define SM_BH(s) (34816 + (s) * 8704)
#define SM_BL(s) (52224 + (s) * 8704)
#define SM_BYTES 69632

__device__ __forceinline__ uint32_t smem_u32(const void* p) {
    uint32_t a;
    asm("{ .reg .u64 t; cvta.to.shared.u64 t, %1; cvt.u32.u64 %0, t; }" : "=r"(a) : "l"(p));
    return a;
}
__device__ __forceinline__ void mma_bf16(float* c, const uint32_t* a, const uint32_t* b) {
    asm("mma.sync.aligned.m16n8k16.row.col.f32.bf16.bf16.f32 "
        "{%0,%1,%2,%3}, {%4,%5,%6,%7}, {%8,%9}, {%0,%1,%2,%3};"
        : "+f"(c[0]), "+f"(c[1]), "+f"(c[2]), "+f"(c[3])
        : "r"(a[0]), "r"(a[1]), "r"(a[2]), "r"(a[3]), "r"(b[0]), "r"(b[1]));
}
__device__ __forceinline__ void cp16(uint32_t dst, const void* src) {
    asm volatile("cp.async.cg.shared.global [%0], [%1], 16;" :: "r"(dst), "l"(src));
}

// OUT: 0 = fp32 C ; 1 = split bf16x2 to Aoh/Aol.  DOTS: also s/t partial dots.
template <int ACT, int OUT, int DOTS>
__global__ __launch_bounds__(256, 2)
void gemm_pp(const uint32_t* __restrict__ Ah, const uint32_t* __restrict__ Al,
             const uint32_t* __restrict__ Bh, const uint32_t* __restrict__ Bl,
             const float* __restrict__ bias, float* __restrict__ C,
             uint32_t* __restrict__ Aoh, uint32_t* __restrict__ Aol,
             const float* __restrict__ av, float* __restrict__ sv,
             float* __restrict__ tv, int M, int nch) {
    extern __shared__ char smem[];
    const uint32_t sb = smem_u32(smem);
    const int tid  = threadIdx.x;
    const int lane = tid & 31;
    const int wid  = tid >> 5;
    const int lq   = lane >> 2, lr = lane & 3;
    const int wm   = (wid & 3) * 32;
    const int wn   = (wid >> 2) * 64;
    const int row0 = blockIdx.y * TBM, col0 = blockIdx.x * TBN;

    float c[2][8][4] = {};

    auto loadStage = [&](int ch, int s) {
        #pragma unroll
        for (int it = 0; it < 2; it++) {
            int f = tid + it * 256;
            int r2 = f >> 5, q = f & 31;
            size_t gA = (size_t)(ch * 16 + r2) * MPAD + row0 + q * 4;
            uint32_t dA = (uint32_t)((r2 * ASTR + q * 4) * 4);
            cp16(sb + SM_AH(s) + dA, Ah + gA);
            cp16(sb + SM_AL(s) + dA, Al + gA);
            size_t gB = (size_t)(ch * 16 + r2) * HDIM + col0 + q * 4;
            uint32_t dB = (uint32_t)((r2 * BSTR + q * 4) * 4);
            cp16(sb + SM_BH(s) + dB, Bh + gB);
            cp16(sb + SM_BL(s) + dB, Bl + gB);
        }
        asm volatile("cp.async.commit_group;");
    };

    loadStage(0, 0);

    for (int ch = 0; ch < nch; ch++) {
        int cur = ch & 1, nxt = cur ^ 1;
        bool more = (ch + 1 < nch);
        if (more) {
            loadStage(ch + 1, nxt);
            asm volatile("cp.async.wait_group 1;");
        } else {
            asm volatile("cp.async.wait_group 0;");
        }
        __syncthreads();

        const uint32_t* AHp = reinterpret_cast<uint32_t*>(smem + SM_AH(cur));
        const uint32_t* ALp = reinterpret_cast<uint32_t*>(smem + SM_AL(cur));
        const uint32_t* BHp = reinterpret_cast<uint32_t*>(smem + SM_BH(cur));
        const uint32_t* BLp = reinterpret_cast<uint32_t*>(smem + SM_BL(cur));

        #pragma unroll
        for (int ks2 = 0; ks2 < 16; ks2 += 8) {
            uint32_t ah[2][4], al[2][4];
            #pragma unroll
            for (int ma = 0; ma < 2; ma++) {
                int row = wm + ma * 16 + lq;
                int kA0 = (ks2 + lr) * ASTR, kA1 = (ks2 + lr + 4) * ASTR;
                ah[ma][0] = AHp[kA0 + row];   ah[ma][1] = AHp[kA0 + row + 8];
                ah[ma][2] = AHp[kA1 + row];   ah[ma][3] = AHp[kA1 + row + 8];
                al[ma][0] = ALp[kA0 + row];   al[ma][1] = ALp[kA0 + row + 8];
                al[ma][2] = ALp[kA1 + row];   al[ma][3] = ALp[kA1 + row + 8];
            }
            #pragma unroll
            for (int ng = 0; ng < 2; ng++) {
                uint32_t bh[4][2], bl[4][2];
                #pragma unroll
                for (int nb = 0; nb < 4; nb++) {
                    int ncol = wn + (ng * 4 + nb) * 8 + lq;
                    int kB0 = (ks2 + lr) * BSTR, kB1 = (ks2 + lr + 4) * BSTR;
                    bh[nb][0] = BHp[kB0 + ncol];  bh[nb][1] = BHp[kB1 + ncol];
                    bl[nb][0] = BLp[kB0 + ncol];  bl[nb][1] = BLp[kB1 + ncol];
                }
                #pragma unroll
                for (int ma = 0; ma < 2; ma++) {
                    #pragma unroll
                    for (int nb = 0; nb < 4; nb++) {
                        float* cc = c[ma][ng * 4 + nb];
                        mma_bf16(cc, ah[ma], bh[nb]);
                        mma_bf16(cc, ah[ma], bl[nb]);
                        mma_bf16(cc, al[ma], bh[nb]);
                    }
                }
            }
        }
        __syncthreads();
    }

    // ---- epilogue ----
    float sp[2][2] = {}, tp[2][2] = {};
    #pragma unroll
    for (int na = 0; na < 8; na++) {
        int gn = col0 + wn + na * 8 + 2 * lr;
        float b0 = bias ? bias[gn]     : 0.f;
        float b1 = bias ? bias[gn + 1] : 0.f;
        float a10 = 0.f, a11 = 0.f, a20 = 0.f, a21 = 0.f;
        if (DOTS) {
            a10 = av[gn]; a11 = av[gn + 1];
            a20 = av[HDIM + gn]; a21 = av[HDIM + gn + 1];
        }
        #pragma unroll
        for (int ma = 0; ma < 2; ma++) {
            int gm = row0 + wm + ma * 16 + lq;
            float v0 = c[ma][na][0] + b0;
            float v1 = c[ma][na][1] + b1;
            float v2 = c[ma][na][2] + b0;
            float v3 = c[ma][na][3] + b1;
            if (ACT == 1) {
                v0 = fmaxf(v0, 0.f); v1 = fmaxf(v1, 0.f);
                v2 = fmaxf(v2, 0.f); v3 = fmaxf(v3, 0.f);
            }
            if (DOTS) {
                sp[ma][0] += v0 * a10 + v1 * a11;
                sp[ma][1] += v2 * a10 + v3 * a11;
                tp[ma][0] += v0 * a20 + v1 * a21;
                tp[ma][1] += v2 * a20 + v3 * a21;
            }
            if (OUT == 0) {
                if (gm < M)
                    *reinterpret_cast<float2*>(C + (size_t)gm * HDIM + gn) = make_float2(v0, v1);
                if (gm + 8 < M)
                    *reinterpret_cast<float2*>(C + (size_t)(gm + 8) * HDIM + gn) = make_float2(v2, v3);
            } else {
                size_t o = (size_t)(gn >> 1) * MPAD;
                float h0 = __bfloat162float(__float2bfloat16(v0));
                float h1 = __bfloat162float(__float2bfloat16(v1));
                __nv_bfloat162 hp = __floats2bfloat162_rn(v0, v1);
                __nv_bfloat162 lp = __floats2bfloat162_rn(v0 - h0, v1 - h1);
                Aoh[o + gm] = *reinterpret_cast<uint32_t*>(&hp);
                Aol[o + gm] = *reinterpret_cast<uint32_t*>(&lp);
                float h2 = __bfloat162float(__float2bfloat16(v2));
                float h3 = __bfloat162float(__float2bfloat16(v3));
                __nv_bfloat162 hp2 = __floats2bfloat162_rn(v2, v3);
                __nv_bfloat162 lp2 = __floats2bfloat162_rn(v2 - h2, v3 - h3);
                Aoh[o + gm + 8] = *reinterpret_cast<uint32_t*>(&hp2);
                Aol[o + gm + 8] = *reinterpret_cast<uint32_t*>(&lp2);
            }
        }
    }
    if (DOTS) {
        // reduce across the 4-lane column group (lanes lq*4 + lr)
        #pragma unroll
        for (int ma = 0; ma < 2; ma++) {
            #pragma unroll
            for (int r = 0; r < 2; r++) {
                sp[ma][r] += __shfl_down_sync(0xffffffffu, sp[ma][r], 1);
                sp[ma][r] += __shfl_down_sync(0xffffffffu, sp[ma][r], 2);
                tp[ma][r] += __shfl_down_sync(0xffffffffu, tp[ma][r], 1);
                tp[ma][r] += __shfl_down_sync(0xffffffffu, tp[ma][r], 2);
            }
        }
        if (lr == 0) {
            #pragma unroll
            for (int ma = 0; ma < 2; ma++) {
                int gm = row0 + wm + ma * 16 + lq;
                if (gm < M)     { atomicAdd(&sv[gm], sp[ma][0]);     atomicAdd(&tv[gm], tp[ma][0]); }
                if (gm + 8 < M) { atomicAdd(&sv[gm + 8], sp[ma][1]); atomicAdd(&tv[gm + 8], tp[ma][1]); }
            }
        }
    }
}

// ================= CSR build =================
__global__ void zero2(int* __restrict__ a, int* __restrict__ b, int n) {
    int i = blockIdx.x * blockDim.x + threadIdx.x;
    if (i < n) { a[i] = 0; b[i] = 0; }
}
__global__ void zero_st(float* __restrict__ s, float* __restrict__ t, int n) {
    int i = blockIdx.x * blockDim.x + threadIdx.x;
    if (i < n) { s[i] = 0.f; t[i] = 0.f; }
}
__global__ void csr_count(const int* __restrict__ src, int* __restrict__ cnt, int E) {
    int i = blockIdx.x * blockDim.x + threadIdx.x;
    if (i < E) atomicAdd(&cnt[src[i]], 1);
}
__global__ void csr_scan(const int* __restrict__ cnt, int* __restrict__ off, int n) {
    __shared__ int sh[1024];
    const int tid = threadIdx.x;
    const int seg = (n + 1023) / 1024;
    const int beg = tid * seg;
    int local[20];
    int sum = 0;
    #pragma unroll
    for (int j = 0; j < 20; j++) {
        int i = beg + j;
        int v = (j < seg && i < n) ? cnt[i] : 0;
        local[j] = sum;
        sum += v;
    }
    sh[tid] = sum;
    __syncthreads();
    #pragma unroll
    for (int o = 1; o < 1024; o <<= 1) {
        int x = (tid >= o) ? sh[tid - o] : 0;
        __syncthreads();
        sh[tid] += x;
        __syncthreads();
    }
    int base = (tid > 0) ? sh[tid - 1] : 0;
    #pragma unroll
    for (int j = 0; j < 20; j++) {
        int i = beg + j;
        if (j < seg && i < n) off[i] = base + local[j];
    }
    if (tid == 1023) off[n] = sh[1023];
}
__global__ void csr_place(const int* __restrict__ src, const int* __restrict__ dst,
                          const int* __restrict__ off, int* __restrict__ cur,
                          int* __restrict__ dsts, int* __restrict__ srcs, int E) {
    int i = blockIdx.x * blockDim.x + threadIdx.x;
    if (i >= E) return;
    int u = src[i];
    int p = off[u] + atomicAdd(&cur[u], 1);
    dsts[p] = dst[i];
    srcs[p] = u;
}

// ---------------- per-edge weights ----------------
__global__ void edge_scores(const int* __restrict__ srcs, const int* __restrict__ dsts,
                            const float* __restrict__ s, const float* __restrict__ t,
                            float* __restrict__ e, int E) {
    int i = blockIdx.x * blockDim.x + threadIdx.x;
    if (i >= E) return;
    float sc = s[srcs[i]] + t[dsts[i]];
    float lr = sc > 0.f ? sc : 0.2f * sc;
    e[i] = expf(-lr);
}

// ---------------- GAT aggregation (unroll 2) ----------------
__global__ void gat_aggregate(const int* __restrict__ off, const int* __restrict__ dsts,
                              const float* __restrict__ e, const float* __restrict__ hw,
                              float* __restrict__ hout) {
    int u = blockIdx.x;
    int c = threadIdx.x;
    int beg = off[u], end = off[u + 1];
    float4 acc = make_float4(0.f, 0.f, 0.f, 0.f);
    float dsum = 0.f;
    int p = beg;
    for (; p + 1 < end; p += 2) {
        int d0 = dsts[p], d1 = dsts[p + 1];
        float e0 = e[p], e1 = e[p + 1];
        float4 v0 = *(reinterpret_cast<const float4*>(hw + (size_t)d0 * HDIM) + c);
        float4 v1 = *(reinterpret_cast<const float4*>(hw + (size_t)d1 * HDIM) + c);
        dsum += e0 + e1;
        acc.x += e0 * v0.x + e1 * v1.x;
        acc.y += e0 * v0.y + e1 * v1.y;
        acc.z += e0 * v0.z + e1 * v1.z;
        acc.w += e0 * v0.w + e1 * v1.w;
    }
    if (p < end) {
        int d = dsts[p];
        float ev = e[p];
        float4 v = *(reinterpret_cast<const float4*>(hw + (size_t)d * HDIM) + c);
        dsum += ev;
        acc.x += ev * v.x; acc.y += ev * v.y;
        acc.z += ev * v.z; acc.w += ev * v.w;
    }
    float inv = 1.f / (dsum + 1e-10f);
    float4 o;
    o.x = fmaxf(acc.x * inv, 0.f);
    o.y = fmaxf(acc.y * inv, 0.f);
    o.z = fmaxf(acc.z * inv, 0.f);
    o.w = fmaxf(acc.w * inv, 0.f);
    *(reinterpret_cast<float4*>(hout + (size_t)u * HDIM) + c) = o;
}

// ---------------- final GEMV + sigmoid ----------------
__global__ void gemv_sigmoid(const float* __restrict__ h2, const float* __restrict__ v3,
                             const float* __restrict__ vb3, float* __restrict__ out, int n) {
    int warp = (blockIdx.x * blockDim.x + threadIdx.x) >> 5;
    int lane = threadIdx.x & 31;
    if (warp >= n) return;
    const float* row = h2 + (size_t)warp * HDIM;
    float acc = 0.f;
    #pragma unroll 4
    for (int c = lane; c < HDIM; c += 32) acc += row[c] * v3[c];
    #pragma unroll
    for (int o = 16; o; o >>= 1) acc += __shfl_down_sync(0xffffffffu, acc, o);
    if (lane == 0) {
        float x = acc + vb3[0];
        out[warp] = 1.f / (1.f + expf(-x));
    }
}

// ---------------- host launcher ----------------
extern "C" void kernel_launch(void* const* d_in, const int* in_sizes, int n_in,
                              void* d_out, int out_size) {
    const float* feat = (const float*)d_in[0];
    const float* goal = (const float*)d_in[1];
    const float* info = (const float*)d_in[2];
    const int*   esrc = (const int*)d_in[3];
    const int*   edst = (const int*)d_in[4];
    const float* W1   = (const float*)d_in[5];
    const float* b1   = (const float*)d_in[6];
    const float* W2   = (const float*)d_in[7];
    const float* b2   = (const float*)d_in[8];
    const float* W3   = (const float*)d_in[9];
    const float* b3   = (const float*)d_in[10];
    const float* V1   = (const float*)d_in[11];
    const float* vb1  = (const float*)d_in[12];
    const float* V2   = (const float*)d_in[13];
    const float* vb2  = (const float*)d_in[14];
    const float* V3   = (const float*)d_in[15];
    const float* vb3  = (const float*)d_in[16];
    const float* gatW = (const float*)d_in[17];
    const float* gatA = (const float*)d_in[18];
    float* out = (float*)d_out;

    int E = in_sizes[3];
    if (E > E_CAP) E = E_CAP;
    const int n = N_NODES;

    float *h, *hw, *acc, *s, *t, *e;
    int *cnt, *off, *cur, *dsts, *srcs;
    uint32_t *Bh, *Bl, *A1h, *A1l, *A2h, *A2l;
    cudaGetSymbolAddress((void**)&h,   g_h);
    cudaGetSymbolAddress((void**)&hw,  g_hw);
    cudaGetSymbolAddress((void**)&acc, g_acc);
    cudaGetSymbolAddress((void**)&s,   g_s);
    cudaGetSymbolAddress((void**)&t,   g_t);
    cudaGetSymbolAddress((void**)&e,   g_e);
    cudaGetSymbolAddress((void**)&cnt, g_cnt);
    cudaGetSymbolAddress((void**)&off, g_off);
    cudaGetSymbolAddress((void**)&cur, g_cur);
    cudaGetSymbolAddress((void**)&dsts,g_dsts);
    cudaGetSymbolAddress((void**)&srcs,g_srcs);
    cudaGetSymbolAddress((void**)&Bh,  g_Bh);
    cudaGetSymbolAddress((void**)&Bl,  g_Bl);
    cudaGetSymbolAddress((void**)&A1h, g_A1h);
    cudaGetSymbolAddress((void**)&A1l, g_A1l);
    cudaGetSymbolAddress((void**)&A2h, g_A2h);
    cudaGetSymbolAddress((void**)&A2l, g_A2l);

    static bool attr_done = false;
    if (!attr_done) {
        cudaFuncSetAttribute(gemm_pp<1,1,0>, cudaFuncAttributeMaxDynamicSharedMemorySize, SM_BYTES);
        cudaFuncSetAttribute(gemm_pp<0,1,0>, cudaFuncAttributeMaxDynamicSharedMemorySize, SM_BYTES);
        cudaFuncSetAttribute(gemm_pp<0,0,1>, cudaFuncAttributeMaxDynamicSharedMemorySize, SM_BYTES);
        cudaFuncSetAttribute(gemm_pp<1,0,0>, cudaFuncAttributeMaxDynamicSharedMemorySize, SM_BYTES);
        attr_done = true;
    }

    const dim3 gg(HDIM / TBN, (n + TBM - 1) / TBM);   // 4 x 157
    const dim3 cg_f(157, K2_FEAT / 16);
    const dim3 cg_h(157, K2_H / 16);
    const int node_warp_blocks = (n * 32 + 255) / 256;
    const int edge_blocks = (E + 255) / 256;

    #define BW(o) (Bh + (size_t)(o) * HDIM), (Bl + (size_t)(o) * HDIM)

    // ---- input chain ----
    split_all<<<(K2_TOTAL * HDIM + 255) / 256, 256>>>(W1, V1, W2, W3, V2, gatW, Bh, Bl);
    conv_a<1><<<cg_f, 256>>>(feat, goal, info, A1h, A1l, n, FEAT);
    gemm_pp<1,1,0><<<gg, 256, SM_BYTES>>>(A1h, A1l, BW(OFF_W1), b1, nullptr, A2h, A2l,
                                          nullptr, nullptr, nullptr, n, K2_FEAT / 16);
    gemm_pp<1,1,0><<<gg, 256, SM_BYTES>>>(A2h, A2l, BW(OFF_W2), b2, nullptr, A1h, A1l,
                                          nullptr, nullptr, nullptr, n, K2_H / 16);
    gemm_pp<0,1,0><<<gg, 256, SM_BYTES>>>(A1h, A1l, BW(OFF_W3), b3, nullptr, A2h, A2l,
                                          nullptr, nullptr, nullptr, n, K2_H / 16);

    // ---- CSR build ----
    zero2<<<(n + 255) / 256, 256>>>(cnt, cur, n);
    csr_count<<<edge_blocks, 256>>>(esrc, cnt, E);
    csr_scan<<<1, 1024>>>(cnt, off, n);
    csr_place<<<edge_blocks, 256>>>(esrc, edst, off, cur, dsts, srcs, E);

    // ---- GAT layers ----
    for (int l = 0; l < NUM_GAT; l++) {
        const float* al = gatA + (size_t)l * 2 * HDIM;
        zero_st<<<(n + 255) / 256, 256>>>(s, t, n);
        gemm_pp<0,0,1><<<gg, 256, SM_BYTES>>>(A2h, A2l, BW(OFF_GAT0 + l * K2_H),
                                              nullptr, hw, nullptr, nullptr,
                                              al, s, t, n, K2_H / 16);
        edge_scores<<<edge_blocks, 256>>>(srcs, dsts, s, t, e, E);
        gat_aggregate<<<n, 128>>>(off, dsts, e, hw, h);
        if (l < NUM_GAT - 1)
            conv_a<0><<<cg_h, 256>>>(h, nullptr, nullptr, A2h, A2l, n, HDIM);
    }

    // ---- output MLP ----
    conv_a<1><<<cg_f, 256>>>(h, goal, info, A1h, A1l, n, FEAT);
    gemm_pp<1,1,0><<<gg, 256, SM_BYTES>>>(A1h, A1l, BW(OFF_V1), vb1, nullptr, A2h, A2l,
                                          nullptr, nullptr, nullptr, n, K2_FEAT / 16);
    gemm_pp<1,0,0><<<gg, 256, SM_BYTES>>>(A2h, A2l, BW(OFF_V2), vb2, acc, nullptr, nullptr,
                                          nullptr, nullptr, nullptr, n, K2_H / 16);
    gemv_sigmoid<<<node_warp_blocks, 256>>>(acc, V3, vb3, out, n);
}

// round 13
// speedup vs baseline: 4.8884x; 1.0386x over previous
#include <cuda_runtime.h>
#include <cuda_bf16.h>
#include <math.h>
#include <stdint.h>

#define N_NODES 20000
#define MPAD    20096     // 157*128
#define HDIM    512
#define FEAT    1029
#define NUM_GAT 5
#define E_CAP   360000

#define K2_FEAT 528    // 33 chunks of 16 k2-rows (K=1056)
#define K2_H    256    // 16 chunks
#define OFF_W1   0
#define OFF_V1   (K2_FEAT)
#define OFF_W2   (2*K2_FEAT)
#define OFF_W3   (OFF_W2 + K2_H)
#define OFF_V2   (OFF_W3 + K2_H)
#define OFF_GAT0 (OFF_V2 + K2_H)
#define K2_TOTAL (OFF_GAT0 + 5*K2_H)

// ---------------- scratch (device globals; no allocation) ----------------
__device__ float    g_h   [(size_t)N_NODES * HDIM];
__device__ float    g_hw  [(size_t)N_NODES * HDIM];
__device__ float    g_acc [(size_t)N_NODES * HDIM];
__device__ float    g_s   [N_NODES];
__device__ float    g_t   [N_NODES];
__device__ int      g_cnt [N_NODES];
__device__ int      g_off [N_NODES + 1];
__device__ int      g_cur [N_NODES];
__device__ int      g_dsts[E_CAP];
__device__ int      g_srcs[E_CAP];
__device__ uint32_t g_Bh  [(size_t)K2_TOTAL * HDIM];   // permuted: [q8][n][j]
__device__ uint32_t g_Bl  [(size_t)K2_TOTAL * HDIM];
__device__ uint32_t g_A1h [(size_t)K2_FEAT * MPAD];    // permuted m within 16-groups
__device__ uint32_t g_A1l [(size_t)K2_FEAT * MPAD];
__device__ uint32_t g_A2h [(size_t)K2_H * MPAD];
__device__ uint32_t g_A2l [(size_t)K2_H * MPAD];

// ---------------- split ALL weights (B-permuted layout) ----------------
__global__ void split_all(const float* __restrict__ W1, const float* __restrict__ V1,
                          const float* __restrict__ W2, const float* __restrict__ W3,
                          const float* __restrict__ V2, const float* __restrict__ gatW,
                          uint32_t* __restrict__ Bh, uint32_t* __restrict__ Bl) {
    int idx = blockIdx.x * blockDim.x + threadIdx.x;
    if (idx >= K2_TOTAL * HDIM) return;
    int k2g = idx >> 9, n = idx & 511;
    const float* src; int KB, k2l;
    if (k2g < K2_FEAT)            { src = W1; k2l = k2g;            KB = FEAT; }
    else if (k2g < 2 * K2_FEAT)   { src = V1; k2l = k2g - K2_FEAT;  KB = FEAT; }
    else {
        int r = k2g - 2 * K2_FEAT;
        int w = r >> 8; k2l = r & 255; KB = HDIM;
        src = (w == 0) ? W2 : (w == 1) ? W3 : (w == 2) ? V2
                                            : gatW + (size_t)(w - 3) * HDIM * HDIM;
    }
    int k = 2 * k2l;
    float x0 = (k     < KB) ? src[(size_t)k * HDIM + n]       : 0.f;
    float x1 = (k + 1 < KB) ? src[(size_t)(k + 1) * HDIM + n] : 0.f;
    float h0 = __bfloat162float(__float2bfloat16(x0));
    float h1 = __bfloat162float(__float2bfloat16(x1));
    __nv_bfloat162 hp = __floats2bfloat162_rn(x0, x1);
    __nv_bfloat162 lp = __floats2bfloat162_rn(x0 - h0, x1 - h1);
    // permuted output: wbase + q8*4096 + n*8 + j ; j = 2*(r&3) | (r>>2)
    int wbase = (k2g - k2l) << 9;
    int q8 = k2l >> 3, r = k2l & 7;
    int j = ((r & 3) << 1) | (r >> 2);
    size_t o = (size_t)wbase + (size_t)q8 * 4096 + n * 8 + j;
    Bh[o] = *reinterpret_cast<uint32_t*>(&hp);
    Bl[o] = *reinterpret_cast<uint32_t*>(&lp);
}

// ---------------- activation convert fp32 -> split bf16x2 [k2][pm(MPAD)] ----------
template <int CAT>
__global__ __launch_bounds__(256)
void conv_a(const float* __restrict__ A, const float* __restrict__ goal,
            const float* __restrict__ info, uint32_t* __restrict__ Ah,
            uint32_t* __restrict__ Al, int M, int Kdim) {
    __shared__ float tile[128][33];
    const int tid = threadIdx.x;
    const int m0 = blockIdx.x * 128;
    const int k0 = blockIdx.y * 32;
    const int ml = tid & 127, half = tid >> 7;
    const int gm = m0 + ml;
    #pragma unroll
    for (int i = 0; i < 4; i++) {
        int kk = k0 + half * 16 + i * 4;
        float4 v = make_float4(0.f, 0.f, 0.f, 0.f);
        if (gm < M) {
            if (CAT == 0) {
                if (kk + 3 < Kdim)
                    v = *reinterpret_cast<const float4*>(A + (size_t)gm * Kdim + kk);
            } else {
                if (kk < 512)
                    v = *reinterpret_cast<const float4*>(A + (size_t)gm * 512 + kk);
                else if (kk < 1024)
                    v = *reinterpret_cast<const float4*>(goal + (size_t)gm * 512 + kk - 512);
                else if (kk == 1024) {
                    const float* ir = info + (size_t)gm * 5;
                    v = make_float4(ir[0], ir[1], ir[2], ir[3]);
                } else if (kk == 1028) {
                    v.x = info[(size_t)gm * 5 + 4];
                }
            }
        }
        int cb = half * 16 + i * 4;
        tile[ml][cb + 0] = v.x; tile[ml][cb + 1] = v.y;
        tile[ml][cb + 2] = v.z; tile[ml][cb + 3] = v.w;
    }
    __syncthreads();
    const int k2l = tid >> 4, mq = tid & 15;
    const size_t k2g = blockIdx.y * 16 + k2l;
    #pragma unroll
    for (int j = 0; j < 8; j++) {
        int m = mq + j * 16;
        float x0 = tile[m][2 * k2l], x1 = tile[m][2 * k2l + 1];
        float h0 = __bfloat162float(__float2bfloat16(x0));
        float h1 = __bfloat162float(__float2bfloat16(x1));
        __nv_bfloat162 hp = __floats2bfloat162_rn(x0, x1);
        __nv_bfloat162 lp = __floats2bfloat162_rn(x0 - h0, x1 - h1);
        int pm = j * 16 + ((mq & 7) << 1) + (mq >> 3);      // permuted m
        size_t o = k2g * MPAD + m0 + pm;
        Ah[o] = *reinterpret_cast<uint32_t*>(&hp);
        Al[o] = *reinterpret_cast<uint32_t*>(&lp);
    }
}

// ================= pipelined split-bf16 GEMM, block 128x128, warp 32x64 =========
#define TBM 128
#define TBN 128
#define ASTR 136
// smem bytes: A 2x8704 hi + 2x8704 lo; B 2x8192 hi + 2x8192 lo
#define SM_AH(s) ((s) * 8704)
#define SM_AL(s) (17408 + (s) * 8704)
#define SM_BH(s) (34816 + (s) * 8192)
#define SM_BL(s) (51200 + (s) * 8192)
#define SM_BYTES 67584

__device__ __forceinline__ uint32_t smem_u32(const void* p) {
    uint32_t a;
    asm("{ .reg .u64 t; cvta.to.shared.u64 t, %1; cvt.u32.u64 %0, t; }" : "=r"(a) : "l"(p));
    return a;
}
__device__ __forceinline__ void mma_bf16(float* c, const uint32_t* a, const uint32_t* b) {
    asm("mma.sync.aligned.m16n8k16.row.col.f32.bf16.bf16.f32 "
        "{%0,%1,%2,%3}, {%4,%5,%6,%7}, {%8,%9}, {%0,%1,%2,%3};"
        : "+f"(c[0]), "+f"(c[1]), "+f"(c[2]), "+f"(c[3])
        : "r"(a[0]), "r"(a[1]), "r"(a[2]), "r"(a[3]), "r"(b[0]), "r"(b[1]));
}
__device__ __forceinline__ void cp16(uint32_t dst, const void* src) {
    asm volatile("cp.async.cg.shared.global [%0], [%1], 16;" :: "r"(dst), "l"(src));
}

// OUT: 0 = fp32 C ; 1 = split bf16x2 (permuted) to Aoh/Aol.  DOTS: s/t partials.
template <int ACT, int OUT, int DOTS>
__global__ __launch_bounds__(256, 2)
void gemm_pp(const uint32_t* __restrict__ Ah, const uint32_t* __restrict__ Al,
             const uint32_t* __restrict__ Bh, const uint32_t* __restrict__ Bl,
             const float* __restrict__ bias, float* __restrict__ C,
             uint32_t* __restrict__ Aoh, uint32_t* __restrict__ Aol,
             const float* __restrict__ av, float* __restrict__ sv,
             float* __restrict__ tv, int M, int nch) {
    extern __shared__ char smem[];
    const uint32_t sb = smem_u32(smem);
    const int tid  = threadIdx.x;
    const int lane = tid & 31;
    const int wid  = tid >> 5;
    const int lq   = lane >> 2, lr = lane & 3;
    const int wm   = (wid & 3) * 32;
    const int wn   = (wid >> 2) * 64;
    const int row0 = blockIdx.y * TBM, col0 = blockIdx.x * TBN;

    float c[2][8][4] = {};

    auto loadStage = [&](int ch, int s) {
        #pragma unroll
        for (int it = 0; it < 2; it++) {
            int f = tid + it * 256;
            // A: 16 k2-rows x 128 words (512 chunks per buffer / 2 iters)
            {
                int r2 = f >> 5, q = f & 31;
                size_t gA = (size_t)(ch * 16 + r2) * MPAD + row0 + q * 4;
                uint32_t dA = (uint32_t)((r2 * ASTR + q * 4) * 4);
                cp16(sb + SM_AH(s) + dA, Ah + gA);
                cp16(sb + SM_AL(s) + dA, Al + gA);
            }
            // B: 2 q8-blocks x 128 n x 8 words = 512 chunks per buffer
            {
                int q8l = f >> 8, rest = f & 255;
                int nl = rest >> 1, j4 = rest & 1;
                size_t gB = (size_t)(ch * 2 + q8l) * 4096 + (size_t)(col0 + nl) * 8 + j4 * 4;
                uint32_t dB = (uint32_t)((q8l * 1024 + nl * 8 + j4 * 4) * 4);
                cp16(sb + SM_BH(s) + dB, Bh + gB);
                cp16(sb + SM_BL(s) + dB, Bl + gB);
            }
        }
        asm volatile("cp.async.commit_group;");
    };

    loadStage(0, 0);

    for (int ch = 0; ch < nch; ch++) {
        int cur = ch & 1, nxt = cur ^ 1;
        bool more = (ch + 1 < nch);
        if (more) {
            loadStage(ch + 1, nxt);
            asm volatile("cp.async.wait_group 1;");
        } else {
            asm volatile("cp.async.wait_group 0;");
        }
        __syncthreads();

        const uint32_t* AHp = reinterpret_cast<uint32_t*>(smem + SM_AH(cur));
        const uint32_t* ALp = reinterpret_cast<uint32_t*>(smem + SM_AL(cur));
        const uint32_t* BHp = reinterpret_cast<uint32_t*>(smem + SM_BH(cur));
        const uint32_t* BLp = reinterpret_cast<uint32_t*>(smem + SM_BL(cur));

        #pragma unroll
        for (int ks2 = 0; ks2 < 16; ks2 += 8) {
            const int q8l = ks2 >> 3;
            uint32_t ah[2][4], al[2][4];
            #pragma unroll
            for (int ma = 0; ma < 2; ma++) {
                int base = wm + ma * 16 + lq * 2;
                int kA0 = (ks2 + lr) * ASTR, kA1 = (ks2 + lr + 4) * ASTR;
                uint2 h0 = *reinterpret_cast<const uint2*>(&AHp[kA0 + base]);
                uint2 h1 = *reinterpret_cast<const uint2*>(&AHp[kA1 + base]);
                uint2 l0 = *reinterpret_cast<const uint2*>(&ALp[kA0 + base]);
                uint2 l1 = *reinterpret_cast<const uint2*>(&ALp[kA1 + base]);
                ah[ma][0] = h0.x; ah[ma][1] = h0.y; ah[ma][2] = h1.x; ah[ma][3] = h1.y;
                al[ma][0] = l0.x; al[ma][1] = l0.y; al[ma][2] = l1.x; al[ma][3] = l1.y;
            }
            #pragma unroll
            for (int ng = 0; ng < 2; ng++) {
                uint32_t bh[4][2], bl[4][2];
                #pragma unroll
                for (int nb = 0; nb < 4; nb++) {
                    int ncol = wn + (ng * 4 + nb) * 8 + lq;
                    int boff = q8l * 1024 + ncol * 8 + lr * 2;
                    uint2 bhv = *reinterpret_cast<const uint2*>(&BHp[boff]);
                    uint2 blv = *reinterpret_cast<const uint2*>(&BLp[boff]);
                    bh[nb][0] = bhv.x; bh[nb][1] = bhv.y;
                    bl[nb][0] = blv.x; bl[nb][1] = blv.y;
                }
                #pragma unroll
                for (int ma = 0; ma < 2; ma++) {
                    #pragma unroll
                    for (int nb = 0; nb < 4; nb++) {
                        float* cc = c[ma][ng * 4 + nb];
                        mma_bf16(cc, ah[ma], bh[nb]);
                        mma_bf16(cc, ah[ma], bl[nb]);
                        mma_bf16(cc, al[ma], bh[nb]);
                    }
                }
            }
        }
        __syncthreads();
    }

    // ---- epilogue ----
    float sp[2][2] = {}, tp[2][2] = {};
    #pragma unroll
    for (int na = 0; na < 8; na++) {
        int gn = col0 + wn + na * 8 + 2 * lr;
        float b0 = bias ? bias[gn]     : 0.f;
        float b1 = bias ? bias[gn + 1] : 0.f;
        float a10 = 0.f, a11 = 0.f, a20 = 0.f, a21 = 0.f;
        if (DOTS) {
            a10 = av[gn]; a11 = av[gn + 1];
            a20 = av[HDIM + gn]; a21 = av[HDIM + gn + 1];
        }
        #pragma unroll
        for (int ma = 0; ma < 2; ma++) {
            int gm = row0 + wm + ma * 16 + lq;
            float v0 = c[ma][na][0] + b0;
            float v1 = c[ma][na][1] + b1;
            float v2 = c[ma][na][2] + b0;
            float v3 = c[ma][na][3] + b1;
            if (ACT == 1) {
                v0 = fmaxf(v0, 0.f); v1 = fmaxf(v1, 0.f);
                v2 = fmaxf(v2, 0.f); v3 = fmaxf(v3, 0.f);
            }
            if (DOTS) {
                sp[ma][0] += v0 * a10 + v1 * a11;
                sp[ma][1] += v2 * a10 + v3 * a11;
                tp[ma][0] += v0 * a20 + v1 * a21;
                tp[ma][1] += v2 * a20 + v3 * a21;
            }
            if (OUT == 0) {
                if (gm < M)
                    *reinterpret_cast<float2*>(C + (size_t)gm * HDIM + gn) = make_float2(v0, v1);
                if (gm + 8 < M)
                    *reinterpret_cast<float2*>(C + (size_t)(gm + 8) * HDIM + gn) = make_float2(v2, v3);
            } else {
                // permuted write: rows (gm, gm+8) -> adjacent words; pad rows in-bounds
                size_t o = (size_t)(gn >> 1) * MPAD + (row0 + wm + ma * 16) + 2 * lq;
                float h0 = __bfloat162float(__float2bfloat16(v0));
                float h1 = __bfloat162float(__float2bfloat16(v1));
                __nv_bfloat162 hpA = __floats2bfloat162_rn(v0, v1);
                __nv_bfloat162 lpA = __floats2bfloat162_rn(v0 - h0, v1 - h1);
                float h2 = __bfloat162float(__float2bfloat16(v2));
                float h3 = __bfloat162float(__float2bfloat16(v3));
                __nv_bfloat162 hpB = __floats2bfloat162_rn(v2, v3);
                __nv_bfloat162 lpB = __floats2bfloat162_rn(v2 - h2, v3 - h3);
                uint2 uh, ul;
                uh.x = *reinterpret_cast<uint32_t*>(&hpA);
                uh.y = *reinterpret_cast<uint32_t*>(&hpB);
                ul.x = *reinterpret_cast<uint32_t*>(&lpA);
                ul.y = *reinterpret_cast<uint32_t*>(&lpB);
                *reinterpret_cast<uint2*>(Aoh + o) = uh;
                *reinterpret_cast<uint2*>(Aol + o) = ul;
            }
        }
    }
    if (DOTS) {
        #pragma unroll
        for (int ma = 0; ma < 2; ma++) {
            #pragma unroll
            for (int r = 0; r < 2; r++) {
                sp[ma][r] += __shfl_down_sync(0xffffffffu, sp[ma][r], 1);
                sp[ma][r] += __shfl_down_sync(0xffffffffu, sp[ma][r], 2);
                tp[ma][r] += __shfl_down_sync(0xffffffffu, tp[ma][r], 1);
                tp[ma][r] += __shfl_down_sync(0xffffffffu, tp[ma][r], 2);
            }
        }
        if (lr == 0) {
            #pragma unroll
            for (int ma = 0; ma < 2; ma++) {
                int gm = row0 + wm + ma * 16 + lq;
                if (gm < M)     { atomicAdd(&sv[gm], sp[ma][0]);     atomicAdd(&tv[gm], tp[ma][0]); }
                if (gm + 8 < M) { atomicAdd(&sv[gm + 8], sp[ma][1]); atomicAdd(&tv[gm + 8], tp[ma][1]); }
            }
        }
    }
}

// ================= CSR build =================
__global__ void zero2(int* __restrict__ a, int* __restrict__ b, int n) {
    int i = blockIdx.x * blockDim.x + threadIdx.x;
    if (i < n) { a[i] = 0; b[i] = 0; }
}
__global__ void zero_st(float* __restrict__ s, float* __restrict__ t, int n) {
    int i = blockIdx.x * blockDim.x + threadIdx.x;
    if (i < n) { s[i] = 0.f; t[i] = 0.f; }
}
__global__ void csr_count(const int* __restrict__ src, int* __restrict__ cnt, int E) {
    int i = blockIdx.x * blockDim.x + threadIdx.x;
    if (i < E) atomicAdd(&cnt[src[i]], 1);
}
__global__ void csr_scan(const int* __restrict__ cnt, int* __restrict__ off, int n) {
    __shared__ int sh[1024];
    const int tid = threadIdx.x;
    const int seg = (n + 1023) / 1024;
    const int beg = tid * seg;
    int local[20];
    int sum = 0;
    #pragma unroll
    for (int j = 0; j < 20; j++) {
        int i = beg + j;
        int v = (j < seg && i < n) ? cnt[i] : 0;
        local[j] = sum;
        sum += v;
    }
    sh[tid] = sum;
    __syncthreads();
    #pragma unroll
    for (int o = 1; o < 1024; o <<= 1) {
        int x = (tid >= o) ? sh[tid - o] : 0;
        __syncthreads();
        sh[tid] += x;
        __syncthreads();
    }
    int base = (tid > 0) ? sh[tid - 1] : 0;
    #pragma unroll
    for (int j = 0; j < 20; j++) {
        int i = beg + j;
        if (j < seg && i < n) off[i] = base + local[j];
    }
    if (tid == 1023) off[n] = sh[1023];
}
__global__ void csr_place(const int* __restrict__ src, const int* __restrict__ dst,
                          const int* __restrict__ off, int* __restrict__ cur,
                          int* __restrict__ dsts, int* __restrict__ srcs, int E) {
    int i = blockIdx.x * blockDim.x + threadIdx.x;
    if (i >= E) return;
    int u = src[i];
    int p = off[u] + atomicAdd(&cur[u], 1);
    dsts[p] = dst[i];
    srcs[p] = u;
}

// ---------------- GAT aggregation (fused edge scores, windowed smem) ----------------
__global__ void gat_aggregate(const int* __restrict__ off, const int* __restrict__ dsts,
                              const float* __restrict__ s, const float* __restrict__ t,
                              const float* __restrict__ hw, float* __restrict__ hout) {
    __shared__ float sh_e[512];
    int u = blockIdx.x;
    int c = threadIdx.x;
    int beg = off[u], end = off[u + 1];
    float su = s[u];
    float4 acc = make_float4(0.f, 0.f, 0.f, 0.f);
    float dsum = 0.f;
    for (int w = beg; w < end; w += 512) {
        int we = w + 512 < end ? w + 512 : end;
        for (int j = w + c; j < we; j += 128) {
            float sc = su + t[dsts[j]];
            float lr = sc > 0.f ? sc : 0.2f * sc;
            sh_e[j - w] = expf(-lr);
        }
        __syncthreads();
        int p = w;
        for (; p + 1 < we; p += 2) {
            int d0 = dsts[p], d1 = dsts[p + 1];
            float e0 = sh_e[p - w], e1 = sh_e[p + 1 - w];
            float4 v0 = *(reinterpret_cast<const float4*>(hw + (size_t)d0 * HDIM) + c);
            float4 v1 = *(reinterpret_cast<const float4*>(hw + (size_t)d1 * HDIM) + c);
            dsum += e0 + e1;
            acc.x += e0 * v0.x + e1 * v1.x;
            acc.y += e0 * v0.y + e1 * v1.y;
            acc.z += e0 * v0.z + e1 * v1.z;
            acc.w += e0 * v0.w + e1 * v1.w;
        }
        if (p < we) {
            int d = dsts[p];
            float ev = sh_e[p - w];
            float4 v = *(reinterpret_cast<const float4*>(hw + (size_t)d * HDIM) + c);
            dsum += ev;
            acc.x += ev * v.x; acc.y += ev * v.y;
            acc.z += ev * v.z; acc.w += ev * v.w;
        }
        __syncthreads();
    }
    float inv = 1.f / (dsum + 1e-10f);
    float4 o;
    o.x = fmaxf(acc.x * inv, 0.f);
    o.y = fmaxf(acc.y * inv, 0.f);
    o.z = fmaxf(acc.z * inv, 0.f);
    o.w = fmaxf(acc.w * inv, 0.f);
    *(reinterpret_cast<float4*>(hout + (size_t)u * HDIM) + c) = o;
}

// ---------------- final GEMV + sigmoid ----------------
__global__ void gemv_sigmoid(const float* __restrict__ h2, const float* __restrict__ v3,
                             const float* __restrict__ vb3, float* __restrict__ out, int n) {
    int warp = (blockIdx.x * blockDim.x + threadIdx.x) >> 5;
    int lane = threadIdx.x & 31;
    if (warp >= n) return;
    const float* row = h2 + (size_t)warp * HDIM;
    float acc = 0.f;
    #pragma unroll 4
    for (int c = lane; c < HDIM; c += 32) acc += row[c] * v3[c];
    #pragma unroll
    for (int o = 16; o; o >>= 1) acc += __shfl_down_sync(0xffffffffu, acc, o);
    if (lane == 0) {
        float x = acc + vb3[0];
        out[warp] = 1.f / (1.f + expf(-x));
    }
}

// ---------------- host launcher ----------------
extern "C" void kernel_launch(void* const* d_in, const int* in_sizes, int n_in,
                              void* d_out, int out_size) {
    const float* feat = (const float*)d_in[0];
    const float* goal = (const float*)d_in[1];
    const float* info = (const float*)d_in[2];
    const int*   esrc = (const int*)d_in[3];
    const int*   edst = (const int*)d_in[4];
    const float* W1   = (const float*)d_in[5];
    const float* b1   = (const float*)d_in[6];
    const float* W2   = (const float*)d_in[7];
    const float* b2   = (const float*)d_in[8];
    const float* W3   = (const float*)d_in[9];
    const float* b3   = (const float*)d_in[10];
    const float* V1   = (const float*)d_in[11];
    const float* vb1  = (const float*)d_in[12];
    const float* V2   = (const float*)d_in[13];
    const float* vb2  = (const float*)d_in[14];
    const float* V3   = (const float*)d_in[15];
    const float* vb3  = (const float*)d_in[16];
    const float* gatW = (const float*)d_in[17];
    const float* gatA = (const float*)d_in[18];
    float* out = (float*)d_out;

    int E = in_sizes[3];
    if (E > E_CAP) E = E_CAP;
    const int n = N_NODES;

    float *h, *hw, *acc, *s, *t;
    int *cnt, *off, *cur, *dsts, *srcs;
    uint32_t *Bh, *Bl, *A1h, *A1l, *A2h, *A2l;
    cudaGetSymbolAddress((void**)&h,   g_h);
    cudaGetSymbolAddress((void**)&hw,  g_hw);
    cudaGetSymbolAddress((void**)&acc, g_acc);
    cudaGetSymbolAddress((void**)&s,   g_s);
    cudaGetSymbolAddress((void**)&t,   g_t);
    cudaGetSymbolAddress((void**)&cnt, g_cnt);
    cudaGetSymbolAddress((void**)&off, g_off);
    cudaGetSymbolAddress((void**)&cur, g_cur);
    cudaGetSymbolAddress((void**)&dsts,g_dsts);
    cudaGetSymbolAddress((void**)&srcs,g_srcs);
    cudaGetSymbolAddress((void**)&Bh,  g_Bh);
    cudaGetSymbolAddress((void**)&Bl,  g_Bl);
    cudaGetSymbolAddress((void**)&A1h, g_A1h);
    cudaGetSymbolAddress((void**)&A1l, g_A1l);
    cudaGetSymbolAddress((void**)&A2h, g_A2h);
    cudaGetSymbolAddress((void**)&A2l, g_A2l);

    static bool attr_done = false;
    if (!attr_done) {
        cudaFuncSetAttribute(gemm_pp<1,1,0>, cudaFuncAttributeMaxDynamicSharedMemorySize, SM_BYTES);
        cudaFuncSetAttribute(gemm_pp<0,1,0>, cudaFuncAttributeMaxDynamicSharedMemorySize, SM_BYTES);
        cudaFuncSetAttribute(gemm_pp<0,0,1>, cudaFuncAttributeMaxDynamicSharedMemorySize, SM_BYTES);
        cudaFuncSetAttribute(gemm_pp<1,0,0>, cudaFuncAttributeMaxDynamicSharedMemorySize, SM_BYTES);
        attr_done = true;
    }

    const dim3 gg(HDIM / TBN, (n + TBM - 1) / TBM);   // 4 x 157
    const dim3 cg_f(157, K2_FEAT / 16);
    const dim3 cg_h(157, K2_H / 16);
    const int node_warp_blocks = (n * 32 + 255) / 256;
    const int edge_blocks = (E + 255) / 256;

    #define BW(o) (Bh + (size_t)(o) * HDIM), (Bl + (size_t)(o) * HDIM)

    // ---- input chain ----
    split_all<<<(K2_TOTAL * HDIM + 255) / 256, 256>>>(W1, V1, W2, W3, V2, gatW, Bh, Bl);
    conv_a<1><<<cg_f, 256>>>(feat, goal, info, A1h, A1l, n, FEAT);
    gemm_pp<1,1,0><<<gg, 256, SM_BYTES>>>(A1h, A1l, BW(OFF_W1), b1, nullptr, A2h, A2l,
                                          nullptr, nullptr, nullptr, n, K2_FEAT / 16);
    gemm_pp<1,1,0><<<gg, 256, SM_BYTES>>>(A2h, A2l, BW(OFF_W2), b2, nullptr, A1h, A1l,
                                          nullptr, nullptr, nullptr, n, K2_H / 16);
    gemm_pp<0,1,0><<<gg, 256, SM_BYTES>>>(A1h, A1l, BW(OFF_W3), b3, nullptr, A2h, A2l,
                                          nullptr, nullptr, nullptr, n, K2_H / 16);

    // ---- CSR build ----
    zero2<<<(n + 255) / 256, 256>>>(cnt, cur, n);
    csr_count<<<edge_blocks, 256>>>(esrc, cnt, E);
    csr_scan<<<1, 1024>>>(cnt, off, n);
    csr_place<<<edge_blocks, 256>>>(esrc, edst, off, cur, dsts, srcs, E);

    // ---- GAT layers ----
    for (int l = 0; l < NUM_GAT; l++) {
        const float* al = gatA + (size_t)l * 2 * HDIM;
        zero_st<<<(n + 255) / 256, 256>>>(s, t, n);
        gemm_pp<0,0,1><<<gg, 256, SM_BYTES>>>(A2h, A2l, BW(OFF_GAT0 + l * K2_H),
                                              nullptr, hw, nullptr, nullptr,
                                              al, s, t, n, K2_H / 16);
        gat_aggregate<<<n, 128>>>(off, dsts, s, t, hw, h);
        if (l < NUM_GAT - 1)
            conv_a<0><<<cg_h, 256>>>(h, nullptr, nullptr, A2h, A2l, n, HDIM);
    }

    // ---- output MLP ----
    conv_a<1><<<cg_f, 256>>>(h, goal, info, A1h, A1l, n, FEAT);
    gemm_pp<1,1,0><<<gg, 256, SM_BYTES>>>(A1h, A1l, BW(OFF_V1), vb1, nullptr, A2h, A2l,
                                          nullptr, nullptr, nullptr, n, K2_FEAT / 16);
    gemm_pp<1,0,0><<<gg, 256, SM_BYTES>>>(A2h, A2l, BW(OFF_V2), vb2, acc, nullptr, nullptr,
                                          nullptr, nullptr, nullptr, n, K2_H / 16);
    gemv_sigmoid<<<node_warp_blocks, 256>>>(acc, V3, vb3, out, n);
}